// round 1
// baseline (speedup 1.0000x reference)
#include <cuda_runtime.h>
#include <math.h>

#define D_MODEL 1024
#define NHEADS  16
#define DK      64
#define SEQ     2048
#define BATCH   2
#define ROWS    (BATCH*SEQ)   // 4096

// scratch (allocation-free rule: __device__ globals)
__device__ float g_q[ROWS*D_MODEL];
__device__ float g_k[ROWS*D_MODEL];
__device__ float g_v[ROWS*D_MODEL];
__device__ float g_ctx[ROWS*D_MODEL];

// ---------------------------------------------------------------------------
// C[M,N] = A[M,K] @ B[N,K]^T + bias[N]
// remap=1: write C in [B, H, S, DK] layout (for q/k/v); remap=0: plain [M,N]
// ---------------------------------------------------------------------------
__global__ __launch_bounds__(256)
void gemm_nt(const float* __restrict__ A, const float* __restrict__ B,
             const float* __restrict__ bias, float* __restrict__ C, int remap)
{
    const int K = D_MODEL;
    __shared__ float As[16][64];
    __shared__ float Bs[16][64];

    int tid = threadIdx.x;
    int tx = tid & 15, ty = tid >> 4;
    int m0 = blockIdx.y * 64, n0 = blockIdx.x * 64;

    int lrow = tid >> 2;            // 0..63
    int lk4  = (tid & 3) << 2;      // 0,4,8,12

    const float* Ap = A + (size_t)(m0 + lrow) * K + lk4;
    const float* Bp = B + (size_t)(n0 + lrow) * K + lk4;

    float acc[4][4] = {};

    for (int k0 = 0; k0 < K; k0 += 16) {
        float4 a4 = *(const float4*)(Ap + k0);
        float4 b4 = *(const float4*)(Bp + k0);
        __syncthreads();
        As[lk4+0][lrow] = a4.x; As[lk4+1][lrow] = a4.y;
        As[lk4+2][lrow] = a4.z; As[lk4+3][lrow] = a4.w;
        Bs[lk4+0][lrow] = b4.x; Bs[lk4+1][lrow] = b4.y;
        Bs[lk4+2][lrow] = b4.z; Bs[lk4+3][lrow] = b4.w;
        __syncthreads();
        #pragma unroll
        for (int kk = 0; kk < 16; kk++) {
            float aq[4], bq[4];
            *(float4*)aq = *(const float4*)&As[kk][ty << 2];
            *(float4*)bq = *(const float4*)&Bs[kk][tx << 2];
            #pragma unroll
            for (int i = 0; i < 4; i++)
                #pragma unroll
                for (int j = 0; j < 4; j++)
                    acc[i][j] = fmaf(aq[i], bq[j], acc[i][j]);
        }
    }

    #pragma unroll
    for (int i = 0; i < 4; i++) {
        int gi = m0 + (ty << 2) + i;
        #pragma unroll
        for (int j = 0; j < 4; j++) {
            int gj = n0 + (tx << 2) + j;
            float val = acc[i][j] + bias[gj];
            if (remap) {
                int b = gi >> 11, s = gi & (SEQ - 1);
                int h = gj >> 6,  d = gj & (DK - 1);
                C[(((size_t)(b * NHEADS + h) * SEQ) + s) * DK + d] = val;
            } else {
                C[(size_t)gi * D_MODEL + gj] = val;
            }
        }
    }
}

// ---------------------------------------------------------------------------
// Causal flash attention, fp32. One block per (q-tile, b*h).
// q/k/v in [B*H, S, DK]; ctx written in [B, S, H*DK].
// ---------------------------------------------------------------------------
__global__ __launch_bounds__(256)
void flash_attn(const float* __restrict__ q, const float* __restrict__ k,
                const float* __restrict__ v, float* __restrict__ ctx)
{
    extern __shared__ float sm[];
    float* Qs   = sm;                       // [64][64] row-major (q-row, d)
    float* Kt   = sm + 4096;                // [64][64] transposed: (d, key)
    float* Vs   = sm + 8192;                // [64][64] row-major (key, d)
    float* Ss   = sm + 12288;               // [64][65]
    float* rowm = sm + 12288 + 64 * 65;     // [64]
    float* rowl = rowm + 64;                // [64]
    float* rowc = rowl + 64;                // [64]

    int qt  = blockIdx.x;
    int bh  = blockIdx.y;
    int tid = threadIdx.x;
    int tx  = tid & 15, ty = tid >> 4;
    const float scale = 0.125f;             // 1/sqrt(64)

    const float* qb = q + ((size_t)bh * SEQ + qt * 64) * DK;
    const float* kb = k + (size_t)bh * SEQ * DK;
    const float* vb = v + (size_t)bh * SEQ * DK;

    // load Q tile (contiguous 4096 floats)
    #pragma unroll
    for (int i = 0; i < 4; i++) {
        int idx = tid + i * 256;
        ((float4*)Qs)[idx] = ((const float4*)qb)[idx];
    }
    if (tid < 64) { rowm[tid] = -INFINITY; rowl[tid] = 0.f; }

    float acc[4][4] = {};

    for (int kt = 0; kt <= qt; kt++) {
        __syncthreads();   // protect smem reuse from previous iteration
        const float* kbt = kb + (size_t)kt * 64 * DK;
        const float* vbt = vb + (size_t)kt * 64 * DK;
        #pragma unroll
        for (int i = 0; i < 4; i++) {
            int idx = tid + i * 256;          // float4 index 0..1023
            // K: transpose into Kt[d][key]
            int key = idx & 63;
            int d4  = (idx >> 6) << 2;
            float4 k4 = *(const float4*)(kbt + key * DK + d4);
            Kt[(d4 + 0) * 64 + key] = k4.x;
            Kt[(d4 + 1) * 64 + key] = k4.y;
            Kt[(d4 + 2) * 64 + key] = k4.z;
            Kt[(d4 + 3) * 64 + key] = k4.w;
            // V: row-major coalesced
            ((float4*)Vs)[idx] = ((const float4*)vbt)[idx];
        }
        __syncthreads();

        // S = (Q K^T) * scale, 4x4 microtile per thread
        float s[4][4] = {};
        #pragma unroll
        for (int d = 0; d < DK; d += 4) {
            float av[4][4], kv[4][4];
            #pragma unroll
            for (int i = 0; i < 4; i++)
                *(float4*)av[i] = *(const float4*)&Qs[((ty << 2) + i) * DK + d];
            #pragma unroll
            for (int e = 0; e < 4; e++)
                *(float4*)kv[e] = *(const float4*)&Kt[(d + e) * 64 + (tx << 2)];
            #pragma unroll
            for (int i = 0; i < 4; i++)
                #pragma unroll
                for (int j = 0; j < 4; j++)
                    #pragma unroll
                    for (int e = 0; e < 4; e++)
                        s[i][j] = fmaf(av[i][e], kv[e][j], s[i][j]);
        }

        // scale + causal mask + write to smem
        #pragma unroll
        for (int i = 0; i < 4; i++) {
            int qrow = qt * 64 + (ty << 2) + i;
            #pragma unroll
            for (int j = 0; j < 4; j++) {
                int kcol = kt * 64 + (tx << 2) + j;
                float val = s[i][j] * scale;
                if (kcol > qrow) val = -1e9f;
                Ss[((ty << 2) + i) * 65 + (tx << 2) + j] = val;
            }
        }
        __syncthreads();

        // online softmax: 4 threads per row
        {
            int row = tid >> 2, sub = tid & 3;
            float mloc = -INFINITY;
            #pragma unroll
            for (int j = 0; j < 16; j++)
                mloc = fmaxf(mloc, Ss[row * 65 + sub + (j << 2)]);
            mloc = fmaxf(mloc, __shfl_xor_sync(0xffffffffu, mloc, 1));
            mloc = fmaxf(mloc, __shfl_xor_sync(0xffffffffu, mloc, 2));
            float mnew = fmaxf(rowm[row], mloc);
            float psum = 0.f;
            #pragma unroll
            for (int j = 0; j < 16; j++) {
                int c = sub + (j << 2);
                float p = __expf(Ss[row * 65 + c] - mnew);
                Ss[row * 65 + c] = p;
                psum += p;
            }
            psum += __shfl_xor_sync(0xffffffffu, psum, 1);
            psum += __shfl_xor_sync(0xffffffffu, psum, 2);
            if (sub == 0) {
                float c0 = __expf(rowm[row] - mnew);
                rowc[row] = c0;
                rowl[row] = rowl[row] * c0 + psum;
                rowm[row] = mnew;
            }
        }
        __syncthreads();

        // O = O * c + P @ V
        float cf[4];
        #pragma unroll
        for (int i = 0; i < 4; i++) cf[i] = rowc[(ty << 2) + i];
        #pragma unroll
        for (int i = 0; i < 4; i++)
            #pragma unroll
            for (int j = 0; j < 4; j++)
                acc[i][j] *= cf[i];
        #pragma unroll
        for (int kk = 0; kk < 64; kk++) {
            float vv[4];
            *(float4*)vv = *(const float4*)&Vs[kk * DK + (tx << 2)];
            float pp[4];
            #pragma unroll
            for (int i = 0; i < 4; i++) pp[i] = Ss[((ty << 2) + i) * 65 + kk];
            #pragma unroll
            for (int i = 0; i < 4; i++)
                #pragma unroll
                for (int j = 0; j < 4; j++)
                    acc[i][j] = fmaf(pp[i], vv[j], acc[i][j]);
        }
    }
    __syncthreads();

    // normalize and write ctx in [B, S, H*DK]
    int b = bh >> 4, h = bh & 15;
    #pragma unroll
    for (int i = 0; i < 4; i++) {
        int srow = qt * 64 + (ty << 2) + i;
        float inv = 1.f / rowl[(ty << 2) + i];
        #pragma unroll
        for (int j = 0; j < 4; j++) {
            ctx[((size_t)b * SEQ + srow) * D_MODEL + h * DK + (tx << 2) + j] =
                acc[i][j] * inv;
        }
    }
}

// ---------------------------------------------------------------------------
extern "C" void kernel_launch(void* const* d_in, const int* in_sizes, int n_in,
                              void* d_out, int out_size)
{
    const float* Q   = (const float*)d_in[0];
    const float* W_Q = (const float*)d_in[1];
    const float* b_Q = (const float*)d_in[2];
    const float* W_K = (const float*)d_in[3];
    const float* b_K = (const float*)d_in[4];
    const float* W_V = (const float*)d_in[5];
    const float* b_V = (const float*)d_in[6];
    const float* W_O = (const float*)d_in[7];
    const float* b_O = (const float*)d_in[8];
    float* out = (float*)d_out;

    float *q, *k, *v, *ctx;
    cudaGetSymbolAddress((void**)&q,   g_q);
    cudaGetSymbolAddress((void**)&k,   g_k);
    cudaGetSymbolAddress((void**)&v,   g_v);
    cudaGetSymbolAddress((void**)&ctx, g_ctx);

    dim3 ggrid(D_MODEL / 64, ROWS / 64);   // (16, 64)

    gemm_nt<<<ggrid, 256>>>(Q, W_Q, b_Q, q, 1);
    gemm_nt<<<ggrid, 256>>>(Q, W_K, b_K, k, 1);
    gemm_nt<<<ggrid, 256>>>(Q, W_V, b_V, v, 1);

    const int smem_bytes = (3 * 64 * 64 + 64 * 65 + 3 * 64) * (int)sizeof(float);
    cudaFuncSetAttribute(flash_attn, cudaFuncAttributeMaxDynamicSharedMemorySize,
                         smem_bytes);
    flash_attn<<<dim3(SEQ / 64, BATCH * NHEADS), 256, smem_bytes>>>(q, k, v, ctx);

    gemm_nt<<<ggrid, 256>>>(ctx, W_O, b_O, out, 0);
}

// round 4
// speedup vs baseline: 1.4034x; 1.4034x over previous
#include <cuda_runtime.h>
#include <cuda_bf16.h>
#include <math.h>
#include <stdint.h>

#define D_MODEL 1024
#define NHEADS  16
#define DK      64
#define SEQ     2048
#define BATCH   2
#define ROWS    (BATCH*SEQ)   // 4096

// scratch (allocation-free rule: __device__ globals)
__device__ float g_q[ROWS*D_MODEL];
__device__ float g_k[ROWS*D_MODEL];
__device__ float g_v[ROWS*D_MODEL];
__device__ float g_ctx[ROWS*D_MODEL];

// ===========================================================================
// helpers
// ===========================================================================
__device__ __forceinline__ uint32_t smem_u32(const void* p) {
    uint32_t a;
    asm("{ .reg .u64 t; cvta.to.shared.u64 t, %1; cvt.u32.u64 %0, t; }"
        : "=r"(a) : "l"(p));
    return a;
}
__device__ __forceinline__ uint32_t swz128(uint32_t off) {
    return off ^ ((off >> 3) & 0x70);
}
__device__ __forceinline__ void ldsm_x4(uint32_t* r, uint32_t addr) {
    asm volatile("ldmatrix.sync.aligned.m8n8.x4.shared.b16 {%0,%1,%2,%3}, [%4];"
                 : "=r"(r[0]), "=r"(r[1]), "=r"(r[2]), "=r"(r[3]) : "r"(addr));
}
__device__ __forceinline__ void mma16816(float* c, const uint32_t* a,
                                         uint32_t b0, uint32_t b1) {
    asm volatile("mma.sync.aligned.m16n8k16.row.col.f32.bf16.bf16.f32 "
                 "{%0,%1,%2,%3}, {%4,%5,%6,%7}, {%8,%9}, {%0,%1,%2,%3};"
                 : "+f"(c[0]), "+f"(c[1]), "+f"(c[2]), "+f"(c[3])
                 : "r"(a[0]), "r"(a[1]), "r"(a[2]), "r"(a[3]), "r"(b0), "r"(b1));
}
__device__ __forceinline__ uint32_t pack_bf2(float f0, float f1) {
    __nv_bfloat16 h0 = __float2bfloat16(f0);
    __nv_bfloat16 h1 = __float2bfloat16(f1);
    return ((uint32_t)__bfloat16_as_ushort(h1) << 16) | __bfloat16_as_ushort(h0);
}

// ===========================================================================
// bf16x3 GEMM via mma.sync:  C[M,N] = A[M,1024] @ B[N,1024]^T + bias[N]
// CTA tile 128x128, K chunk 64, 512 threads (warp grid 4x4, warp tile 32x32).
// remap=1: write C in [B, H, S, DK] layout; remap=0: plain [M,N]
// ===========================================================================
#define GT_NCHUNK (D_MODEL / 64)     // 16
#define SM_AH 0
#define SM_AL 16384
#define SM_BH 32768
#define SM_BL 49152
#define GT_SMEM 65536

__global__ __launch_bounds__(512, 1)
void gemm_tc(const float* __restrict__ A, const float* __restrict__ B,
             const float* __restrict__ bias, float* __restrict__ C, int remap)
{
    extern __shared__ __align__(1024) char smem[];
    const uint32_t sbase = smem_u32(smem);
    const int tid  = threadIdx.x;
    const int wid  = tid >> 5;
    const int lane = tid & 31;
    const int wm   = wid & 3;        // 0..3  (M)
    const int wn   = wid >> 2;       // 0..3  (N)

    const int m0 = blockIdx.y * 128;
    const int n0 = blockIdx.x * 128;

    const float* Ab = A + (size_t)m0 * D_MODEL;
    const float* Bb = B + (size_t)n0 * D_MODEL;

    // per-thread load geometry (2 iterations of 8 floats for A and B)
    int rowi[2], k8i[2];
    uint32_t soff[2];
    #pragma unroll
    for (int i = 0; i < 2; i++) {
        int g = i * 512 + tid;       // 0..1023
        rowi[i] = g >> 3;            // 0..127
        k8i[i]  = g & 7;             // 0..7
        soff[i] = swz128((uint32_t)(rowi[i] * 128 + k8i[i] * 16));
    }

    float acc[2][4][4] = {};
    uint32_t pAh[2][4], pAl[2][4], pBh[2][4], pBl[2][4];

    // ---- prologue: load + convert chunk 0 ----
    {
        #pragma unroll
        for (int i = 0; i < 2; i++) {
            const float* ap = Ab + (size_t)rowi[i] * D_MODEL + k8i[i] * 8;
            const float* bp = Bb + (size_t)rowi[i] * D_MODEL + k8i[i] * 8;
            float4 a0 = *(const float4*)ap, a1 = *(const float4*)(ap + 4);
            float4 b0 = *(const float4*)bp, b1 = *(const float4*)(bp + 4);
            float fa[8] = {a0.x,a0.y,a0.z,a0.w,a1.x,a1.y,a1.z,a1.w};
            float fb[8] = {b0.x,b0.y,b0.z,b0.w,b1.x,b1.y,b1.z,b1.w};
            #pragma unroll
            for (int p = 0; p < 4; p++) {
                pAh[i][p] = pack_bf2(fa[2*p], fa[2*p+1]);
                float r0 = fa[2*p]   - __bfloat162float(__float2bfloat16(fa[2*p]));
                float r1 = fa[2*p+1] - __bfloat162float(__float2bfloat16(fa[2*p+1]));
                pAl[i][p] = pack_bf2(r0, r1);
                pBh[i][p] = pack_bf2(fb[2*p], fb[2*p+1]);
                r0 = fb[2*p]   - __bfloat162float(__float2bfloat16(fb[2*p]));
                r1 = fb[2*p+1] - __bfloat162float(__float2bfloat16(fb[2*p+1]));
                pBl[i][p] = pack_bf2(r0, r1);
            }
        }
    }

    for (int kc = 0; kc < GT_NCHUNK; kc++) {
        // ---- store pending chunk to smem ----
        #pragma unroll
        for (int i = 0; i < 2; i++) {
            asm volatile("st.shared.v4.b32 [%0], {%1,%2,%3,%4};" ::
                "r"(sbase + SM_AH + soff[i]),
                "r"(pAh[i][0]), "r"(pAh[i][1]), "r"(pAh[i][2]), "r"(pAh[i][3]));
            asm volatile("st.shared.v4.b32 [%0], {%1,%2,%3,%4};" ::
                "r"(sbase + SM_AL + soff[i]),
                "r"(pAl[i][0]), "r"(pAl[i][1]), "r"(pAl[i][2]), "r"(pAl[i][3]));
            asm volatile("st.shared.v4.b32 [%0], {%1,%2,%3,%4};" ::
                "r"(sbase + SM_BH + soff[i]),
                "r"(pBh[i][0]), "r"(pBh[i][1]), "r"(pBh[i][2]), "r"(pBh[i][3]));
            asm volatile("st.shared.v4.b32 [%0], {%1,%2,%3,%4};" ::
                "r"(sbase + SM_BL + soff[i]),
                "r"(pBl[i][0]), "r"(pBl[i][1]), "r"(pBl[i][2]), "r"(pBl[i][3]));
        }
        __syncthreads();

        // ---- issue next chunk's global loads (latency hidden by mma) ----
        float fa[2][8], fb[2][8];
        if (kc + 1 < GT_NCHUNK) {
            #pragma unroll
            for (int i = 0; i < 2; i++) {
                const float* ap = Ab + (size_t)rowi[i] * D_MODEL + (kc+1) * 64 + k8i[i] * 8;
                const float* bp = Bb + (size_t)rowi[i] * D_MODEL + (kc+1) * 64 + k8i[i] * 8;
                float4 a0 = *(const float4*)ap, a1 = *(const float4*)(ap + 4);
                float4 b0 = *(const float4*)bp, b1 = *(const float4*)(bp + 4);
                fa[i][0]=a0.x; fa[i][1]=a0.y; fa[i][2]=a0.z; fa[i][3]=a0.w;
                fa[i][4]=a1.x; fa[i][5]=a1.y; fa[i][6]=a1.z; fa[i][7]=a1.w;
                fb[i][0]=b0.x; fb[i][1]=b0.y; fb[i][2]=b0.z; fb[i][3]=b0.w;
                fb[i][4]=b1.x; fb[i][5]=b1.y; fb[i][6]=b1.z; fb[i][7]=b1.w;
            }
        }

        // ---- mma over this chunk: 4 K16 steps x 3 split terms ----
        #pragma unroll
        for (int ks = 0; ks < 4; ks++) {
            uint32_t ah[2][4], al[2][4];
            #pragma unroll
            for (int mi = 0; mi < 2; mi++) {
                int mrow = wm * 32 + mi * 16 + (lane & 15);
                uint32_t off = swz128((uint32_t)(mrow * 128 + ks * 32 + (lane >> 4) * 16));
                ldsm_x4(ah[mi], sbase + SM_AH + off);
                ldsm_x4(al[mi], sbase + SM_AL + off);
            }
            // B stored [n][k] row-major == col-major for mma row.col:
            // NON-trans ldmatrix, A-style addressing.
            // quadrants: r0=(n0-7,k0-7) r1=(n8-15,k0-7) r2=(n0-7,k8-15) r3=(n8-15,k8-15)
            uint32_t bh[2][4], bl[2][4];
            #pragma unroll
            for (int nj = 0; nj < 2; nj++) {
                int nrow = wn * 32 + nj * 16 + (lane & 15);
                uint32_t off = swz128((uint32_t)(nrow * 128 + ks * 32 + (lane >> 4) * 16));
                ldsm_x4(bh[nj], sbase + SM_BH + off);
                ldsm_x4(bl[nj], sbase + SM_BL + off);
            }
            #pragma unroll
            for (int mi = 0; mi < 2; mi++)
                #pragma unroll
                for (int nj = 0; nj < 2; nj++) {
                    // n-group nj*16+0..7 -> (r0, r2); nj*16+8..15 -> (r1, r3)
                    mma16816(acc[mi][nj*2+0], ah[mi], bh[nj][0], bh[nj][2]);
                    mma16816(acc[mi][nj*2+1], ah[mi], bh[nj][1], bh[nj][3]);
                    mma16816(acc[mi][nj*2+0], al[mi], bh[nj][0], bh[nj][2]);
                    mma16816(acc[mi][nj*2+1], al[mi], bh[nj][1], bh[nj][3]);
                    mma16816(acc[mi][nj*2+0], ah[mi], bl[nj][0], bl[nj][2]);
                    mma16816(acc[mi][nj*2+1], ah[mi], bl[nj][1], bl[nj][3]);
                }
        }

        // ---- convert next chunk into pending regs ----
        if (kc + 1 < GT_NCHUNK) {
            #pragma unroll
            for (int i = 0; i < 2; i++)
                #pragma unroll
                for (int p = 0; p < 4; p++) {
                    pAh[i][p] = pack_bf2(fa[i][2*p], fa[i][2*p+1]);
                    float r0 = fa[i][2*p]   - __bfloat162float(__float2bfloat16(fa[i][2*p]));
                    float r1 = fa[i][2*p+1] - __bfloat162float(__float2bfloat16(fa[i][2*p+1]));
                    pAl[i][p] = pack_bf2(r0, r1);
                    pBh[i][p] = pack_bf2(fb[i][2*p], fb[i][2*p+1]);
                    r0 = fb[i][2*p]   - __bfloat162float(__float2bfloat16(fb[i][2*p]));
                    r1 = fb[i][2*p+1] - __bfloat162float(__float2bfloat16(fb[i][2*p+1]));
                    pBl[i][p] = pack_bf2(r0, r1);
                }
        }
        __syncthreads();
    }

    // ---- epilogue: write accumulators (+bias, optional q/k/v head remap) ----
    #pragma unroll
    for (int mi = 0; mi < 2; mi++) {
        #pragma unroll
        for (int nj = 0; nj < 4; nj++) {
            int gj = n0 + wn * 32 + nj * 8 + (lane & 3) * 2;
            float bi0 = __ldg(bias + gj), bi1 = __ldg(bias + gj + 1);
            #pragma unroll
            for (int half = 0; half < 2; half++) {
                int gi = m0 + wm * 32 + mi * 16 + (lane >> 2) + half * 8;
                float v0 = acc[mi][nj][half*2+0] + bi0;
                float v1 = acc[mi][nj][half*2+1] + bi1;
                if (remap) {
                    int b = gi >> 11, s = gi & (SEQ - 1);
                    int h = gj >> 6,  d = gj & (DK - 1);
                    float2* dst = (float2*)&C[(((size_t)(b * NHEADS + h) * SEQ) + s) * DK + d];
                    *dst = make_float2(v0, v1);
                } else {
                    float2* dst = (float2*)&C[(size_t)gi * D_MODEL + gj];
                    *dst = make_float2(v0, v1);
                }
            }
        }
    }
}

// ---------------------------------------------------------------------------
// Causal flash attention, fp32 (unchanged). One block per (q-tile, b*h).
// ---------------------------------------------------------------------------
__global__ __launch_bounds__(256)
void flash_attn(const float* __restrict__ q, const float* __restrict__ k,
                const float* __restrict__ v, float* __restrict__ ctx)
{
    extern __shared__ float sm[];
    float* Qs   = sm;
    float* Kt   = sm + 4096;
    float* Vs   = sm + 8192;
    float* Ss   = sm + 12288;
    float* rowm = sm + 12288 + 64 * 65;
    float* rowl = rowm + 64;
    float* rowc = rowl + 64;

    int qt  = blockIdx.x;
    int bh  = blockIdx.y;
    int tid = threadIdx.x;
    int tx  = tid & 15, ty = tid >> 4;
    const float scale = 0.125f;

    const float* qb = q + ((size_t)bh * SEQ + qt * 64) * DK;
    const float* kb = k + (size_t)bh * SEQ * DK;
    const float* vb = v + (size_t)bh * SEQ * DK;

    #pragma unroll
    for (int i = 0; i < 4; i++) {
        int idx = tid + i * 256;
        ((float4*)Qs)[idx] = ((const float4*)qb)[idx];
    }
    if (tid < 64) { rowm[tid] = -INFINITY; rowl[tid] = 0.f; }

    float acc[4][4] = {};

    for (int kt = 0; kt <= qt; kt++) {
        __syncthreads();
        const float* kbt = kb + (size_t)kt * 64 * DK;
        const float* vbt = vb + (size_t)kt * 64 * DK;
        #pragma unroll
        for (int i = 0; i < 4; i++) {
            int idx = tid + i * 256;
            int key = idx & 63;
            int d4  = (idx >> 6) << 2;
            float4 k4 = *(const float4*)(kbt + key * DK + d4);
            Kt[(d4 + 0) * 64 + key] = k4.x;
            Kt[(d4 + 1) * 64 + key] = k4.y;
            Kt[(d4 + 2) * 64 + key] = k4.z;
            Kt[(d4 + 3) * 64 + key] = k4.w;
            ((float4*)Vs)[idx] = ((const float4*)vbt)[idx];
        }
        __syncthreads();

        float s[4][4] = {};
        #pragma unroll
        for (int d = 0; d < DK; d += 4) {
            float av[4][4], kv[4][4];
            #pragma unroll
            for (int i = 0; i < 4; i++)
                *(float4*)av[i] = *(const float4*)&Qs[((ty << 2) + i) * DK + d];
            #pragma unroll
            for (int e = 0; e < 4; e++)
                *(float4*)kv[e] = *(const float4*)&Kt[(d + e) * 64 + (tx << 2)];
            #pragma unroll
            for (int i = 0; i < 4; i++)
                #pragma unroll
                for (int j = 0; j < 4; j++)
                    #pragma unroll
                    for (int e = 0; e < 4; e++)
                        s[i][j] = fmaf(av[i][e], kv[e][j], s[i][j]);
        }

        #pragma unroll
        for (int i = 0; i < 4; i++) {
            int qrow = qt * 64 + (ty << 2) + i;
            #pragma unroll
            for (int j = 0; j < 4; j++) {
                int kcol = kt * 64 + (tx << 2) + j;
                float val = s[i][j] * scale;
                if (kcol > qrow) val = -1e9f;
                Ss[((ty << 2) + i) * 65 + (tx << 2) + j] = val;
            }
        }
        __syncthreads();

        {
            int row = tid >> 2, sub = tid & 3;
            float mloc = -INFINITY;
            #pragma unroll
            for (int j = 0; j < 16; j++)
                mloc = fmaxf(mloc, Ss[row * 65 + sub + (j << 2)]);
            mloc = fmaxf(mloc, __shfl_xor_sync(0xffffffffu, mloc, 1));
            mloc = fmaxf(mloc, __shfl_xor_sync(0xffffffffu, mloc, 2));
            float mnew = fmaxf(rowm[row], mloc);
            float psum = 0.f;
            #pragma unroll
            for (int j = 0; j < 16; j++) {
                int c = sub + (j << 2);
                float p = __expf(Ss[row * 65 + c] - mnew);
                Ss[row * 65 + c] = p;
                psum += p;
            }
            psum += __shfl_xor_sync(0xffffffffu, psum, 1);
            psum += __shfl_xor_sync(0xffffffffu, psum, 2);
            if (sub == 0) {
                float c0 = __expf(rowm[row] - mnew);
                rowc[row] = c0;
                rowl[row] = rowl[row] * c0 + psum;
                rowm[row] = mnew;
            }
        }
        __syncthreads();

        float cf[4];
        #pragma unroll
        for (int i = 0; i < 4; i++) cf[i] = rowc[(ty << 2) + i];
        #pragma unroll
        for (int i = 0; i < 4; i++)
            #pragma unroll
            for (int j = 0; j < 4; j++)
                acc[i][j] *= cf[i];
        #pragma unroll
        for (int kk = 0; kk < 64; kk++) {
            float vv[4];
            *(float4*)vv = *(const float4*)&Vs[kk * DK + (tx << 2)];
            float pp[4];
            #pragma unroll
            for (int i = 0; i < 4; i++) pp[i] = Ss[((ty << 2) + i) * 65 + kk];
            #pragma unroll
            for (int i = 0; i < 4; i++)
                #pragma unroll
                for (int j = 0; j < 4; j++)
                    acc[i][j] = fmaf(pp[i], vv[j], acc[i][j]);
        }
    }
    __syncthreads();

    int b = bh >> 4, h = bh & 15;
    #pragma unroll
    for (int i = 0; i < 4; i++) {
        int srow = qt * 64 + (ty << 2) + i;
        float inv = 1.f / rowl[(ty << 2) + i];
        #pragma unroll
        for (int j = 0; j < 4; j++) {
            ctx[((size_t)b * SEQ + srow) * D_MODEL + h * DK + (tx << 2) + j] =
                acc[i][j] * inv;
        }
    }
}

// ---------------------------------------------------------------------------
extern "C" void kernel_launch(void* const* d_in, const int* in_sizes, int n_in,
                              void* d_out, int out_size)
{
    const float* Q   = (const float*)d_in[0];
    const float* W_Q = (const float*)d_in[1];
    const float* b_Q = (const float*)d_in[2];
    const float* W_K = (const float*)d_in[3];
    const float* b_K = (const float*)d_in[4];
    const float* W_V = (const float*)d_in[5];
    const float* b_V = (const float*)d_in[6];
    const float* W_O = (const float*)d_in[7];
    const float* b_O = (const float*)d_in[8];
    float* out = (float*)d_out;

    float *q, *k, *v, *ctx;
    cudaGetSymbolAddress((void**)&q,   g_q);
    cudaGetSymbolAddress((void**)&k,   g_k);
    cudaGetSymbolAddress((void**)&v,   g_v);
    cudaGetSymbolAddress((void**)&ctx, g_ctx);

    cudaFuncSetAttribute(gemm_tc, cudaFuncAttributeMaxDynamicSharedMemorySize,
                         GT_SMEM);
    const int fa_smem = (3 * 64 * 64 + 64 * 65 + 3 * 64) * (int)sizeof(float);
    cudaFuncSetAttribute(flash_attn, cudaFuncAttributeMaxDynamicSharedMemorySize,
                         fa_smem);

    dim3 ggrid(D_MODEL / 128, ROWS / 128);   // (8, 32)

    gemm_tc<<<ggrid, 512, GT_SMEM>>>(Q, W_Q, b_Q, q, 1);
    gemm_tc<<<ggrid, 512, GT_SMEM>>>(Q, W_K, b_K, k, 1);
    gemm_tc<<<ggrid, 512, GT_SMEM>>>(Q, W_V, b_V, v, 1);

    flash_attn<<<dim3(SEQ / 64, BATCH * NHEADS), 256, fa_smem>>>(q, k, v, ctx);

    gemm_tc<<<ggrid, 512, GT_SMEM>>>(ctx, W_O, b_O, out, 0);
}

// round 5
// speedup vs baseline: 3.1530x; 2.2467x over previous
#include <cuda_runtime.h>
#include <cuda_fp16.h>
#include <math.h>
#include <stdint.h>

#define D_MODEL 1024
#define NHEADS  16
#define DK      64
#define SEQ     2048
#define BATCH   2
#define ROWS    (BATCH*SEQ)   // 4096
#define WELEM   (D_MODEL*D_MODEL)

// fp16 scratch (allocation-free rule: __device__ globals; 16B-aligned for uint4)
__device__ __align__(16) __half g_Qh[ROWS*D_MODEL];
__device__ __align__(16) __half g_Ql[ROWS*D_MODEL];
__device__ __align__(16) __half g_wh[4*WELEM];   // Wq,Wk,Wv,Wo hi
__device__ __align__(16) __half g_wl[4*WELEM];   // lo
__device__ __align__(16) __half g_qh[ROWS*D_MODEL];   // q fp16 [B,H,S,DK]
__device__ __align__(16) __half g_kh[ROWS*D_MODEL];
__device__ __align__(16) __half g_vh[ROWS*D_MODEL];
__device__ __align__(16) __half g_vl[ROWS*D_MODEL];
__device__ __align__(16) __half g_ch[ROWS*D_MODEL];   // ctx hi [B,S,D]
__device__ __align__(16) __half g_cl[ROWS*D_MODEL];

// ===========================================================================
// helpers
// ===========================================================================
__device__ __forceinline__ uint32_t smem_u32(const void* p) {
    uint32_t a;
    asm("{ .reg .u64 t; cvta.to.shared.u64 t, %1; cvt.u32.u64 %0, t; }"
        : "=r"(a) : "l"(p));
    return a;
}
__device__ __forceinline__ uint32_t swz128(uint32_t off) {
    return off ^ ((off >> 3) & 0x70);
}
__device__ __forceinline__ void ldsm_x4(uint32_t* r, uint32_t addr) {
    asm volatile("ldmatrix.sync.aligned.m8n8.x4.shared.b16 {%0,%1,%2,%3}, [%4];"
                 : "=r"(r[0]), "=r"(r[1]), "=r"(r[2]), "=r"(r[3]) : "r"(addr));
}
__device__ __forceinline__ void ldsm_x4_t(uint32_t* r, uint32_t addr) {
    asm volatile("ldmatrix.sync.aligned.m8n8.x4.trans.shared.b16 {%0,%1,%2,%3}, [%4];"
                 : "=r"(r[0]), "=r"(r[1]), "=r"(r[2]), "=r"(r[3]) : "r"(addr));
}
__device__ __forceinline__ void mmah(float* c, const uint32_t* a,
                                     uint32_t b0, uint32_t b1) {
    asm volatile("mma.sync.aligned.m16n8k16.row.col.f32.f16.f16.f32 "
                 "{%0,%1,%2,%3}, {%4,%5,%6,%7}, {%8,%9}, {%0,%1,%2,%3};"
                 : "+f"(c[0]), "+f"(c[1]), "+f"(c[2]), "+f"(c[3])
                 : "r"(a[0]), "r"(a[1]), "r"(a[2]), "r"(a[3]), "r"(b0), "r"(b1));
}
// 2^t via FMA-pipe polynomial (avoids MUFU bottleneck). t <= 0.
__device__ __forceinline__ float exp2p(float t) {
    t = fmaxf(t, -126.0f);
    float i = rintf(t);
    float f = t - i;
    float p = fmaf(f, 0.0096181291f, 0.055504109f);
    p = fmaf(f, p, 0.24022651f);
    p = fmaf(f, p, 0.69314718f);
    p = fmaf(f, p, 1.0f);
    return p * __int_as_float(((int)i + 127) << 23);
}
// pack pair to fp16x2 hi + residual lo
__device__ __forceinline__ void pack2hl(float a, float b, uint32_t& h, uint32_t& l) {
    __half2 H = __floats2half2_rn(a, b);
    float2 F = __half22float2(H);
    __half2 L = __floats2half2_rn(a - F.x, b - F.y);
    h = *reinterpret_cast<uint32_t*>(&H);
    l = *reinterpret_cast<uint32_t*>(&L);
}

// ===========================================================================
// fp32 -> fp16 hi/lo split (one-time per input array)
// ===========================================================================
__global__ void split16(const float* __restrict__ s, __half* __restrict__ h,
                        __half* __restrict__ l, int n) {
    int i = (blockIdx.x * blockDim.x + threadIdx.x) * 4;
    if (i >= n) return;
    float4 x = *(const float4*)(s + i);
    __half2 h01 = __floats2half2_rn(x.x, x.y);
    __half2 h23 = __floats2half2_rn(x.z, x.w);
    float2 f01 = __half22float2(h01), f23 = __half22float2(h23);
    __half2 l01 = __floats2half2_rn(x.x - f01.x, x.y - f01.y);
    __half2 l23 = __floats2half2_rn(x.z - f23.x, x.w - f23.y);
    *(__half2*)(h + i) = h01; *(__half2*)(h + i + 2) = h23;
    *(__half2*)(l + i) = l01; *(__half2*)(l + i + 2) = l23;
}

// ===========================================================================
// fp16x3 GEMM via mma.sync on pre-split operands.
// C[M,N] = (Ah+Al)[M,1024] @ (Bh+Bl)[N,1024]^T + bias[N]
// CTA 128x128, K-chunk 64, 512 threads (warp grid 4x4, warp tile 32x32).
// mode 0: fp32 [M,N]; mode 1: fp16 [B,H,S,DK]; mode 2: fp16 hi/lo [B,H,S,DK]
// ===========================================================================
#define SM_AH 0
#define SM_AL 16384
#define SM_BH 32768
#define SM_BL 49152
#define GT_SMEM 65536

__global__ __launch_bounds__(512, 1)
void gemm3(const __half* __restrict__ Ah, const __half* __restrict__ Al,
           const __half* __restrict__ Bh, const __half* __restrict__ Bl,
           const float* __restrict__ bias, float* __restrict__ Cf,
           __half* __restrict__ Oh, __half* __restrict__ Ol, int mode)
{
    extern __shared__ __align__(1024) char smem[];
    const uint32_t sbase = smem_u32(smem);
    const int tid  = threadIdx.x;
    const int wid  = tid >> 5;
    const int lane = tid & 31;
    const int wm   = wid & 3;
    const int wn   = wid >> 2;

    const int m0 = blockIdx.y * 128;
    const int n0 = blockIdx.x * 128;

    // loader geometry: 2 x (row, 16B-chunk) per thread per array
    int rowi[2], c8i[2];
    uint32_t soff[2];
    #pragma unroll
    for (int i = 0; i < 2; i++) {
        int g = i * 512 + tid;       // 0..1023
        rowi[i] = g >> 3;            // 0..127
        c8i[i]  = g & 7;             // 0..7
        soff[i] = swz128((uint32_t)(rowi[i] * 128 + c8i[i] * 16));
    }

    float acc[2][4][4] = {};
    uint4 rA[2], rAl[2], rB[2], rBl[2];

    // prologue: chunk 0
    #pragma unroll
    for (int i = 0; i < 2; i++) {
        size_t ao = (size_t)(m0 + rowi[i]) * D_MODEL + c8i[i] * 8;
        size_t bo = (size_t)(n0 + rowi[i]) * D_MODEL + c8i[i] * 8;
        rA[i]  = *(const uint4*)(Ah + ao);
        rAl[i] = *(const uint4*)(Al + ao);
        rB[i]  = *(const uint4*)(Bh + bo);
        rBl[i] = *(const uint4*)(Bl + bo);
    }

    for (int kc = 0; kc < 16; kc++) {
        #pragma unroll
        for (int i = 0; i < 2; i++) {
            asm volatile("st.shared.v4.b32 [%0], {%1,%2,%3,%4};" ::
                "r"(sbase + SM_AH + soff[i]), "r"(rA[i].x), "r"(rA[i].y), "r"(rA[i].z), "r"(rA[i].w));
            asm volatile("st.shared.v4.b32 [%0], {%1,%2,%3,%4};" ::
                "r"(sbase + SM_AL + soff[i]), "r"(rAl[i].x), "r"(rAl[i].y), "r"(rAl[i].z), "r"(rAl[i].w));
            asm volatile("st.shared.v4.b32 [%0], {%1,%2,%3,%4};" ::
                "r"(sbase + SM_BH + soff[i]), "r"(rB[i].x), "r"(rB[i].y), "r"(rB[i].z), "r"(rB[i].w));
            asm volatile("st.shared.v4.b32 [%0], {%1,%2,%3,%4};" ::
                "r"(sbase + SM_BL + soff[i]), "r"(rBl[i].x), "r"(rBl[i].y), "r"(rBl[i].z), "r"(rBl[i].w));
        }
        __syncthreads();

        if (kc + 1 < 16) {
            #pragma unroll
            for (int i = 0; i < 2; i++) {
                size_t ao = (size_t)(m0 + rowi[i]) * D_MODEL + (kc + 1) * 64 + c8i[i] * 8;
                size_t bo = (size_t)(n0 + rowi[i]) * D_MODEL + (kc + 1) * 64 + c8i[i] * 8;
                rA[i]  = *(const uint4*)(Ah + ao);
                rAl[i] = *(const uint4*)(Al + ao);
                rB[i]  = *(const uint4*)(Bh + bo);
                rBl[i] = *(const uint4*)(Bl + bo);
            }
        }

        #pragma unroll
        for (int ks = 0; ks < 4; ks++) {
            uint32_t ah[2][4], al[2][4];
            #pragma unroll
            for (int mi = 0; mi < 2; mi++) {
                int mrow = wm * 32 + mi * 16 + (lane & 15);
                uint32_t off = swz128((uint32_t)(mrow * 128 + ks * 32 + (lane >> 4) * 16));
                ldsm_x4(ah[mi], sbase + SM_AH + off);
                ldsm_x4(al[mi], sbase + SM_AL + off);
            }
            uint32_t bh[2][4], bl[2][4];
            #pragma unroll
            for (int nj = 0; nj < 2; nj++) {
                int nrow = wn * 32 + nj * 16 + (lane & 15);
                uint32_t off = swz128((uint32_t)(nrow * 128 + ks * 32 + (lane >> 4) * 16));
                ldsm_x4(bh[nj], sbase + SM_BH + off);
                ldsm_x4(bl[nj], sbase + SM_BL + off);
            }
            #pragma unroll
            for (int mi = 0; mi < 2; mi++)
                #pragma unroll
                for (int nj = 0; nj < 2; nj++) {
                    mmah(acc[mi][nj*2+0], ah[mi], bh[nj][0], bh[nj][2]);
                    mmah(acc[mi][nj*2+1], ah[mi], bh[nj][1], bh[nj][3]);
                    mmah(acc[mi][nj*2+0], al[mi], bh[nj][0], bh[nj][2]);
                    mmah(acc[mi][nj*2+1], al[mi], bh[nj][1], bh[nj][3]);
                    mmah(acc[mi][nj*2+0], ah[mi], bl[nj][0], bl[nj][2]);
                    mmah(acc[mi][nj*2+1], ah[mi], bl[nj][1], bl[nj][3]);
                }
        }
        __syncthreads();
    }

    // epilogue
    #pragma unroll
    for (int mi = 0; mi < 2; mi++) {
        #pragma unroll
        for (int nj = 0; nj < 4; nj++) {
            int gj = n0 + wn * 32 + nj * 8 + (lane & 3) * 2;
            float bi0 = __ldg(bias + gj), bi1 = __ldg(bias + gj + 1);
            #pragma unroll
            for (int half = 0; half < 2; half++) {
                int gi = m0 + wm * 32 + mi * 16 + (lane >> 2) + half * 8;
                float v0 = acc[mi][nj][half*2+0] + bi0;
                float v1 = acc[mi][nj][half*2+1] + bi1;
                if (mode == 0) {
                    *(float2*)&Cf[(size_t)gi * D_MODEL + gj] = make_float2(v0, v1);
                } else {
                    int b = gi >> 11, s = gi & (SEQ - 1);
                    int h = gj >> 6,  d = gj & (DK - 1);
                    size_t idx = (((size_t)(b * NHEADS + h) * SEQ) + s) * DK + d;
                    if (mode == 1) {
                        __half2 H = __floats2half2_rn(v0, v1);
                        *(__half2*)&Oh[idx] = H;
                    } else {
                        __half2 H = __floats2half2_rn(v0, v1);
                        float2 F = __half22float2(H);
                        __half2 L = __floats2half2_rn(v0 - F.x, v1 - F.y);
                        *(__half2*)&Oh[idx] = H;
                        *(__half2*)&Ol[idx] = L;
                    }
                }
            }
        }
    }
}

// ===========================================================================
// Causal flash attention, fp16 tensor-core.
// CTA: 128 q-rows x 64-key tiles, 8 warps (warp w: rows 16w..16w+15).
// QK single fp16 term; PV 3-term (PhVh + PlVh + PhVl). Softmax on FMA pipe.
// Writes ctx as fp16 hi/lo [B,S,D] for the W_O GEMM.
// ===========================================================================
#define FSQ  0
#define FSK  16384
#define FSVH 24576
#define FSVL 32768
#define F_SMEM 40960

__global__ __launch_bounds__(256)
void flash_tc(const __half* __restrict__ qh, const __half* __restrict__ kh,
              const __half* __restrict__ vh, const __half* __restrict__ vl,
              __half* __restrict__ ch, __half* __restrict__ cl)
{
    extern __shared__ __align__(1024) char smem[];
    const uint32_t sb = smem_u32(smem);
    const int tid  = threadIdx.x;
    const int wid  = tid >> 5;
    const int lane = tid & 31;
    const int qt   = (gridDim.x - 1) - blockIdx.x;   // descending for balance
    const int bh   = blockIdx.y;
    const size_t base = (size_t)bh * SEQ * DK;
    const float Cs = 0.18033688011f;   // 0.125 * log2(e)

    // load Q tile -> smem (swizzled)
    #pragma unroll
    for (int i = 0; i < 4; i++) {
        int c = i * 256 + tid;          // 0..1023
        int r = c >> 3, c8 = c & 7;
        uint4 d = *(const uint4*)(qh + base + (size_t)(qt * 128 + r) * DK + c8 * 8);
        asm volatile("st.shared.v4.b32 [%0], {%1,%2,%3,%4};" ::
            "r"(sb + FSQ + swz128((uint32_t)(r * 128 + c8 * 16))),
            "r"(d.x), "r"(d.y), "r"(d.z), "r"(d.w));
    }
    __syncthreads();

    // Q fragments (held in registers for the whole kernel)
    uint32_t qf[4][4];
    #pragma unroll
    for (int ks = 0; ks < 4; ks++) {
        uint32_t off = swz128((uint32_t)((16 * wid + (lane & 15)) * 128 + ks * 32 + (lane >> 4) * 16));
        ldsm_x4(qf[ks], sb + FSQ + off);
    }

    float oacc[8][4] = {};
    float m0 = -INFINITY, m1 = -INFINITY, l0 = 0.f, l1 = 0.f;
    const int r0g = qt * 128 + 16 * wid + (lane >> 2);   // global q-row of c0/c1

    const int nkt = 2 * qt + 2;
    for (int kt = 0; kt < nkt; kt++) {
        __syncthreads();
        // load K, Vh, Vl tiles (64 x 64 fp16 each)
        #pragma unroll
        for (int i = 0; i < 2; i++) {
            int c = i * 256 + tid;      // 0..511
            int r = c >> 3, c8 = c & 7;
            size_t go = base + (size_t)(kt * 64 + r) * DK + c8 * 8;
            uint32_t so = swz128((uint32_t)(r * 128 + c8 * 16));
            uint4 dk_ = *(const uint4*)(kh + go);
            uint4 dvh = *(const uint4*)(vh + go);
            uint4 dvl = *(const uint4*)(vl + go);
            asm volatile("st.shared.v4.b32 [%0], {%1,%2,%3,%4};" ::
                "r"(sb + FSK + so), "r"(dk_.x), "r"(dk_.y), "r"(dk_.z), "r"(dk_.w));
            asm volatile("st.shared.v4.b32 [%0], {%1,%2,%3,%4};" ::
                "r"(sb + FSVH + so), "r"(dvh.x), "r"(dvh.y), "r"(dvh.z), "r"(dvh.w));
            asm volatile("st.shared.v4.b32 [%0], {%1,%2,%3,%4};" ::
                "r"(sb + FSVL + so), "r"(dvl.x), "r"(dvl.y), "r"(dvl.z), "r"(dvl.w));
        }
        __syncthreads();

        // S = Q @ K^T (single fp16 term)
        float sacc[8][4] = {};
        #pragma unroll
        for (int g = 0; g < 4; g++) {
            #pragma unroll
            for (int ks = 0; ks < 4; ks++) {
                uint32_t bf[4];
                uint32_t off = swz128((uint32_t)((16 * g + (lane & 15)) * 128 + ks * 32 + (lane >> 4) * 16));
                ldsm_x4(bf, sb + FSK + off);
                mmah(sacc[2*g+0], qf[ks], bf[0], bf[2]);
                mmah(sacc[2*g+1], qf[ks], bf[1], bf[3]);
            }
        }

        // causal mask (only diagonal-overlapping tiles)
        if (kt * 64 + 63 > qt * 128 + 16 * wid) {
            #pragma unroll
            for (int t = 0; t < 8; t++) {
                int col = kt * 64 + 8 * t + 2 * (lane & 3);
                if (col     > r0g)     sacc[t][0] = -1e9f;
                if (col + 1 > r0g)     sacc[t][1] = -1e9f;
                if (col     > r0g + 8) sacc[t][2] = -1e9f;
                if (col + 1 > r0g + 8) sacc[t][3] = -1e9f;
            }
        }

        // row max (quad lanes share a row)
        float mh0 = -INFINITY, mh1 = -INFINITY;
        #pragma unroll
        for (int t = 0; t < 8; t++) {
            mh0 = fmaxf(mh0, fmaxf(sacc[t][0], sacc[t][1]));
            mh1 = fmaxf(mh1, fmaxf(sacc[t][2], sacc[t][3]));
        }
        mh0 = fmaxf(mh0, __shfl_xor_sync(0xffffffffu, mh0, 1));
        mh0 = fmaxf(mh0, __shfl_xor_sync(0xffffffffu, mh0, 2));
        mh1 = fmaxf(mh1, __shfl_xor_sync(0xffffffffu, mh1, 1));
        mh1 = fmaxf(mh1, __shfl_xor_sync(0xffffffffu, mh1, 2));
        float mn0 = fmaxf(m0, mh0), mn1 = fmaxf(m1, mh1);
        float c0 = exp2p((m0 - mn0) * Cs);
        float c1 = exp2p((m1 - mn1) * Cs);
        m0 = mn0; m1 = mn1;

        // p = 2^((s-m)*Cs), sum
        float ps0 = 0.f, ps1 = 0.f;
        #pragma unroll
        for (int t = 0; t < 8; t++) {
            float p0 = exp2p((sacc[t][0] - mn0) * Cs);
            float p1 = exp2p((sacc[t][1] - mn0) * Cs);
            float p2 = exp2p((sacc[t][2] - mn1) * Cs);
            float p3 = exp2p((sacc[t][3] - mn1) * Cs);
            sacc[t][0] = p0; sacc[t][1] = p1; sacc[t][2] = p2; sacc[t][3] = p3;
            ps0 += p0 + p1; ps1 += p2 + p3;
        }
        l0 = l0 * c0 + ps0;
        l1 = l1 * c1 + ps1;
        #pragma unroll
        for (int t = 0; t < 8; t++) {
            oacc[t][0] *= c0; oacc[t][1] *= c0;
            oacc[t][2] *= c1; oacc[t][3] *= c1;
        }

        // O += P @ V  (3-term), kk-major to keep P frags short-lived
        #pragma unroll
        for (int kk = 0; kk < 4; kk++) {
            uint32_t PH[4], PL[4];
            pack2hl(sacc[2*kk  ][0], sacc[2*kk  ][1], PH[0], PL[0]);
            pack2hl(sacc[2*kk  ][2], sacc[2*kk  ][3], PH[1], PL[1]);
            pack2hl(sacc[2*kk+1][0], sacc[2*kk+1][1], PH[2], PL[2]);
            pack2hl(sacc[2*kk+1][2], sacc[2*kk+1][3], PH[3], PL[3]);
            int keyrow = kk * 16 + (lane & 7) + 8 * ((lane >> 3) & 1);
            #pragma unroll
            for (int g2 = 0; g2 < 4; g2++) {
                uint32_t bvh[4], bvl[4];
                int dkc = 16 * g2 + 8 * (lane >> 4);
                uint32_t off = swz128((uint32_t)(keyrow * 128 + dkc * 2));
                ldsm_x4_t(bvh, sb + FSVH + off);
                ldsm_x4_t(bvl, sb + FSVL + off);
                mmah(oacc[2*g2+0], PH, bvh[0], bvh[1]);
                mmah(oacc[2*g2+1], PH, bvh[2], bvh[3]);
                mmah(oacc[2*g2+0], PL, bvh[0], bvh[1]);
                mmah(oacc[2*g2+1], PL, bvh[2], bvh[3]);
                mmah(oacc[2*g2+0], PH, bvl[0], bvl[1]);
                mmah(oacc[2*g2+1], PH, bvl[2], bvl[3]);
            }
        }
    }

    // finalize: reduce l over quad, normalize, write ctx hi/lo
    l0 += __shfl_xor_sync(0xffffffffu, l0, 1);
    l0 += __shfl_xor_sync(0xffffffffu, l0, 2);
    l1 += __shfl_xor_sync(0xffffffffu, l1, 1);
    l1 += __shfl_xor_sync(0xffffffffu, l1, 2);
    float inv0 = 1.f / l0, inv1 = 1.f / l1;

    int b = bh >> 4, hh = bh & 15;
    int s0 = qt * 128 + 16 * wid + (lane >> 2);
    int s1 = s0 + 8;
    #pragma unroll
    for (int t = 0; t < 8; t++) {
        int n = 8 * t + 2 * (lane & 3);
        float v0 = oacc[t][0] * inv0, v1 = oacc[t][1] * inv0;
        float v2 = oacc[t][2] * inv1, v3 = oacc[t][3] * inv1;
        size_t i0 = ((size_t)b * SEQ + s0) * D_MODEL + hh * DK + n;
        size_t i1 = ((size_t)b * SEQ + s1) * D_MODEL + hh * DK + n;
        uint32_t H, L;
        pack2hl(v0, v1, H, L);
        *(uint32_t*)&ch[i0] = H; *(uint32_t*)&cl[i0] = L;
        pack2hl(v2, v3, H, L);
        *(uint32_t*)&ch[i1] = H; *(uint32_t*)&cl[i1] = L;
    }
}

// ---------------------------------------------------------------------------
extern "C" void kernel_launch(void* const* d_in, const int* in_sizes, int n_in,
                              void* d_out, int out_size)
{
    const float* Q   = (const float*)d_in[0];
    const float* W_Q = (const float*)d_in[1];
    const float* b_Q = (const float*)d_in[2];
    const float* W_K = (const float*)d_in[3];
    const float* b_K = (const float*)d_in[4];
    const float* W_V = (const float*)d_in[5];
    const float* b_V = (const float*)d_in[6];
    const float* W_O = (const float*)d_in[7];
    const float* b_O = (const float*)d_in[8];
    float* out = (float*)d_out;

    __half *Qh, *Ql, *wh, *wl, *qh, *kh, *vh, *vl, *ch, *cl;
    cudaGetSymbolAddress((void**)&Qh, g_Qh);
    cudaGetSymbolAddress((void**)&Ql, g_Ql);
    cudaGetSymbolAddress((void**)&wh, g_wh);
    cudaGetSymbolAddress((void**)&wl, g_wl);
    cudaGetSymbolAddress((void**)&qh, g_qh);
    cudaGetSymbolAddress((void**)&kh, g_kh);
    cudaGetSymbolAddress((void**)&vh, g_vh);
    cudaGetSymbolAddress((void**)&vl, g_vl);
    cudaGetSymbolAddress((void**)&ch, g_ch);
    cudaGetSymbolAddress((void**)&cl, g_cl);

    cudaFuncSetAttribute(gemm3, cudaFuncAttributeMaxDynamicSharedMemorySize, GT_SMEM);

    // one-time splits (cheap, memory-bound)
    const int nQ = ROWS * D_MODEL;
    split16<<<nQ / 4 / 256, 256>>>(Q, Qh, Ql, nQ);
    split16<<<WELEM / 4 / 256, 256>>>(W_Q, wh + 0*WELEM, wl + 0*WELEM, WELEM);
    split16<<<WELEM / 4 / 256, 256>>>(W_K, wh + 1*WELEM, wl + 1*WELEM, WELEM);
    split16<<<WELEM / 4 / 256, 256>>>(W_V, wh + 2*WELEM, wl + 2*WELEM, WELEM);
    split16<<<WELEM / 4 / 256, 256>>>(W_O, wh + 3*WELEM, wl + 3*WELEM, WELEM);

    dim3 ggrid(D_MODEL / 128, ROWS / 128);   // (8, 32)
    gemm3<<<ggrid, 512, GT_SMEM>>>(Qh, Ql, wh + 0*WELEM, wl + 0*WELEM, b_Q,
                                   nullptr, qh, nullptr, 1);
    gemm3<<<ggrid, 512, GT_SMEM>>>(Qh, Ql, wh + 1*WELEM, wl + 1*WELEM, b_K,
                                   nullptr, kh, nullptr, 1);
    gemm3<<<ggrid, 512, GT_SMEM>>>(Qh, Ql, wh + 2*WELEM, wl + 2*WELEM, b_V,
                                   nullptr, vh, vl, 2);

    flash_tc<<<dim3(SEQ / 128, BATCH * NHEADS), 256, F_SMEM>>>(qh, kh, vh, vl, ch, cl);

    gemm3<<<ggrid, 512, GT_SMEM>>>(ch, cl, wh + 3*WELEM, wl + 3*WELEM, b_O,
                                   out, nullptr, nullptr, 0);
}

// round 6
// speedup vs baseline: 3.8670x; 1.2265x over previous
#include <cuda_runtime.h>
#include <cuda_fp16.h>
#include <math.h>
#include <stdint.h>

#define D_MODEL 1024
#define NHEADS  16
#define DK      64
#define SEQ     2048
#define BATCH   2
#define ROWS    (BATCH*SEQ)   // 4096
#define WELEM   (D_MODEL*D_MODEL)

// fp16 scratch (allocation-free rule: __device__ globals; 16B-aligned)
__device__ __align__(16) __half g_Qh[ROWS*D_MODEL];
__device__ __align__(16) __half g_Ql[ROWS*D_MODEL];
__device__ __align__(16) __half g_wh[4*WELEM];        // Wq,Wk,Wv,Wo hi
__device__ __align__(16) __half g_qh[ROWS*D_MODEL];   // q fp16 [B,H,S,DK]
__device__ __align__(16) __half g_kh[ROWS*D_MODEL];
__device__ __align__(16) __half g_vh[ROWS*D_MODEL];
__device__ __align__(16) __half g_vl[ROWS*D_MODEL];
__device__ __align__(16) __half g_ch[ROWS*D_MODEL];   // ctx hi [B,S,D]
__device__ __align__(16) __half g_cl[ROWS*D_MODEL];

// ===========================================================================
// helpers
// ===========================================================================
__device__ __forceinline__ uint32_t smem_u32(const void* p) {
    uint32_t a;
    asm("{ .reg .u64 t; cvta.to.shared.u64 t, %1; cvt.u32.u64 %0, t; }"
        : "=r"(a) : "l"(p));
    return a;
}
__device__ __forceinline__ uint32_t swz128(uint32_t off) {
    return off ^ ((off >> 3) & 0x70);
}
__device__ __forceinline__ void ldsm_x4(uint32_t* r, uint32_t addr) {
    asm volatile("ldmatrix.sync.aligned.m8n8.x4.shared.b16 {%0,%1,%2,%3}, [%4];"
                 : "=r"(r[0]), "=r"(r[1]), "=r"(r[2]), "=r"(r[3]) : "r"(addr));
}
__device__ __forceinline__ void ldsm_x4_t(uint32_t* r, uint32_t addr) {
    asm volatile("ldmatrix.sync.aligned.m8n8.x4.trans.shared.b16 {%0,%1,%2,%3}, [%4];"
                 : "=r"(r[0]), "=r"(r[1]), "=r"(r[2]), "=r"(r[3]) : "r"(addr));
}
__device__ __forceinline__ void mmah(float* c, const uint32_t* a,
                                     uint32_t b0, uint32_t b1) {
    asm volatile("mma.sync.aligned.m16n8k16.row.col.f32.f16.f16.f32 "
                 "{%0,%1,%2,%3}, {%4,%5,%6,%7}, {%8,%9}, {%0,%1,%2,%3};"
                 : "+f"(c[0]), "+f"(c[1]), "+f"(c[2]), "+f"(c[3])
                 : "r"(a[0]), "r"(a[1]), "r"(a[2]), "r"(a[3]), "r"(b0), "r"(b1));
}
// 2^t via FMA-pipe polynomial (avoids MUFU bottleneck). t <= 0.
__device__ __forceinline__ float exp2p(float t) {
    t = fmaxf(t, -126.0f);
    float i = rintf(t);
    float f = t - i;
    float p = fmaf(f, 0.0096181291f, 0.055504109f);
    p = fmaf(f, p, 0.24022651f);
    p = fmaf(f, p, 0.69314718f);
    p = fmaf(f, p, 1.0f);
    return p * __int_as_float(((int)i + 127) << 23);
}
__device__ __forceinline__ void pack2hl(float a, float b, uint32_t& h, uint32_t& l) {
    __half2 H = __floats2half2_rn(a, b);
    float2 F = __half22float2(H);
    __half2 L = __floats2half2_rn(a - F.x, b - F.y);
    h = *reinterpret_cast<uint32_t*>(&H);
    l = *reinterpret_cast<uint32_t*>(&L);
}

// ===========================================================================
// one-time splits
// ===========================================================================
__global__ void splitQ(const float* __restrict__ s, __half* __restrict__ h,
                       __half* __restrict__ l, int n) {
    int i = (blockIdx.x * blockDim.x + threadIdx.x) * 4;
    if (i >= n) return;
    float4 x = *(const float4*)(s + i);
    __half2 h01 = __floats2half2_rn(x.x, x.y);
    __half2 h23 = __floats2half2_rn(x.z, x.w);
    float2 f01 = __half22float2(h01), f23 = __half22float2(h23);
    *(__half2*)(h + i) = h01; *(__half2*)(h + i + 2) = h23;
    *(__half2*)(l + i)     = __floats2half2_rn(x.x - f01.x, x.y - f01.y);
    *(__half2*)(l + i + 2) = __floats2half2_rn(x.z - f23.x, x.w - f23.y);
}
// 4 weight matrices -> hi halves only (lo term dropped in 2-term GEMM)
__global__ void splitW4(const float* __restrict__ w0, const float* __restrict__ w1,
                        const float* __restrict__ w2, const float* __restrict__ w3,
                        __half* __restrict__ h) {
    int z = blockIdx.y;
    const float* s = (z == 0) ? w0 : (z == 1) ? w1 : (z == 2) ? w2 : w3;
    int i = (blockIdx.x * blockDim.x + threadIdx.x) * 4;
    float4 x = *(const float4*)(s + i);
    __half* hp = h + (size_t)z * WELEM + i;
    *(__half2*)(hp)     = __floats2half2_rn(x.x, x.y);
    *(__half2*)(hp + 2) = __floats2half2_rn(x.z, x.w);
}

// ===========================================================================
// 2-term fp16 GEMM body: C[M,N] = (Ah+Al)[M,1024] @ Bh[N,1024]^T + bias[N]
// CTA 128x128, K-chunk 64, 512 threads (warp grid 4x4, warp tile 32x32).
// mode 0: fp32 [M,N]; mode 1: fp16 [B,H,S,DK]; mode 2: fp16 hi/lo [B,H,S,DK]
// ===========================================================================
#define SM_AH 0
#define SM_AL 16384
#define SM_BH 32768
#define GT_SMEM 49152

__device__ __forceinline__ void gemm2_body(
    const __half* __restrict__ Ah, const __half* __restrict__ Al,
    const __half* __restrict__ Bh, const float* __restrict__ bias,
    float* __restrict__ Cf, __half* __restrict__ Oh, __half* __restrict__ Ol,
    int mode)
{
    extern __shared__ __align__(1024) char smem[];
    const uint32_t sbase = smem_u32(smem);
    const int tid  = threadIdx.x;
    const int wid  = tid >> 5;
    const int lane = tid & 31;
    const int wm   = wid & 3;
    const int wn   = wid >> 2;

    const int m0 = blockIdx.y * 128;
    const int n0 = blockIdx.x * 128;

    int rowi[2], c8i[2];
    uint32_t soff[2];
    #pragma unroll
    for (int i = 0; i < 2; i++) {
        int g = i * 512 + tid;
        rowi[i] = g >> 3;
        c8i[i]  = g & 7;
        soff[i] = swz128((uint32_t)(rowi[i] * 128 + c8i[i] * 16));
    }

    float acc[2][4][4] = {};
    uint4 rA[2], rAl[2], rB[2];

    #pragma unroll
    for (int i = 0; i < 2; i++) {
        size_t ao = (size_t)(m0 + rowi[i]) * D_MODEL + c8i[i] * 8;
        size_t bo = (size_t)(n0 + rowi[i]) * D_MODEL + c8i[i] * 8;
        rA[i]  = *(const uint4*)(Ah + ao);
        rAl[i] = *(const uint4*)(Al + ao);
        rB[i]  = *(const uint4*)(Bh + bo);
    }

    for (int kc = 0; kc < 16; kc++) {
        #pragma unroll
        for (int i = 0; i < 2; i++) {
            asm volatile("st.shared.v4.b32 [%0], {%1,%2,%3,%4};" ::
                "r"(sbase + SM_AH + soff[i]), "r"(rA[i].x), "r"(rA[i].y), "r"(rA[i].z), "r"(rA[i].w));
            asm volatile("st.shared.v4.b32 [%0], {%1,%2,%3,%4};" ::
                "r"(sbase + SM_AL + soff[i]), "r"(rAl[i].x), "r"(rAl[i].y), "r"(rAl[i].z), "r"(rAl[i].w));
            asm volatile("st.shared.v4.b32 [%0], {%1,%2,%3,%4};" ::
                "r"(sbase + SM_BH + soff[i]), "r"(rB[i].x), "r"(rB[i].y), "r"(rB[i].z), "r"(rB[i].w));
        }
        __syncthreads();

        if (kc + 1 < 16) {
            #pragma unroll
            for (int i = 0; i < 2; i++) {
                size_t ao = (size_t)(m0 + rowi[i]) * D_MODEL + (kc + 1) * 64 + c8i[i] * 8;
                size_t bo = (size_t)(n0 + rowi[i]) * D_MODEL + (kc + 1) * 64 + c8i[i] * 8;
                rA[i]  = *(const uint4*)(Ah + ao);
                rAl[i] = *(const uint4*)(Al + ao);
                rB[i]  = *(const uint4*)(Bh + bo);
            }
        }

        #pragma unroll
        for (int ks = 0; ks < 4; ks++) {
            uint32_t ah[2][4], al[2][4];
            #pragma unroll
            for (int mi = 0; mi < 2; mi++) {
                int mrow = wm * 32 + mi * 16 + (lane & 15);
                uint32_t off = swz128((uint32_t)(mrow * 128 + ks * 32 + (lane >> 4) * 16));
                ldsm_x4(ah[mi], sbase + SM_AH + off);
                ldsm_x4(al[mi], sbase + SM_AL + off);
            }
            uint32_t bh[2][4];
            #pragma unroll
            for (int nj = 0; nj < 2; nj++) {
                int nrow = wn * 32 + nj * 16 + (lane & 15);
                uint32_t off = swz128((uint32_t)(nrow * 128 + ks * 32 + (lane >> 4) * 16));
                ldsm_x4(bh[nj], sbase + SM_BH + off);
            }
            #pragma unroll
            for (int mi = 0; mi < 2; mi++)
                #pragma unroll
                for (int nj = 0; nj < 2; nj++) {
                    mmah(acc[mi][nj*2+0], ah[mi], bh[nj][0], bh[nj][2]);
                    mmah(acc[mi][nj*2+1], ah[mi], bh[nj][1], bh[nj][3]);
                    mmah(acc[mi][nj*2+0], al[mi], bh[nj][0], bh[nj][2]);
                    mmah(acc[mi][nj*2+1], al[mi], bh[nj][1], bh[nj][3]);
                }
        }
        __syncthreads();
    }

    #pragma unroll
    for (int mi = 0; mi < 2; mi++) {
        #pragma unroll
        for (int nj = 0; nj < 4; nj++) {
            int gj = n0 + wn * 32 + nj * 8 + (lane & 3) * 2;
            float bi0 = __ldg(bias + gj), bi1 = __ldg(bias + gj + 1);
            #pragma unroll
            for (int half = 0; half < 2; half++) {
                int gi = m0 + wm * 32 + mi * 16 + (lane >> 2) + half * 8;
                float v0 = acc[mi][nj][half*2+0] + bi0;
                float v1 = acc[mi][nj][half*2+1] + bi1;
                if (mode == 0) {
                    *(float2*)&Cf[(size_t)gi * D_MODEL + gj] = make_float2(v0, v1);
                } else {
                    int b = gi >> 11, s = gi & (SEQ - 1);
                    int h = gj >> 6,  d = gj & (DK - 1);
                    size_t idx = (((size_t)(b * NHEADS + h) * SEQ) + s) * DK + d;
                    if (mode == 1) {
                        __half2 H = __floats2half2_rn(v0, v1);
                        *(__half2*)&Oh[idx] = H;
                    } else {
                        __half2 H = __floats2half2_rn(v0, v1);
                        float2 F = __half22float2(H);
                        __half2 L = __floats2half2_rn(v0 - F.x, v1 - F.y);
                        *(__half2*)&Oh[idx] = H;
                        *(__half2*)&Ol[idx] = L;
                    }
                }
            }
        }
    }
}

// fused Q/K/V projection: grid (8, 32, 3), z selects weight/bias/output
__global__ __launch_bounds__(512, 1)
void gemm_qkv(const __half* __restrict__ Ah, const __half* __restrict__ Al,
              const __half* __restrict__ wh,
              const float* __restrict__ bQ, const float* __restrict__ bK,
              const float* __restrict__ bV,
              __half* __restrict__ qh, __half* __restrict__ kh,
              __half* __restrict__ vh, __half* __restrict__ vl)
{
    int z = blockIdx.z;
    const __half* Bh = wh + (size_t)z * WELEM;
    if (z == 0)      gemm2_body(Ah, Al, Bh, bQ, nullptr, qh, nullptr, 1);
    else if (z == 1) gemm2_body(Ah, Al, Bh, bK, nullptr, kh, nullptr, 1);
    else             gemm2_body(Ah, Al, Bh, bV, nullptr, vh, vl, 2);
}

__global__ __launch_bounds__(512, 1)
void gemm_o(const __half* __restrict__ ch, const __half* __restrict__ cl,
            const __half* __restrict__ woh, const float* __restrict__ bO,
            float* __restrict__ out)
{
    gemm2_body(ch, cl, woh, bO, out, nullptr, nullptr, 0);
}

// ===========================================================================
// Causal flash attention, fp16 tensor-core (unchanged from R5).
// CTA: 128 q-rows x 64-key tiles, 8 warps.
// ===========================================================================
#define FSQ  0
#define FSK  16384
#define FSVH 24576
#define FSVL 32768
#define F_SMEM 40960

__global__ __launch_bounds__(256)
void flash_tc(const __half* __restrict__ qh, const __half* __restrict__ kh,
              const __half* __restrict__ vh, const __half* __restrict__ vl,
              __half* __restrict__ ch, __half* __restrict__ cl)
{
    extern __shared__ __align__(1024) char smem[];
    const uint32_t sb = smem_u32(smem);
    const int tid  = threadIdx.x;
    const int wid  = tid >> 5;
    const int lane = tid & 31;
    const int qt   = (gridDim.x - 1) - blockIdx.x;
    const int bh   = blockIdx.y;
    const size_t base = (size_t)bh * SEQ * DK;
    const float Cs = 0.18033688011f;   // 0.125 * log2(e)

    #pragma unroll
    for (int i = 0; i < 4; i++) {
        int c = i * 256 + tid;
        int r = c >> 3, c8 = c & 7;
        uint4 d = *(const uint4*)(qh + base + (size_t)(qt * 128 + r) * DK + c8 * 8);
        asm volatile("st.shared.v4.b32 [%0], {%1,%2,%3,%4};" ::
            "r"(sb + FSQ + swz128((uint32_t)(r * 128 + c8 * 16))),
            "r"(d.x), "r"(d.y), "r"(d.z), "r"(d.w));
    }
    __syncthreads();

    uint32_t qf[4][4];
    #pragma unroll
    for (int ks = 0; ks < 4; ks++) {
        uint32_t off = swz128((uint32_t)((16 * wid + (lane & 15)) * 128 + ks * 32 + (lane >> 4) * 16));
        ldsm_x4(qf[ks], sb + FSQ + off);
    }

    float oacc[8][4] = {};
    float m0 = -INFINITY, m1 = -INFINITY, l0 = 0.f, l1 = 0.f;
    const int r0g = qt * 128 + 16 * wid + (lane >> 2);

    const int nkt = 2 * qt + 2;
    for (int kt = 0; kt < nkt; kt++) {
        __syncthreads();
        #pragma unroll
        for (int i = 0; i < 2; i++) {
            int c = i * 256 + tid;
            int r = c >> 3, c8 = c & 7;
            size_t go = base + (size_t)(kt * 64 + r) * DK + c8 * 8;
            uint32_t so = swz128((uint32_t)(r * 128 + c8 * 16));
            uint4 dk_ = *(const uint4*)(kh + go);
            uint4 dvh = *(const uint4*)(vh + go);
            uint4 dvl = *(const uint4*)(vl + go);
            asm volatile("st.shared.v4.b32 [%0], {%1,%2,%3,%4};" ::
                "r"(sb + FSK + so), "r"(dk_.x), "r"(dk_.y), "r"(dk_.z), "r"(dk_.w));
            asm volatile("st.shared.v4.b32 [%0], {%1,%2,%3,%4};" ::
                "r"(sb + FSVH + so), "r"(dvh.x), "r"(dvh.y), "r"(dvh.z), "r"(dvh.w));
            asm volatile("st.shared.v4.b32 [%0], {%1,%2,%3,%4};" ::
                "r"(sb + FSVL + so), "r"(dvl.x), "r"(dvl.y), "r"(dvl.z), "r"(dvl.w));
        }
        __syncthreads();

        float sacc[8][4] = {};
        #pragma unroll
        for (int g = 0; g < 4; g++) {
            #pragma unroll
            for (int ks = 0; ks < 4; ks++) {
                uint32_t bf[4];
                uint32_t off = swz128((uint32_t)((16 * g + (lane & 15)) * 128 + ks * 32 + (lane >> 4) * 16));
                ldsm_x4(bf, sb + FSK + off);
                mmah(sacc[2*g+0], qf[ks], bf[0], bf[2]);
                mmah(sacc[2*g+1], qf[ks], bf[1], bf[3]);
            }
        }

        if (kt * 64 + 63 > qt * 128 + 16 * wid) {
            #pragma unroll
            for (int t = 0; t < 8; t++) {
                int col = kt * 64 + 8 * t + 2 * (lane & 3);
                if (col     > r0g)     sacc[t][0] = -1e9f;
                if (col + 1 > r0g)     sacc[t][1] = -1e9f;
                if (col     > r0g + 8) sacc[t][2] = -1e9f;
                if (col + 1 > r0g + 8) sacc[t][3] = -1e9f;
            }
        }

        float mh0 = -INFINITY, mh1 = -INFINITY;
        #pragma unroll
        for (int t = 0; t < 8; t++) {
            mh0 = fmaxf(mh0, fmaxf(sacc[t][0], sacc[t][1]));
            mh1 = fmaxf(mh1, fmaxf(sacc[t][2], sacc[t][3]));
        }
        mh0 = fmaxf(mh0, __shfl_xor_sync(0xffffffffu, mh0, 1));
        mh0 = fmaxf(mh0, __shfl_xor_sync(0xffffffffu, mh0, 2));
        mh1 = fmaxf(mh1, __shfl_xor_sync(0xffffffffu, mh1, 1));
        mh1 = fmaxf(mh1, __shfl_xor_sync(0xffffffffu, mh1, 2));
        float mn0 = fmaxf(m0, mh0), mn1 = fmaxf(m1, mh1);
        float c0 = exp2p((m0 - mn0) * Cs);
        float c1 = exp2p((m1 - mn1) * Cs);
        m0 = mn0; m1 = mn1;

        float ps0 = 0.f, ps1 = 0.f;
        #pragma unroll
        for (int t = 0; t < 8; t++) {
            float p0 = exp2p((sacc[t][0] - mn0) * Cs);
            float p1 = exp2p((sacc[t][1] - mn0) * Cs);
            float p2 = exp2p((sacc[t][2] - mn1) * Cs);
            float p3 = exp2p((sacc[t][3] - mn1) * Cs);
            sacc[t][0] = p0; sacc[t][1] = p1; sacc[t][2] = p2; sacc[t][3] = p3;
            ps0 += p0 + p1; ps1 += p2 + p3;
        }
        l0 = l0 * c0 + ps0;
        l1 = l1 * c1 + ps1;
        #pragma unroll
        for (int t = 0; t < 8; t++) {
            oacc[t][0] *= c0; oacc[t][1] *= c0;
            oacc[t][2] *= c1; oacc[t][3] *= c1;
        }

        #pragma unroll
        for (int kk = 0; kk < 4; kk++) {
            uint32_t PH[4], PL[4];
            pack2hl(sacc[2*kk  ][0], sacc[2*kk  ][1], PH[0], PL[0]);
            pack2hl(sacc[2*kk  ][2], sacc[2*kk  ][3], PH[1], PL[1]);
            pack2hl(sacc[2*kk+1][0], sacc[2*kk+1][1], PH[2], PL[2]);
            pack2hl(sacc[2*kk+1][2], sacc[2*kk+1][3], PH[3], PL[3]);
            int keyrow = kk * 16 + (lane & 7) + 8 * ((lane >> 3) & 1);
            #pragma unroll
            for (int g2 = 0; g2 < 4; g2++) {
                uint32_t bvh[4], bvl[4];
                int dkc = 16 * g2 + 8 * (lane >> 4);
                uint32_t off = swz128((uint32_t)(keyrow * 128 + dkc * 2));
                ldsm_x4_t(bvh, sb + FSVH + off);
                ldsm_x4_t(bvl, sb + FSVL + off);
                mmah(oacc[2*g2+0], PH, bvh[0], bvh[1]);
                mmah(oacc[2*g2+1], PH, bvh[2], bvh[3]);
                mmah(oacc[2*g2+0], PL, bvh[0], bvh[1]);
                mmah(oacc[2*g2+1], PL, bvh[2], bvh[3]);
                mmah(oacc[2*g2+0], PH, bvl[0], bvl[1]);
                mmah(oacc[2*g2+1], PH, bvl[2], bvl[3]);
            }
        }
    }

    l0 += __shfl_xor_sync(0xffffffffu, l0, 1);
    l0 += __shfl_xor_sync(0xffffffffu, l0, 2);
    l1 += __shfl_xor_sync(0xffffffffu, l1, 1);
    l1 += __shfl_xor_sync(0xffffffffu, l1, 2);
    float inv0 = 1.f / l0, inv1 = 1.f / l1;

    int b = bh >> 4, hh = bh & 15;
    int s0 = qt * 128 + 16 * wid + (lane >> 2);
    int s1 = s0 + 8;
    #pragma unroll
    for (int t = 0; t < 8; t++) {
        int n = 8 * t + 2 * (lane & 3);
        float v0 = oacc[t][0] * inv0, v1 = oacc[t][1] * inv0;
        float v2 = oacc[t][2] * inv1, v3 = oacc[t][3] * inv1;
        size_t i0 = ((size_t)b * SEQ + s0) * D_MODEL + hh * DK + n;
        size_t i1 = ((size_t)b * SEQ + s1) * D_MODEL + hh * DK + n;
        uint32_t H, L;
        pack2hl(v0, v1, H, L);
        *(uint32_t*)&ch[i0] = H; *(uint32_t*)&cl[i0] = L;
        pack2hl(v2, v3, H, L);
        *(uint32_t*)&ch[i1] = H; *(uint32_t*)&cl[i1] = L;
    }
}

// ---------------------------------------------------------------------------
extern "C" void kernel_launch(void* const* d_in, const int* in_sizes, int n_in,
                              void* d_out, int out_size)
{
    const float* Q   = (const float*)d_in[0];
    const float* W_Q = (const float*)d_in[1];
    const float* b_Q = (const float*)d_in[2];
    const float* W_K = (const float*)d_in[3];
    const float* b_K = (const float*)d_in[4];
    const float* W_V = (const float*)d_in[5];
    const float* b_V = (const float*)d_in[6];
    const float* W_O = (const float*)d_in[7];
    const float* b_O = (const float*)d_in[8];
    float* out = (float*)d_out;

    __half *Qh, *Ql, *wh, *qh, *kh, *vh, *vl, *ch, *cl;
    cudaGetSymbolAddress((void**)&Qh, g_Qh);
    cudaGetSymbolAddress((void**)&Ql, g_Ql);
    cudaGetSymbolAddress((void**)&wh, g_wh);
    cudaGetSymbolAddress((void**)&qh, g_qh);
    cudaGetSymbolAddress((void**)&kh, g_kh);
    cudaGetSymbolAddress((void**)&vh, g_vh);
    cudaGetSymbolAddress((void**)&vl, g_vl);
    cudaGetSymbolAddress((void**)&ch, g_ch);
    cudaGetSymbolAddress((void**)&cl, g_cl);

    cudaFuncSetAttribute(gemm_qkv, cudaFuncAttributeMaxDynamicSharedMemorySize, GT_SMEM);
    cudaFuncSetAttribute(gemm_o,   cudaFuncAttributeMaxDynamicSharedMemorySize, GT_SMEM);

    const int nQ = ROWS * D_MODEL;
    splitQ<<<nQ / 4 / 256, 256>>>(Q, Qh, Ql, nQ);
    splitW4<<<dim3(WELEM / 4 / 256, 4), 256>>>(W_Q, W_K, W_V, W_O, wh);

    gemm_qkv<<<dim3(8, 32, 3), 512, GT_SMEM>>>(Qh, Ql, wh, b_Q, b_K, b_V,
                                               qh, kh, vh, vl);

    flash_tc<<<dim3(SEQ / 128, BATCH * NHEADS), 256, F_SMEM>>>(qh, kh, vh, vl, ch, cl);

    gemm_o<<<dim3(8, 32), 512, GT_SMEM>>>(ch, cl, wh + 3 * (size_t)WELEM, b_O, out);
}

// round 7
// speedup vs baseline: 4.1072x; 1.0621x over previous
#include <cuda_runtime.h>
#include <cuda_fp16.h>
#include <math.h>
#include <stdint.h>

#define D_MODEL 1024
#define NHEADS  16
#define DK      64
#define SEQ     2048
#define BATCH   2
#define ROWS    (BATCH*SEQ)   // 4096
#define WELEM   (D_MODEL*D_MODEL)

// fp16 scratch (allocation-free rule: __device__ globals; 16B-aligned)
__device__ __align__(16) __half g_Qh[ROWS*D_MODEL];
__device__ __align__(16) __half g_Ql[ROWS*D_MODEL];
__device__ __align__(16) __half g_wh[4*WELEM];        // Wq,Wk,Wv,Wo hi
__device__ __align__(16) __half g_qh[ROWS*D_MODEL];   // q fp16 [B,H,S,DK]
__device__ __align__(16) __half g_kh[ROWS*D_MODEL];
__device__ __align__(16) __half g_vh[ROWS*D_MODEL];
__device__ __align__(16) __half g_ch[ROWS*D_MODEL];   // ctx hi [B,S,D]
__device__ __align__(16) __half g_cl[ROWS*D_MODEL];

// ===========================================================================
// helpers
// ===========================================================================
__device__ __forceinline__ uint32_t smem_u32(const void* p) {
    uint32_t a;
    asm("{ .reg .u64 t; cvta.to.shared.u64 t, %1; cvt.u32.u64 %0, t; }"
        : "=r"(a) : "l"(p));
    return a;
}
__device__ __forceinline__ uint32_t swz128(uint32_t off) {
    return off ^ ((off >> 3) & 0x70);
}
__device__ __forceinline__ void ldsm_x4(uint32_t* r, uint32_t addr) {
    asm volatile("ldmatrix.sync.aligned.m8n8.x4.shared.b16 {%0,%1,%2,%3}, [%4];"
                 : "=r"(r[0]), "=r"(r[1]), "=r"(r[2]), "=r"(r[3]) : "r"(addr));
}
__device__ __forceinline__ void ldsm_x4_t(uint32_t* r, uint32_t addr) {
    asm volatile("ldmatrix.sync.aligned.m8n8.x4.trans.shared.b16 {%0,%1,%2,%3}, [%4];"
                 : "=r"(r[0]), "=r"(r[1]), "=r"(r[2]), "=r"(r[3]) : "r"(addr));
}
__device__ __forceinline__ void mmah(float* c, const uint32_t* a,
                                     uint32_t b0, uint32_t b1) {
    asm volatile("mma.sync.aligned.m16n8k16.row.col.f32.f16.f16.f32 "
                 "{%0,%1,%2,%3}, {%4,%5,%6,%7}, {%8,%9}, {%0,%1,%2,%3};"
                 : "+f"(c[0]), "+f"(c[1]), "+f"(c[2]), "+f"(c[3])
                 : "r"(a[0]), "r"(a[1]), "r"(a[2]), "r"(a[3]), "r"(b0), "r"(b1));
}
// 2^t via FMA-pipe polynomial (avoids MUFU bottleneck). t <= 0.
__device__ __forceinline__ float exp2p(float t) {
    t = fmaxf(t, -126.0f);
    float i = rintf(t);
    float f = t - i;
    float p = fmaf(f, 0.0096181291f, 0.055504109f);
    p = fmaf(f, p, 0.24022651f);
    p = fmaf(f, p, 0.69314718f);
    p = fmaf(f, p, 1.0f);
    return p * __int_as_float(((int)i + 127) << 23);
}
__device__ __forceinline__ void pack2hl(float a, float b, uint32_t& h, uint32_t& l) {
    __half2 H = __floats2half2_rn(a, b);
    float2 F = __half22float2(H);
    __half2 L = __floats2half2_rn(a - F.x, b - F.y);
    h = *reinterpret_cast<uint32_t*>(&H);
    l = *reinterpret_cast<uint32_t*>(&L);
}

// ===========================================================================
// one-time splits
// ===========================================================================
__global__ void splitQ(const float* __restrict__ s, __half* __restrict__ h,
                       __half* __restrict__ l, int n) {
    int i = (blockIdx.x * blockDim.x + threadIdx.x) * 4;
    if (i >= n) return;
    float4 x = *(const float4*)(s + i);
    __half2 h01 = __floats2half2_rn(x.x, x.y);
    __half2 h23 = __floats2half2_rn(x.z, x.w);
    float2 f01 = __half22float2(h01), f23 = __half22float2(h23);
    *(__half2*)(h + i) = h01; *(__half2*)(h + i + 2) = h23;
    *(__half2*)(l + i)     = __floats2half2_rn(x.x - f01.x, x.y - f01.y);
    *(__half2*)(l + i + 2) = __floats2half2_rn(x.z - f23.x, x.w - f23.y);
}
__global__ void splitW4(const float* __restrict__ w0, const float* __restrict__ w1,
                        const float* __restrict__ w2, const float* __restrict__ w3,
                        __half* __restrict__ h) {
    int z = blockIdx.y;
    const float* s = (z == 0) ? w0 : (z == 1) ? w1 : (z == 2) ? w2 : w3;
    int i = (blockIdx.x * blockDim.x + threadIdx.x) * 4;
    float4 x = *(const float4*)(s + i);
    __half* hp = h + (size_t)z * WELEM + i;
    *(__half2*)(hp)     = __floats2half2_rn(x.x, x.y);
    *(__half2*)(hp + 2) = __floats2half2_rn(x.z, x.w);
}

// ===========================================================================
// 2-term fp16 GEMM body: C[M,N] = (Ah+Al)[M,1024] @ Bh[N,1024]^T + bias[N]
// CTA 128x128, K-chunk 64, 512 threads (warp grid 4x4, warp tile 32x32).
// mode 0: fp32 [M,N]; mode 1: fp16 [B,H,S,DK]
// ===========================================================================
#define SM_AH 0
#define SM_AL 16384
#define SM_BH 32768
#define GT_SMEM 49152

__device__ __forceinline__ void gemm2_body(
    const __half* __restrict__ Ah, const __half* __restrict__ Al,
    const __half* __restrict__ Bh, const float* __restrict__ bias,
    float* __restrict__ Cf, __half* __restrict__ Oh, int mode)
{
    extern __shared__ __align__(1024) char smem[];
    const uint32_t sbase = smem_u32(smem);
    const int tid  = threadIdx.x;
    const int wid  = tid >> 5;
    const int lane = tid & 31;
    const int wm   = wid & 3;
    const int wn   = wid >> 2;

    const int m0 = blockIdx.y * 128;
    const int n0 = blockIdx.x * 128;

    int rowi[2], c8i[2];
    uint32_t soff[2];
    #pragma unroll
    for (int i = 0; i < 2; i++) {
        int g = i * 512 + tid;
        rowi[i] = g >> 3;
        c8i[i]  = g & 7;
        soff[i] = swz128((uint32_t)(rowi[i] * 128 + c8i[i] * 16));
    }

    float acc[2][4][4] = {};
    uint4 rA[2], rAl[2], rB[2];

    #pragma unroll
    for (int i = 0; i < 2; i++) {
        size_t ao = (size_t)(m0 + rowi[i]) * D_MODEL + c8i[i] * 8;
        size_t bo = (size_t)(n0 + rowi[i]) * D_MODEL + c8i[i] * 8;
        rA[i]  = *(const uint4*)(Ah + ao);
        rAl[i] = *(const uint4*)(Al + ao);
        rB[i]  = *(const uint4*)(Bh + bo);
    }

    for (int kc = 0; kc < 16; kc++) {
        #pragma unroll
        for (int i = 0; i < 2; i++) {
            asm volatile("st.shared.v4.b32 [%0], {%1,%2,%3,%4};" ::
                "r"(sbase + SM_AH + soff[i]), "r"(rA[i].x), "r"(rA[i].y), "r"(rA[i].z), "r"(rA[i].w));
            asm volatile("st.shared.v4.b32 [%0], {%1,%2,%3,%4};" ::
                "r"(sbase + SM_AL + soff[i]), "r"(rAl[i].x), "r"(rAl[i].y), "r"(rAl[i].z), "r"(rAl[i].w));
            asm volatile("st.shared.v4.b32 [%0], {%1,%2,%3,%4};" ::
                "r"(sbase + SM_BH + soff[i]), "r"(rB[i].x), "r"(rB[i].y), "r"(rB[i].z), "r"(rB[i].w));
        }
        __syncthreads();

        if (kc + 1 < 16) {
            #pragma unroll
            for (int i = 0; i < 2; i++) {
                size_t ao = (size_t)(m0 + rowi[i]) * D_MODEL + (kc + 1) * 64 + c8i[i] * 8;
                size_t bo = (size_t)(n0 + rowi[i]) * D_MODEL + (kc + 1) * 64 + c8i[i] * 8;
                rA[i]  = *(const uint4*)(Ah + ao);
                rAl[i] = *(const uint4*)(Al + ao);
                rB[i]  = *(const uint4*)(Bh + bo);
            }
        }

        #pragma unroll
        for (int ks = 0; ks < 4; ks++) {
            uint32_t ah[2][4], al[2][4];
            #pragma unroll
            for (int mi = 0; mi < 2; mi++) {
                int mrow = wm * 32 + mi * 16 + (lane & 15);
                uint32_t off = swz128((uint32_t)(mrow * 128 + ks * 32 + (lane >> 4) * 16));
                ldsm_x4(ah[mi], sbase + SM_AH + off);
                ldsm_x4(al[mi], sbase + SM_AL + off);
            }
            uint32_t bh[2][4];
            #pragma unroll
            for (int nj = 0; nj < 2; nj++) {
                int nrow = wn * 32 + nj * 16 + (lane & 15);
                uint32_t off = swz128((uint32_t)(nrow * 128 + ks * 32 + (lane >> 4) * 16));
                ldsm_x4(bh[nj], sbase + SM_BH + off);
            }
            #pragma unroll
            for (int mi = 0; mi < 2; mi++)
                #pragma unroll
                for (int nj = 0; nj < 2; nj++) {
                    mmah(acc[mi][nj*2+0], ah[mi], bh[nj][0], bh[nj][2]);
                    mmah(acc[mi][nj*2+1], ah[mi], bh[nj][1], bh[nj][3]);
                    mmah(acc[mi][nj*2+0], al[mi], bh[nj][0], bh[nj][2]);
                    mmah(acc[mi][nj*2+1], al[mi], bh[nj][1], bh[nj][3]);
                }
        }
        __syncthreads();
    }

    #pragma unroll
    for (int mi = 0; mi < 2; mi++) {
        #pragma unroll
        for (int nj = 0; nj < 4; nj++) {
            int gj = n0 + wn * 32 + nj * 8 + (lane & 3) * 2;
            float bi0 = __ldg(bias + gj), bi1 = __ldg(bias + gj + 1);
            #pragma unroll
            for (int half = 0; half < 2; half++) {
                int gi = m0 + wm * 32 + mi * 16 + (lane >> 2) + half * 8;
                float v0 = acc[mi][nj][half*2+0] + bi0;
                float v1 = acc[mi][nj][half*2+1] + bi1;
                if (mode == 0) {
                    *(float2*)&Cf[(size_t)gi * D_MODEL + gj] = make_float2(v0, v1);
                } else {
                    int b = gi >> 11, s = gi & (SEQ - 1);
                    int h = gj >> 6,  d = gj & (DK - 1);
                    size_t idx = (((size_t)(b * NHEADS + h) * SEQ) + s) * DK + d;
                    __half2 H = __floats2half2_rn(v0, v1);
                    *(__half2*)&Oh[idx] = H;
                }
            }
        }
    }
}

// fused Q/K/V projection: grid (8, 32, 3), z selects weight/bias/output
__global__ __launch_bounds__(512, 1)
void gemm_qkv(const __half* __restrict__ Ah, const __half* __restrict__ Al,
              const __half* __restrict__ wh,
              const float* __restrict__ bQ, const float* __restrict__ bK,
              const float* __restrict__ bV,
              __half* __restrict__ qh, __half* __restrict__ kh,
              __half* __restrict__ vh)
{
    int z = blockIdx.z;
    const __half* Bh = wh + (size_t)z * WELEM;
    if (z == 0)      gemm2_body(Ah, Al, Bh, bQ, nullptr, qh, 1);
    else if (z == 1) gemm2_body(Ah, Al, Bh, bK, nullptr, kh, 1);
    else             gemm2_body(Ah, Al, Bh, bV, nullptr, vh, 1);
}

__global__ __launch_bounds__(512, 1)
void gemm_o(const __half* __restrict__ ch, const __half* __restrict__ cl,
            const __half* __restrict__ woh, const float* __restrict__ bO,
            float* __restrict__ out)
{
    gemm2_body(ch, cl, woh, bO, out, nullptr, 0);
}

// ===========================================================================
// Causal flash attention, fp16 tensor-core.
// CTA: 128 q-rows x 64-key tiles, 8 warps, 2 CTAs/SM.
// QK 1-term; PV 2-term (PhVh + PlVh). Softmax on FMA pipe.
// ===========================================================================
#define FSQ  0
#define FSK  16384
#define FSVH 24576
#define F_SMEM 32768

__global__ __launch_bounds__(256, 2)
void flash_tc(const __half* __restrict__ qh, const __half* __restrict__ kh,
              const __half* __restrict__ vh,
              __half* __restrict__ ch, __half* __restrict__ cl)
{
    extern __shared__ __align__(1024) char smem[];
    const uint32_t sb = smem_u32(smem);
    const int tid  = threadIdx.x;
    const int wid  = tid >> 5;
    const int lane = tid & 31;
    const int qt   = (gridDim.x - 1) - blockIdx.x;
    const int bh   = blockIdx.y;
    const size_t base = (size_t)bh * SEQ * DK;
    const float Cs = 0.18033688011f;   // 0.125 * log2(e)

    #pragma unroll
    for (int i = 0; i < 4; i++) {
        int c = i * 256 + tid;
        int r = c >> 3, c8 = c & 7;
        uint4 d = *(const uint4*)(qh + base + (size_t)(qt * 128 + r) * DK + c8 * 8);
        asm volatile("st.shared.v4.b32 [%0], {%1,%2,%3,%4};" ::
            "r"(sb + FSQ + swz128((uint32_t)(r * 128 + c8 * 16))),
            "r"(d.x), "r"(d.y), "r"(d.z), "r"(d.w));
    }
    __syncthreads();

    uint32_t qf[4][4];
    #pragma unroll
    for (int ks = 0; ks < 4; ks++) {
        uint32_t off = swz128((uint32_t)((16 * wid + (lane & 15)) * 128 + ks * 32 + (lane >> 4) * 16));
        ldsm_x4(qf[ks], sb + FSQ + off);
    }

    float oacc[8][4] = {};
    float m0 = -INFINITY, m1 = -INFINITY, l0 = 0.f, l1 = 0.f;
    const int r0g = qt * 128 + 16 * wid + (lane >> 2);

    const int nkt = 2 * qt + 2;
    for (int kt = 0; kt < nkt; kt++) {
        __syncthreads();
        #pragma unroll
        for (int i = 0; i < 2; i++) {
            int c = i * 256 + tid;
            int r = c >> 3, c8 = c & 7;
            size_t go = base + (size_t)(kt * 64 + r) * DK + c8 * 8;
            uint32_t so = swz128((uint32_t)(r * 128 + c8 * 16));
            uint4 dk_ = *(const uint4*)(kh + go);
            uint4 dvh = *(const uint4*)(vh + go);
            asm volatile("st.shared.v4.b32 [%0], {%1,%2,%3,%4};" ::
                "r"(sb + FSK + so), "r"(dk_.x), "r"(dk_.y), "r"(dk_.z), "r"(dk_.w));
            asm volatile("st.shared.v4.b32 [%0], {%1,%2,%3,%4};" ::
                "r"(sb + FSVH + so), "r"(dvh.x), "r"(dvh.y), "r"(dvh.z), "r"(dvh.w));
        }
        __syncthreads();

        float sacc[8][4] = {};
        #pragma unroll
        for (int g = 0; g < 4; g++) {
            #pragma unroll
            for (int ks = 0; ks < 4; ks++) {
                uint32_t bf[4];
                uint32_t off = swz128((uint32_t)((16 * g + (lane & 15)) * 128 + ks * 32 + (lane >> 4) * 16));
                ldsm_x4(bf, sb + FSK + off);
                mmah(sacc[2*g+0], qf[ks], bf[0], bf[2]);
                mmah(sacc[2*g+1], qf[ks], bf[1], bf[3]);
            }
        }

        if (kt * 64 + 63 > qt * 128 + 16 * wid) {
            #pragma unroll
            for (int t = 0; t < 8; t++) {
                int col = kt * 64 + 8 * t + 2 * (lane & 3);
                if (col     > r0g)     sacc[t][0] = -1e9f;
                if (col + 1 > r0g)     sacc[t][1] = -1e9f;
                if (col     > r0g + 8) sacc[t][2] = -1e9f;
                if (col + 1 > r0g + 8) sacc[t][3] = -1e9f;
            }
        }

        float mh0 = -INFINITY, mh1 = -INFINITY;
        #pragma unroll
        for (int t = 0; t < 8; t++) {
            mh0 = fmaxf(mh0, fmaxf(sacc[t][0], sacc[t][1]));
            mh1 = fmaxf(mh1, fmaxf(sacc[t][2], sacc[t][3]));
        }
        mh0 = fmaxf(mh0, __shfl_xor_sync(0xffffffffu, mh0, 1));
        mh0 = fmaxf(mh0, __shfl_xor_sync(0xffffffffu, mh0, 2));
        mh1 = fmaxf(mh1, __shfl_xor_sync(0xffffffffu, mh1, 1));
        mh1 = fmaxf(mh1, __shfl_xor_sync(0xffffffffu, mh1, 2));
        float mn0 = fmaxf(m0, mh0), mn1 = fmaxf(m1, mh1);
        float c0 = exp2p((m0 - mn0) * Cs);
        float c1 = exp2p((m1 - mn1) * Cs);
        m0 = mn0; m1 = mn1;

        float ps0 = 0.f, ps1 = 0.f;
        #pragma unroll
        for (int t = 0; t < 8; t++) {
            float p0 = exp2p((sacc[t][0] - mn0) * Cs);
            float p1 = exp2p((sacc[t][1] - mn0) * Cs);
            float p2 = exp2p((sacc[t][2] - mn1) * Cs);
            float p3 = exp2p((sacc[t][3] - mn1) * Cs);
            sacc[t][0] = p0; sacc[t][1] = p1; sacc[t][2] = p2; sacc[t][3] = p3;
            ps0 += p0 + p1; ps1 += p2 + p3;
        }
        l0 = l0 * c0 + ps0;
        l1 = l1 * c1 + ps1;
        #pragma unroll
        for (int t = 0; t < 8; t++) {
            oacc[t][0] *= c0; oacc[t][1] *= c0;
            oacc[t][2] *= c1; oacc[t][3] *= c1;
        }

        // O += P @ V  (2-term: PhVh + PlVh)
        #pragma unroll
        for (int kk = 0; kk < 4; kk++) {
            uint32_t PH[4], PL[4];
            pack2hl(sacc[2*kk  ][0], sacc[2*kk  ][1], PH[0], PL[0]);
            pack2hl(sacc[2*kk  ][2], sacc[2*kk  ][3], PH[1], PL[1]);
            pack2hl(sacc[2*kk+1][0], sacc[2*kk+1][1], PH[2], PL[2]);
            pack2hl(sacc[2*kk+1][2], sacc[2*kk+1][3], PH[3], PL[3]);
            int keyrow = kk * 16 + (lane & 7) + 8 * ((lane >> 3) & 1);
            #pragma unroll
            for (int g2 = 0; g2 < 4; g2++) {
                uint32_t bvh[4];
                int dkc = 16 * g2 + 8 * (lane >> 4);
                uint32_t off = swz128((uint32_t)(keyrow * 128 + dkc * 2));
                ldsm_x4_t(bvh, sb + FSVH + off);
                mmah(oacc[2*g2+0], PH, bvh[0], bvh[1]);
                mmah(oacc[2*g2+1], PH, bvh[2], bvh[3]);
                mmah(oacc[2*g2+0], PL, bvh[0], bvh[1]);
                mmah(oacc[2*g2+1], PL, bvh[2], bvh[3]);
            }
        }
    }

    l0 += __shfl_xor_sync(0xffffffffu, l0, 1);
    l0 += __shfl_xor_sync(0xffffffffu, l0, 2);
    l1 += __shfl_xor_sync(0xffffffffu, l1, 1);
    l1 += __shfl_xor_sync(0xffffffffu, l1, 2);
    float inv0 = 1.f / l0, inv1 = 1.f / l1;

    int b = bh >> 4, hh = bh & 15;
    int s0 = qt * 128 + 16 * wid + (lane >> 2);
    int s1 = s0 + 8;
    #pragma unroll
    for (int t = 0; t < 8; t++) {
        int n = 8 * t + 2 * (lane & 3);
        float v0 = oacc[t][0] * inv0, v1 = oacc[t][1] * inv0;
        float v2 = oacc[t][2] * inv1, v3 = oacc[t][3] * inv1;
        size_t i0 = ((size_t)b * SEQ + s0) * D_MODEL + hh * DK + n;
        size_t i1 = ((size_t)b * SEQ + s1) * D_MODEL + hh * DK + n;
        uint32_t H, L;
        pack2hl(v0, v1, H, L);
        *(uint32_t*)&ch[i0] = H; *(uint32_t*)&cl[i0] = L;
        pack2hl(v2, v3, H, L);
        *(uint32_t*)&ch[i1] = H; *(uint32_t*)&cl[i1] = L;
    }
}

// ---------------------------------------------------------------------------
extern "C" void kernel_launch(void* const* d_in, const int* in_sizes, int n_in,
                              void* d_out, int out_size)
{
    const float* Q   = (const float*)d_in[0];
    const float* W_Q = (const float*)d_in[1];
    const float* b_Q = (const float*)d_in[2];
    const float* W_K = (const float*)d_in[3];
    const float* b_K = (const float*)d_in[4];
    const float* W_V = (const float*)d_in[5];
    const float* b_V = (const float*)d_in[6];
    const float* W_O = (const float*)d_in[7];
    const float* b_O = (const float*)d_in[8];
    float* out = (float*)d_out;

    __half *Qh, *Ql, *wh, *qh, *kh, *vh, *ch, *cl;
    cudaGetSymbolAddress((void**)&Qh, g_Qh);
    cudaGetSymbolAddress((void**)&Ql, g_Ql);
    cudaGetSymbolAddress((void**)&wh, g_wh);
    cudaGetSymbolAddress((void**)&qh, g_qh);
    cudaGetSymbolAddress((void**)&kh, g_kh);
    cudaGetSymbolAddress((void**)&vh, g_vh);
    cudaGetSymbolAddress((void**)&ch, g_ch);
    cudaGetSymbolAddress((void**)&cl, g_cl);

    cudaFuncSetAttribute(gemm_qkv, cudaFuncAttributeMaxDynamicSharedMemorySize, GT_SMEM);
    cudaFuncSetAttribute(gemm_o,   cudaFuncAttributeMaxDynamicSharedMemorySize, GT_SMEM);

    const int nQ = ROWS * D_MODEL;
    splitQ<<<nQ / 4 / 256, 256>>>(Q, Qh, Ql, nQ);
    splitW4<<<dim3(WELEM / 4 / 256, 4), 256>>>(W_Q, W_K, W_V, W_O, wh);

    gemm_qkv<<<dim3(8, 32, 3), 512, GT_SMEM>>>(Qh, Ql, wh, b_Q, b_K, b_V,
                                               qh, kh, vh);

    flash_tc<<<dim3(SEQ / 128, BATCH * NHEADS), 256, F_SMEM>>>(qh, kh, vh, ch, cl);

    gemm_o<<<dim3(8, 32), 512, GT_SMEM>>>(ch, cl, wh + 3 * (size_t)WELEM, b_O, out);
}

// round 8
// speedup vs baseline: 4.4598x; 1.0858x over previous
#include <cuda_runtime.h>
#include <cuda_fp16.h>
#include <math.h>
#include <stdint.h>

#define D_MODEL 1024
#define NHEADS  16
#define DK      64
#define SEQ     2048
#define BATCH   2
#define ROWS    (BATCH*SEQ)   // 4096
#define WELEM   (D_MODEL*D_MODEL)

// fp16 scratch (allocation-free rule: __device__ globals; 16B-aligned)
__device__ __align__(16) __half g_Qh[ROWS*D_MODEL];
__device__ __align__(16) __half g_Ql[ROWS*D_MODEL];
__device__ __align__(16) __half g_wh[4*WELEM];        // Wq,Wk,Wv,Wo hi
__device__ __align__(16) __half g_qh[ROWS*D_MODEL];   // q fp16 [B,H,S,DK] (pre-scaled)
__device__ __align__(16) __half g_kh[ROWS*D_MODEL];
__device__ __align__(16) __half g_vh[ROWS*D_MODEL];
__device__ __align__(16) __half g_ch[ROWS*D_MODEL];   // ctx hi [B,S,D]
__device__ __align__(16) __half g_cl[ROWS*D_MODEL];

// ===========================================================================
// helpers
// ===========================================================================
__device__ __forceinline__ uint32_t smem_u32(const void* p) {
    uint32_t a;
    asm("{ .reg .u64 t; cvta.to.shared.u64 t, %1; cvt.u32.u64 %0, t; }"
        : "=r"(a) : "l"(p));
    return a;
}
__device__ __forceinline__ uint32_t swz128(uint32_t off) {
    return off ^ ((off >> 3) & 0x70);
}
__device__ __forceinline__ void cp16(uint32_t smem_addr, const void* gptr) {
    asm volatile("cp.async.cg.shared.global [%0], [%1], 16;"
                 :: "r"(smem_addr), "l"(gptr));
}
#define CP_COMMIT() asm volatile("cp.async.commit_group;" ::: "memory")
#define CP_WAIT1()  asm volatile("cp.async.wait_group 1;" ::: "memory")
__device__ __forceinline__ void ldsm_x4(uint32_t* r, uint32_t addr) {
    asm volatile("ldmatrix.sync.aligned.m8n8.x4.shared.b16 {%0,%1,%2,%3}, [%4];"
                 : "=r"(r[0]), "=r"(r[1]), "=r"(r[2]), "=r"(r[3]) : "r"(addr));
}
__device__ __forceinline__ void ldsm_x4_t(uint32_t* r, uint32_t addr) {
    asm volatile("ldmatrix.sync.aligned.m8n8.x4.trans.shared.b16 {%0,%1,%2,%3}, [%4];"
                 : "=r"(r[0]), "=r"(r[1]), "=r"(r[2]), "=r"(r[3]) : "r"(addr));
}
__device__ __forceinline__ void mmah(float* c, const uint32_t* a,
                                     uint32_t b0, uint32_t b1) {
    asm volatile("mma.sync.aligned.m16n8k16.row.col.f32.f16.f16.f32 "
                 "{%0,%1,%2,%3}, {%4,%5,%6,%7}, {%8,%9}, {%0,%1,%2,%3};"
                 : "+f"(c[0]), "+f"(c[1]), "+f"(c[2]), "+f"(c[3])
                 : "r"(a[0]), "r"(a[1]), "r"(a[2]), "r"(a[3]), "r"(b0), "r"(b1));
}
// 2^t via FMA-pipe polynomial (avoids MUFU bottleneck). t <= 0.
__device__ __forceinline__ float exp2p(float t) {
    t = fmaxf(t, -126.0f);
    float i = rintf(t);
    float f = t - i;
    float p = fmaf(f, 0.0096181291f, 0.055504109f);
    p = fmaf(f, p, 0.24022651f);
    p = fmaf(f, p, 0.69314718f);
    p = fmaf(f, p, 1.0f);
    return p * __int_as_float(((int)i + 127) << 23);
}
__device__ __forceinline__ void pack2hl(float a, float b, uint32_t& h, uint32_t& l) {
    __half2 H = __floats2half2_rn(a, b);
    float2 F = __half22float2(H);
    __half2 L = __floats2half2_rn(a - F.x, b - F.y);
    h = *reinterpret_cast<uint32_t*>(&H);
    l = *reinterpret_cast<uint32_t*>(&L);
}

// ===========================================================================
// one-time splits
// ===========================================================================
__global__ void splitQ(const float* __restrict__ s, __half* __restrict__ h,
                       __half* __restrict__ l, int n) {
    int i = (blockIdx.x * blockDim.x + threadIdx.x) * 4;
    if (i >= n) return;
    float4 x = *(const float4*)(s + i);
    __half2 h01 = __floats2half2_rn(x.x, x.y);
    __half2 h23 = __floats2half2_rn(x.z, x.w);
    float2 f01 = __half22float2(h01), f23 = __half22float2(h23);
    *(__half2*)(h + i) = h01; *(__half2*)(h + i + 2) = h23;
    *(__half2*)(l + i)     = __floats2half2_rn(x.x - f01.x, x.y - f01.y);
    *(__half2*)(l + i + 2) = __floats2half2_rn(x.z - f23.x, x.w - f23.y);
}
__global__ void splitW4(const float* __restrict__ w0, const float* __restrict__ w1,
                        const float* __restrict__ w2, const float* __restrict__ w3,
                        __half* __restrict__ h) {
    int z = blockIdx.y;
    const float* s = (z == 0) ? w0 : (z == 1) ? w1 : (z == 2) ? w2 : w3;
    int i = (blockIdx.x * blockDim.x + threadIdx.x) * 4;
    float4 x = *(const float4*)(s + i);
    __half* hp = h + (size_t)z * WELEM + i;
    *(__half2*)(hp)     = __floats2half2_rn(x.x, x.y);
    *(__half2*)(hp + 2) = __floats2half2_rn(x.z, x.w);
}

// ===========================================================================
// 2-term fp16 GEMM, cp.async 2-stage: C = (Ah+Al) @ Bh^T + bias, then *oscale
// CTA 128x128, K chunk 64, 512 threads. Stage: AH +0, AL +16K, BH +32K.
// mode 0: fp32 [M,N]; mode 1: fp16 [B,H,S,DK]
// ===========================================================================
#define GST 49152
#define GT_SMEM (2*GST)   // 98304

__device__ __forceinline__ void gemm2_body(
    const __half* __restrict__ Ah, const __half* __restrict__ Al,
    const __half* __restrict__ Bh, const float* __restrict__ bias,
    float* __restrict__ Cf, __half* __restrict__ Oh, int mode, float oscale)
{
    extern __shared__ __align__(1024) char smem[];
    const uint32_t sbase = smem_u32(smem);
    const int tid  = threadIdx.x;
    const int wid  = tid >> 5;
    const int lane = tid & 31;
    const int wm   = wid & 3;
    const int wn   = wid >> 2;

    const int m0 = blockIdx.y * 128;
    const int n0 = blockIdx.x * 128;

    int rowi[2], c8i[2];
    uint32_t soff[2];
    #pragma unroll
    for (int i = 0; i < 2; i++) {
        int g = i * 512 + tid;
        rowi[i] = g >> 3;
        c8i[i]  = g & 7;
        soff[i] = swz128((uint32_t)(rowi[i] * 128 + c8i[i] * 16));
    }

    float acc[2][4][4] = {};

    // prologue: chunk 0 -> stage 0
    #pragma unroll
    for (int i = 0; i < 2; i++) {
        size_t ao = (size_t)(m0 + rowi[i]) * D_MODEL + c8i[i] * 8;
        size_t bo = (size_t)(n0 + rowi[i]) * D_MODEL + c8i[i] * 8;
        cp16(sbase + soff[i],          Ah + ao);
        cp16(sbase + 16384 + soff[i],  Al + ao);
        cp16(sbase + 32768 + soff[i],  Bh + bo);
    }
    CP_COMMIT();

    for (int kc = 0; kc < 16; kc++) {
        if (kc + 1 < 16) {
            uint32_t st = sbase + ((kc + 1) & 1) * GST;
            #pragma unroll
            for (int i = 0; i < 2; i++) {
                size_t ao = (size_t)(m0 + rowi[i]) * D_MODEL + (kc + 1) * 64 + c8i[i] * 8;
                size_t bo = (size_t)(n0 + rowi[i]) * D_MODEL + (kc + 1) * 64 + c8i[i] * 8;
                cp16(st + soff[i],         Ah + ao);
                cp16(st + 16384 + soff[i], Al + ao);
                cp16(st + 32768 + soff[i], Bh + bo);
            }
        }
        CP_COMMIT();
        CP_WAIT1();
        __syncthreads();

        const uint32_t sbs = sbase + (kc & 1) * GST;
        #pragma unroll
        for (int ks = 0; ks < 4; ks++) {
            uint32_t ah[2][4], al[2][4];
            #pragma unroll
            for (int mi = 0; mi < 2; mi++) {
                int mrow = wm * 32 + mi * 16 + (lane & 15);
                uint32_t off = swz128((uint32_t)(mrow * 128 + ks * 32 + (lane >> 4) * 16));
                ldsm_x4(ah[mi], sbs + off);
                ldsm_x4(al[mi], sbs + 16384 + off);
            }
            uint32_t bh[2][4];
            #pragma unroll
            for (int nj = 0; nj < 2; nj++) {
                int nrow = wn * 32 + nj * 16 + (lane & 15);
                uint32_t off = swz128((uint32_t)(nrow * 128 + ks * 32 + (lane >> 4) * 16));
                ldsm_x4(bh[nj], sbs + 32768 + off);
            }
            #pragma unroll
            for (int mi = 0; mi < 2; mi++)
                #pragma unroll
                for (int nj = 0; nj < 2; nj++) {
                    mmah(acc[mi][nj*2+0], ah[mi], bh[nj][0], bh[nj][2]);
                    mmah(acc[mi][nj*2+1], ah[mi], bh[nj][1], bh[nj][3]);
                    mmah(acc[mi][nj*2+0], al[mi], bh[nj][0], bh[nj][2]);
                    mmah(acc[mi][nj*2+1], al[mi], bh[nj][1], bh[nj][3]);
                }
        }
        __syncthreads();   // all reads of this stage done before it is refilled
    }

    #pragma unroll
    for (int mi = 0; mi < 2; mi++) {
        #pragma unroll
        for (int nj = 0; nj < 4; nj++) {
            int gj = n0 + wn * 32 + nj * 8 + (lane & 3) * 2;
            float bi0 = __ldg(bias + gj), bi1 = __ldg(bias + gj + 1);
            #pragma unroll
            for (int half = 0; half < 2; half++) {
                int gi = m0 + wm * 32 + mi * 16 + (lane >> 2) + half * 8;
                float v0 = (acc[mi][nj][half*2+0] + bi0) * oscale;
                float v1 = (acc[mi][nj][half*2+1] + bi1) * oscale;
                if (mode == 0) {
                    *(float2*)&Cf[(size_t)gi * D_MODEL + gj] = make_float2(v0, v1);
                } else {
                    int b = gi >> 11, s = gi & (SEQ - 1);
                    int h = gj >> 6,  d = gj & (DK - 1);
                    size_t idx = (((size_t)(b * NHEADS + h) * SEQ) + s) * DK + d;
                    __half2 H = __floats2half2_rn(v0, v1);
                    *(__half2*)&Oh[idx] = H;
                }
            }
        }
    }
}

#define QSCALE 0.18033688011f   // 0.125 * log2(e), folded into q

// fused Q/K/V projection: grid (8, 32, 3), z selects weight/bias/output
__global__ __launch_bounds__(512, 1)
void gemm_qkv(const __half* __restrict__ Ah, const __half* __restrict__ Al,
              const __half* __restrict__ wh,
              const float* __restrict__ bQ, const float* __restrict__ bK,
              const float* __restrict__ bV,
              __half* __restrict__ qh, __half* __restrict__ kh,
              __half* __restrict__ vh)
{
    int z = blockIdx.z;
    const __half* Bh = wh + (size_t)z * WELEM;
    if (z == 0)      gemm2_body(Ah, Al, Bh, bQ, nullptr, qh, 1, QSCALE);
    else if (z == 1) gemm2_body(Ah, Al, Bh, bK, nullptr, kh, 1, 1.0f);
    else             gemm2_body(Ah, Al, Bh, bV, nullptr, vh, 1, 1.0f);
}

__global__ __launch_bounds__(512, 1)
void gemm_o(const __half* __restrict__ ch, const __half* __restrict__ cl,
            const __half* __restrict__ woh, const float* __restrict__ bO,
            float* __restrict__ out)
{
    gemm2_body(ch, cl, woh, bO, out, nullptr, 0, 1.0f);
}

// ===========================================================================
// Causal flash attention, fp16 tensor-core, cp.async 2-stage K/V pipeline.
// CTA: 128 q-rows x 64-key tiles, 8 warps, 2 CTAs/SM.
// q pre-scaled by 0.125*log2(e): softmax is exp2(s - m) directly.
// QK 1-term; PV 2-term (PhVh + PlVh).
// ===========================================================================
#define F_STAGE(s) (16384 + (s) * 16384)     // K +0 (8K), V +8192 (8K)
#define F_SMEM 49152

__global__ __launch_bounds__(256, 2)
void flash_tc(const __half* __restrict__ qh, const __half* __restrict__ kh,
              const __half* __restrict__ vh,
              __half* __restrict__ ch, __half* __restrict__ cl)
{
    extern __shared__ __align__(1024) char smem[];
    const uint32_t sb = smem_u32(smem);
    const int tid  = threadIdx.x;
    const int wid  = tid >> 5;
    const int lane = tid & 31;
    const int qt   = (gridDim.x - 1) - blockIdx.x;
    const int bh   = blockIdx.y;
    const size_t base = (size_t)bh * SEQ * DK;
    const int nkt = 2 * qt + 2;

    // loader geometry (shared by K and V)
    int lr[2], lc8[2];
    uint32_t lso[2];
    #pragma unroll
    for (int i = 0; i < 2; i++) {
        int c = i * 256 + tid;          // 0..511
        lr[i]  = c >> 3;
        lc8[i] = c & 7;
        lso[i] = swz128((uint32_t)(lr[i] * 128 + lc8[i] * 16));
    }

    // issue chunk 0 into stage 0 (overlaps Q load below)
    #pragma unroll
    for (int i = 0; i < 2; i++) {
        size_t go = base + (size_t)(lr[i]) * DK + lc8[i] * 8;
        cp16(sb + F_STAGE(0) + lso[i],        kh + go);
        cp16(sb + F_STAGE(0) + 8192 + lso[i], vh + go);
    }
    CP_COMMIT();

    // load Q tile -> smem (swizzled)
    #pragma unroll
    for (int i = 0; i < 4; i++) {
        int c = i * 256 + tid;
        int r = c >> 3, c8 = c & 7;
        uint4 d = *(const uint4*)(qh + base + (size_t)(qt * 128 + r) * DK + c8 * 8);
        asm volatile("st.shared.v4.b32 [%0], {%1,%2,%3,%4};" ::
            "r"(sb + swz128((uint32_t)(r * 128 + c8 * 16))),
            "r"(d.x), "r"(d.y), "r"(d.z), "r"(d.w));
    }
    __syncthreads();

    uint32_t qf[4][4];
    #pragma unroll
    for (int ks = 0; ks < 4; ks++) {
        uint32_t off = swz128((uint32_t)((16 * wid + (lane & 15)) * 128 + ks * 32 + (lane >> 4) * 16));
        ldsm_x4(qf[ks], sb + off);
    }

    float oacc[8][4] = {};
    float m0 = -INFINITY, m1 = -INFINITY, l0 = 0.f, l1 = 0.f;
    const int r0g = qt * 128 + 16 * wid + (lane >> 2);

    for (int kt = 0; kt < nkt; kt++) {
        // issue next chunk into the other stage
        if (kt + 1 < nkt) {
            uint32_t st = sb + F_STAGE((kt + 1) & 1);
            #pragma unroll
            for (int i = 0; i < 2; i++) {
                size_t go = base + (size_t)((kt + 1) * 64 + lr[i]) * DK + lc8[i] * 8;
                cp16(st + lso[i],        kh + go);
                cp16(st + 8192 + lso[i], vh + go);
            }
        }
        CP_COMMIT();
        CP_WAIT1();
        __syncthreads();

        const uint32_t fsk  = sb + F_STAGE(kt & 1);
        const uint32_t fsvh = fsk + 8192;

        // S = Q @ K^T (scores already in log2 domain via q pre-scale)
        float sacc[8][4] = {};
        #pragma unroll
        for (int g = 0; g < 4; g++) {
            #pragma unroll
            for (int ks = 0; ks < 4; ks++) {
                uint32_t bf[4];
                uint32_t off = swz128((uint32_t)((16 * g + (lane & 15)) * 128 + ks * 32 + (lane >> 4) * 16));
                ldsm_x4(bf, fsk + off);
                mmah(sacc[2*g+0], qf[ks], bf[0], bf[2]);
                mmah(sacc[2*g+1], qf[ks], bf[1], bf[3]);
            }
        }

        if (kt * 64 + 63 > qt * 128 + 16 * wid) {
            #pragma unroll
            for (int t = 0; t < 8; t++) {
                int col = kt * 64 + 8 * t + 2 * (lane & 3);
                if (col     > r0g)     sacc[t][0] = -1e9f;
                if (col + 1 > r0g)     sacc[t][1] = -1e9f;
                if (col     > r0g + 8) sacc[t][2] = -1e9f;
                if (col + 1 > r0g + 8) sacc[t][3] = -1e9f;
            }
        }

        float mh0 = -INFINITY, mh1 = -INFINITY;
        #pragma unroll
        for (int t = 0; t < 8; t++) {
            mh0 = fmaxf(mh0, fmaxf(sacc[t][0], sacc[t][1]));
            mh1 = fmaxf(mh1, fmaxf(sacc[t][2], sacc[t][3]));
        }
        mh0 = fmaxf(mh0, __shfl_xor_sync(0xffffffffu, mh0, 1));
        mh0 = fmaxf(mh0, __shfl_xor_sync(0xffffffffu, mh0, 2));
        mh1 = fmaxf(mh1, __shfl_xor_sync(0xffffffffu, mh1, 1));
        mh1 = fmaxf(mh1, __shfl_xor_sync(0xffffffffu, mh1, 2));
        float mn0 = fmaxf(m0, mh0), mn1 = fmaxf(m1, mh1);
        float c0 = exp2p(m0 - mn0);
        float c1 = exp2p(m1 - mn1);
        m0 = mn0; m1 = mn1;

        float ps0 = 0.f, ps1 = 0.f;
        #pragma unroll
        for (int t = 0; t < 8; t++) {
            float p0 = exp2p(sacc[t][0] - mn0);
            float p1 = exp2p(sacc[t][1] - mn0);
            float p2 = exp2p(sacc[t][2] - mn1);
            float p3 = exp2p(sacc[t][3] - mn1);
            sacc[t][0] = p0; sacc[t][1] = p1; sacc[t][2] = p2; sacc[t][3] = p3;
            ps0 += p0 + p1; ps1 += p2 + p3;
        }
        l0 = l0 * c0 + ps0;
        l1 = l1 * c1 + ps1;
        #pragma unroll
        for (int t = 0; t < 8; t++) {
            oacc[t][0] *= c0; oacc[t][1] *= c0;
            oacc[t][2] *= c1; oacc[t][3] *= c1;
        }

        // O += P @ V  (2-term: PhVh + PlVh)
        #pragma unroll
        for (int kk = 0; kk < 4; kk++) {
            uint32_t PH[4], PL[4];
            pack2hl(sacc[2*kk  ][0], sacc[2*kk  ][1], PH[0], PL[0]);
            pack2hl(sacc[2*kk  ][2], sacc[2*kk  ][3], PH[1], PL[1]);
            pack2hl(sacc[2*kk+1][0], sacc[2*kk+1][1], PH[2], PL[2]);
            pack2hl(sacc[2*kk+1][2], sacc[2*kk+1][3], PH[3], PL[3]);
            int keyrow = kk * 16 + (lane & 7) + 8 * ((lane >> 3) & 1);
            #pragma unroll
            for (int g2 = 0; g2 < 4; g2++) {
                uint32_t bvh[4];
                int dkc = 16 * g2 + 8 * (lane >> 4);
                uint32_t off = swz128((uint32_t)(keyrow * 128 + dkc * 2));
                ldsm_x4_t(bvh, fsvh + off);
                mmah(oacc[2*g2+0], PH, bvh[0], bvh[1]);
                mmah(oacc[2*g2+1], PH, bvh[2], bvh[3]);
                mmah(oacc[2*g2+0], PL, bvh[0], bvh[1]);
                mmah(oacc[2*g2+1], PL, bvh[2], bvh[3]);
            }
        }
        __syncthreads();   // all reads of this stage done before it is refilled
    }

    l0 += __shfl_xor_sync(0xffffffffu, l0, 1);
    l0 += __shfl_xor_sync(0xffffffffu, l0, 2);
    l1 += __shfl_xor_sync(0xffffffffu, l1, 1);
    l1 += __shfl_xor_sync(0xffffffffu, l1, 2);
    float inv0 = 1.f / l0, inv1 = 1.f / l1;

    int b = bh >> 4, hh = bh & 15;
    int s0 = qt * 128 + 16 * wid + (lane >> 2);
    int s1 = s0 + 8;
    #pragma unroll
    for (int t = 0; t < 8; t++) {
        int n = 8 * t + 2 * (lane & 3);
        float v0 = oacc[t][0] * inv0, v1 = oacc[t][1] * inv0;
        float v2 = oacc[t][2] * inv1, v3 = oacc[t][3] * inv1;
        size_t i0 = ((size_t)b * SEQ + s0) * D_MODEL + hh * DK + n;
        size_t i1 = ((size_t)b * SEQ + s1) * D_MODEL + hh * DK + n;
        uint32_t H, L;
        pack2hl(v0, v1, H, L);
        *(uint32_t*)&ch[i0] = H; *(uint32_t*)&cl[i0] = L;
        pack2hl(v2, v3, H, L);
        *(uint32_t*)&ch[i1] = H; *(uint32_t*)&cl[i1] = L;
    }
}

// ---------------------------------------------------------------------------
extern "C" void kernel_launch(void* const* d_in, const int* in_sizes, int n_in,
                              void* d_out, int out_size)
{
    const float* Q   = (const float*)d_in[0];
    const float* W_Q = (const float*)d_in[1];
    const float* b_Q = (const float*)d_in[2];
    const float* W_K = (const float*)d_in[3];
    const float* b_K = (const float*)d_in[4];
    const float* W_V = (const float*)d_in[5];
    const float* b_V = (const float*)d_in[6];
    const float* W_O = (const float*)d_in[7];
    const float* b_O = (const float*)d_in[8];
    float* out = (float*)d_out;

    __half *Qh, *Ql, *wh, *qh, *kh, *vh, *ch, *cl;
    cudaGetSymbolAddress((void**)&Qh, g_Qh);
    cudaGetSymbolAddress((void**)&Ql, g_Ql);
    cudaGetSymbolAddress((void**)&wh, g_wh);
    cudaGetSymbolAddress((void**)&qh, g_qh);
    cudaGetSymbolAddress((void**)&kh, g_kh);
    cudaGetSymbolAddress((void**)&vh, g_vh);
    cudaGetSymbolAddress((void**)&ch, g_ch);
    cudaGetSymbolAddress((void**)&cl, g_cl);

    cudaFuncSetAttribute(gemm_qkv, cudaFuncAttributeMaxDynamicSharedMemorySize, GT_SMEM);
    cudaFuncSetAttribute(gemm_o,   cudaFuncAttributeMaxDynamicSharedMemorySize, GT_SMEM);
    cudaFuncSetAttribute(flash_tc, cudaFuncAttributeMaxDynamicSharedMemorySize, F_SMEM);

    const int nQ = ROWS * D_MODEL;
    splitQ<<<nQ / 4 / 256, 256>>>(Q, Qh, Ql, nQ);
    splitW4<<<dim3(WELEM / 4 / 256, 4), 256>>>(W_Q, W_K, W_V, W_O, wh);

    gemm_qkv<<<dim3(8, 32, 3), 512, GT_SMEM>>>(Qh, Ql, wh, b_Q, b_K, b_V,
                                               qh, kh, vh);

    flash_tc<<<dim3(SEQ / 128, BATCH * NHEADS), 256, F_SMEM>>>(qh, kh, vh, ch, cl);

    gemm_o<<<dim3(8, 32), 512, GT_SMEM>>>(ch, cl, wh + 3 * (size_t)WELEM, b_O, out);
}

// round 9
// speedup vs baseline: 4.8039x; 1.0772x over previous
#include <cuda_runtime.h>
#include <cuda_fp16.h>
#include <math.h>
#include <stdint.h>

#define D_MODEL 1024
#define NHEADS  16
#define DK      64
#define SEQ     2048
#define BATCH   2
#define ROWS    (BATCH*SEQ)   // 4096
#define WELEM   (D_MODEL*D_MODEL)

// fp16 scratch (allocation-free rule: __device__ globals; 16B-aligned)
__device__ __align__(16) __half g_Qh[ROWS*D_MODEL];
__device__ __align__(16) __half g_Ql[ROWS*D_MODEL];
__device__ __align__(16) __half g_wh[4*WELEM];        // Wq,Wk,Wv,Wo hi
__device__ __align__(16) __half g_qh[ROWS*D_MODEL];   // q fp16 [B,H,S,DK] (pre-scaled)
__device__ __align__(16) __half g_kh[ROWS*D_MODEL];
__device__ __align__(16) __half g_vh[ROWS*D_MODEL];
__device__ __align__(16) __half g_ch[ROWS*D_MODEL];   // ctx hi [B,S,D]
__device__ __align__(16) __half g_cl[ROWS*D_MODEL];

// ===========================================================================
// helpers
// ===========================================================================
__device__ __forceinline__ uint32_t smem_u32(const void* p) {
    uint32_t a;
    asm("{ .reg .u64 t; cvta.to.shared.u64 t, %1; cvt.u32.u64 %0, t; }"
        : "=r"(a) : "l"(p));
    return a;
}
__device__ __forceinline__ uint32_t swz128(uint32_t off) {
    return off ^ ((off >> 3) & 0x70);
}
__device__ __forceinline__ void cp16(uint32_t smem_addr, const void* gptr) {
    asm volatile("cp.async.cg.shared.global [%0], [%1], 16;"
                 :: "r"(smem_addr), "l"(gptr));
}
#define CP_COMMIT() asm volatile("cp.async.commit_group;" ::: "memory")
#define CP_WAIT1()  asm volatile("cp.async.wait_group 1;" ::: "memory")
__device__ __forceinline__ void ldsm_x4(uint32_t* r, uint32_t addr) {
    asm volatile("ldmatrix.sync.aligned.m8n8.x4.shared.b16 {%0,%1,%2,%3}, [%4];"
                 : "=r"(r[0]), "=r"(r[1]), "=r"(r[2]), "=r"(r[3]) : "r"(addr));
}
__device__ __forceinline__ void ldsm_x4_t(uint32_t* r, uint32_t addr) {
    asm volatile("ldmatrix.sync.aligned.m8n8.x4.trans.shared.b16 {%0,%1,%2,%3}, [%4];"
                 : "=r"(r[0]), "=r"(r[1]), "=r"(r[2]), "=r"(r[3]) : "r"(addr));
}
__device__ __forceinline__ void mmah(float* c, const uint32_t* a,
                                     uint32_t b0, uint32_t b1) {
    asm volatile("mma.sync.aligned.m16n8k16.row.col.f32.f16.f16.f32 "
                 "{%0,%1,%2,%3}, {%4,%5,%6,%7}, {%8,%9}, {%0,%1,%2,%3};"
                 : "+f"(c[0]), "+f"(c[1]), "+f"(c[2]), "+f"(c[3])
                 : "r"(a[0]), "r"(a[1]), "r"(a[2]), "r"(a[3]), "r"(b0), "r"(b1));
}
// 2^t via FMA-pipe deg-3 minimax poly (rel err ~7e-5, under p's fp16 quant). t <= 0.
__device__ __forceinline__ float exp2p(float t) {
    t = fmaxf(t, -126.0f);
    float i = rintf(t);
    float f = t - i;
    float p = fmaf(f, 0.0558263f, 0.2401597f);
    p = fmaf(f, p, 0.6931475f);
    p = fmaf(f, p, 1.0f);
    return p * __int_as_float(((int)i + 127) << 23);
}
__device__ __forceinline__ void pack2hl(float a, float b, uint32_t& h, uint32_t& l) {
    __half2 H = __floats2half2_rn(a, b);
    float2 F = __half22float2(H);
    __half2 L = __floats2half2_rn(a - F.x, b - F.y);
    h = *reinterpret_cast<uint32_t*>(&H);
    l = *reinterpret_cast<uint32_t*>(&L);
}

// ===========================================================================
// one-time splits (4x ILP for bandwidth)
// ===========================================================================
__global__ void splitQ(const float* __restrict__ s, __half* __restrict__ h,
                       __half* __restrict__ l) {
    #pragma unroll
    for (int j = 0; j < 4; j++) {
        int i = (blockIdx.x * 1024 + j * 256 + threadIdx.x) * 4;
        float4 x = *(const float4*)(s + i);
        __half2 h01 = __floats2half2_rn(x.x, x.y);
        __half2 h23 = __floats2half2_rn(x.z, x.w);
        float2 f01 = __half22float2(h01), f23 = __half22float2(h23);
        *(__half2*)(h + i) = h01; *(__half2*)(h + i + 2) = h23;
        *(__half2*)(l + i)     = __floats2half2_rn(x.x - f01.x, x.y - f01.y);
        *(__half2*)(l + i + 2) = __floats2half2_rn(x.z - f23.x, x.w - f23.y);
    }
}
__global__ void splitW4(const float* __restrict__ w0, const float* __restrict__ w1,
                        const float* __restrict__ w2, const float* __restrict__ w3,
                        __half* __restrict__ h) {
    int z = blockIdx.y;
    const float* s = (z == 0) ? w0 : (z == 1) ? w1 : (z == 2) ? w2 : w3;
    __half* hz = h + (size_t)z * WELEM;
    #pragma unroll
    for (int j = 0; j < 4; j++) {
        int i = (blockIdx.x * 1024 + j * 256 + threadIdx.x) * 4;
        float4 x = *(const float4*)(s + i);
        *(__half2*)(hz + i)     = __floats2half2_rn(x.x, x.y);
        *(__half2*)(hz + i + 2) = __floats2half2_rn(x.z, x.w);
    }
}

// ===========================================================================
// 2-term fp16 GEMM, cp.async 2-stage, 256 threads, warp tile 32x64, 2 CTA/SM.
// C = (Ah+Al) @ Bh^T + bias, then *oscale.
// Stage layout: AH +0 (16K), AL +16K, BH +32K. 2 stages = 96K smem.
// mode 0: fp32 [M,N]; mode 1: fp16 [B,H,S,DK]
// ===========================================================================
#define GST 49152
#define GT_SMEM (2*GST)   // 98304

__device__ __forceinline__ void gemm2_body(
    const __half* __restrict__ Ah, const __half* __restrict__ Al,
    const __half* __restrict__ Bh, const float* __restrict__ bias,
    float* __restrict__ Cf, __half* __restrict__ Oh, int mode, float oscale)
{
    extern __shared__ __align__(1024) char smem[];
    const uint32_t sbase = smem_u32(smem);
    const int tid  = threadIdx.x;
    const int wid  = tid >> 5;
    const int lane = tid & 31;
    const int wm   = wid & 3;        // 0..3 (M)
    const int wn   = wid >> 2;       // 0..1 (N)

    const int m0 = blockIdx.y * 128;
    const int n0 = blockIdx.x * 128;

    // loader geometry: 4 x 16B-chunk per thread per array
    int rowi[4], c8i[4];
    uint32_t soff[4];
    #pragma unroll
    for (int i = 0; i < 4; i++) {
        int g = i * 256 + tid;       // 0..1023
        rowi[i] = g >> 3;            // 0..127
        c8i[i]  = g & 7;
        soff[i] = swz128((uint32_t)(rowi[i] * 128 + c8i[i] * 16));
    }

    float acc[2][8][4] = {};

    // prologue: chunk 0 -> stage 0
    #pragma unroll
    for (int i = 0; i < 4; i++) {
        size_t ao = (size_t)(m0 + rowi[i]) * D_MODEL + c8i[i] * 8;
        size_t bo = (size_t)(n0 + rowi[i]) * D_MODEL + c8i[i] * 8;
        cp16(sbase + soff[i],          Ah + ao);
        cp16(sbase + 16384 + soff[i],  Al + ao);
        cp16(sbase + 32768 + soff[i],  Bh + bo);
    }
    CP_COMMIT();

    for (int kc = 0; kc < 16; kc++) {
        if (kc + 1 < 16) {
            uint32_t st = sbase + ((kc + 1) & 1) * GST;
            #pragma unroll
            for (int i = 0; i < 4; i++) {
                size_t ao = (size_t)(m0 + rowi[i]) * D_MODEL + (kc + 1) * 64 + c8i[i] * 8;
                size_t bo = (size_t)(n0 + rowi[i]) * D_MODEL + (kc + 1) * 64 + c8i[i] * 8;
                cp16(st + soff[i],         Ah + ao);
                cp16(st + 16384 + soff[i], Al + ao);
                cp16(st + 32768 + soff[i], Bh + bo);
            }
        }
        CP_COMMIT();
        CP_WAIT1();
        __syncthreads();

        const uint32_t sbs = sbase + (kc & 1) * GST;
        #pragma unroll
        for (int ks = 0; ks < 4; ks++) {
            uint32_t ah[2][4], al[2][4];
            #pragma unroll
            for (int mi = 0; mi < 2; mi++) {
                int mrow = wm * 32 + mi * 16 + (lane & 15);
                uint32_t off = swz128((uint32_t)(mrow * 128 + ks * 32 + (lane >> 4) * 16));
                ldsm_x4(ah[mi], sbs + off);
                ldsm_x4(al[mi], sbs + 16384 + off);
            }
            #pragma unroll
            for (int nj16 = 0; nj16 < 4; nj16++) {
                uint32_t bf[4];
                int nrow = wn * 64 + nj16 * 16 + (lane & 15);
                uint32_t off = swz128((uint32_t)(nrow * 128 + ks * 32 + (lane >> 4) * 16));
                ldsm_x4(bf, sbs + 32768 + off);
                #pragma unroll
                for (int mi = 0; mi < 2; mi++) {
                    mmah(acc[mi][nj16*2+0], ah[mi], bf[0], bf[2]);
                    mmah(acc[mi][nj16*2+1], ah[mi], bf[1], bf[3]);
                    mmah(acc[mi][nj16*2+0], al[mi], bf[0], bf[2]);
                    mmah(acc[mi][nj16*2+1], al[mi], bf[1], bf[3]);
                }
            }
        }
        __syncthreads();   // all reads of this stage done before it is refilled
    }

    #pragma unroll
    for (int mi = 0; mi < 2; mi++) {
        #pragma unroll
        for (int nj = 0; nj < 8; nj++) {
            int gj = n0 + wn * 64 + nj * 8 + (lane & 3) * 2;
            float bi0 = __ldg(bias + gj), bi1 = __ldg(bias + gj + 1);
            #pragma unroll
            for (int half = 0; half < 2; half++) {
                int gi = m0 + wm * 32 + mi * 16 + (lane >> 2) + half * 8;
                float v0 = (acc[mi][nj][half*2+0] + bi0) * oscale;
                float v1 = (acc[mi][nj][half*2+1] + bi1) * oscale;
                if (mode == 0) {
                    *(float2*)&Cf[(size_t)gi * D_MODEL + gj] = make_float2(v0, v1);
                } else {
                    int b = gi >> 11, s = gi & (SEQ - 1);
                    int h = gj >> 6,  d = gj & (DK - 1);
                    size_t idx = (((size_t)(b * NHEADS + h) * SEQ) + s) * DK + d;
                    __half2 H = __floats2half2_rn(v0, v1);
                    *(__half2*)&Oh[idx] = H;
                }
            }
        }
    }
}

#define QSCALE 0.18033688011f   // 0.125 * log2(e), folded into q

// fused Q/K/V projection: grid (8, 32, 3), z selects weight/bias/output
__global__ __launch_bounds__(256, 2)
void gemm_qkv(const __half* __restrict__ Ah, const __half* __restrict__ Al,
              const __half* __restrict__ wh,
              const float* __restrict__ bQ, const float* __restrict__ bK,
              const float* __restrict__ bV,
              __half* __restrict__ qh, __half* __restrict__ kh,
              __half* __restrict__ vh)
{
    int z = blockIdx.z;
    const __half* Bh = wh + (size_t)z * WELEM;
    if (z == 0)      gemm2_body(Ah, Al, Bh, bQ, nullptr, qh, 1, QSCALE);
    else if (z == 1) gemm2_body(Ah, Al, Bh, bK, nullptr, kh, 1, 1.0f);
    else             gemm2_body(Ah, Al, Bh, bV, nullptr, vh, 1, 1.0f);
}

__global__ __launch_bounds__(256, 2)
void gemm_o(const __half* __restrict__ ch, const __half* __restrict__ cl,
            const __half* __restrict__ woh, const float* __restrict__ bO,
            float* __restrict__ out)
{
    gemm2_body(ch, cl, woh, bO, out, nullptr, 0, 1.0f);
}

// ===========================================================================
// Causal flash attention, fp16 tensor-core, cp.async 2-stage K/V pipeline.
// CTA: 128 q-rows x 64-key tiles, 8 warps, 2 CTAs/SM.
// q pre-scaled by 0.125*log2(e): softmax is exp2(s - m) directly.
// QK 1-term; PV 2-term (PhVh + PlVh).
// ===========================================================================
#define F_STAGE(s) (16384 + (s) * 16384)     // K +0 (8K), V +8192 (8K)
#define F_SMEM 49152

__global__ __launch_bounds__(256, 2)
void flash_tc(const __half* __restrict__ qh, const __half* __restrict__ kh,
              const __half* __restrict__ vh,
              __half* __restrict__ ch, __half* __restrict__ cl)
{
    extern __shared__ __align__(1024) char smem[];
    const uint32_t sb = smem_u32(smem);
    const int tid  = threadIdx.x;
    const int wid  = tid >> 5;
    const int lane = tid & 31;
    const int qt   = (gridDim.x - 1) - blockIdx.x;
    const int bh   = blockIdx.y;
    const size_t base = (size_t)bh * SEQ * DK;
    const int nkt = 2 * qt + 2;

    // loader geometry (shared by K and V)
    int lr[2], lc8[2];
    uint32_t lso[2];
    #pragma unroll
    for (int i = 0; i < 2; i++) {
        int c = i * 256 + tid;          // 0..511
        lr[i]  = c >> 3;
        lc8[i] = c & 7;
        lso[i] = swz128((uint32_t)(lr[i] * 128 + lc8[i] * 16));
    }

    // issue chunk 0 into stage 0 (overlaps Q load below)
    #pragma unroll
    for (int i = 0; i < 2; i++) {
        size_t go = base + (size_t)(lr[i]) * DK + lc8[i] * 8;
        cp16(sb + F_STAGE(0) + lso[i],        kh + go);
        cp16(sb + F_STAGE(0) + 8192 + lso[i], vh + go);
    }
    CP_COMMIT();

    // load Q tile -> smem (swizzled)
    #pragma unroll
    for (int i = 0; i < 4; i++) {
        int c = i * 256 + tid;
        int r = c >> 3, c8 = c & 7;
        uint4 d = *(const uint4*)(qh + base + (size_t)(qt * 128 + r) * DK + c8 * 8);
        asm volatile("st.shared.v4.b32 [%0], {%1,%2,%3,%4};" ::
            "r"(sb + swz128((uint32_t)(r * 128 + c8 * 16))),
            "r"(d.x), "r"(d.y), "r"(d.z), "r"(d.w));
    }
    __syncthreads();

    uint32_t qf[4][4];
    #pragma unroll
    for (int ks = 0; ks < 4; ks++) {
        uint32_t off = swz128((uint32_t)((16 * wid + (lane & 15)) * 128 + ks * 32 + (lane >> 4) * 16));
        ldsm_x4(qf[ks], sb + off);
    }

    float oacc[8][4] = {};
    float m0 = -INFINITY, m1 = -INFINITY, l0 = 0.f, l1 = 0.f;
    const int r0g = qt * 128 + 16 * wid + (lane >> 2);

    for (int kt = 0; kt < nkt; kt++) {
        // issue next chunk into the other stage
        if (kt + 1 < nkt) {
            uint32_t st = sb + F_STAGE((kt + 1) & 1);
            #pragma unroll
            for (int i = 0; i < 2; i++) {
                size_t go = base + (size_t)((kt + 1) * 64 + lr[i]) * DK + lc8[i] * 8;
                cp16(st + lso[i],        kh + go);
                cp16(st + 8192 + lso[i], vh + go);
            }
        }
        CP_COMMIT();
        CP_WAIT1();
        __syncthreads();

        const uint32_t fsk  = sb + F_STAGE(kt & 1);
        const uint32_t fsvh = fsk + 8192;

        // S = Q @ K^T (scores already in log2 domain via q pre-scale)
        float sacc[8][4] = {};
        #pragma unroll
        for (int g = 0; g < 4; g++) {
            #pragma unroll
            for (int ks = 0; ks < 4; ks++) {
                uint32_t bf[4];
                uint32_t off = swz128((uint32_t)((16 * g + (lane & 15)) * 128 + ks * 32 + (lane >> 4) * 16));
                ldsm_x4(bf, fsk + off);
                mmah(sacc[2*g+0], qf[ks], bf[0], bf[2]);
                mmah(sacc[2*g+1], qf[ks], bf[1], bf[3]);
            }
        }

        if (kt * 64 + 63 > qt * 128 + 16 * wid) {
            #pragma unroll
            for (int t = 0; t < 8; t++) {
                int col = kt * 64 + 8 * t + 2 * (lane & 3);
                if (col     > r0g)     sacc[t][0] = -1e9f;
                if (col + 1 > r0g)     sacc[t][1] = -1e9f;
                if (col     > r0g + 8) sacc[t][2] = -1e9f;
                if (col + 1 > r0g + 8) sacc[t][3] = -1e9f;
            }
        }

        float mh0 = -INFINITY, mh1 = -INFINITY;
        #pragma unroll
        for (int t = 0; t < 8; t++) {
            mh0 = fmaxf(mh0, fmaxf(sacc[t][0], sacc[t][1]));
            mh1 = fmaxf(mh1, fmaxf(sacc[t][2], sacc[t][3]));
        }
        mh0 = fmaxf(mh0, __shfl_xor_sync(0xffffffffu, mh0, 1));
        mh0 = fmaxf(mh0, __shfl_xor_sync(0xffffffffu, mh0, 2));
        mh1 = fmaxf(mh1, __shfl_xor_sync(0xffffffffu, mh1, 1));
        mh1 = fmaxf(mh1, __shfl_xor_sync(0xffffffffu, mh1, 2));
        float mn0 = fmaxf(m0, mh0), mn1 = fmaxf(m1, mh1);
        float c0 = exp2p(m0 - mn0);
        float c1 = exp2p(m1 - mn1);
        m0 = mn0; m1 = mn1;

        float ps0 = 0.f, ps1 = 0.f;
        #pragma unroll
        for (int t = 0; t < 8; t++) {
            float p0 = exp2p(sacc[t][0] - mn0);
            float p1 = exp2p(sacc[t][1] - mn0);
            float p2 = exp2p(sacc[t][2] - mn1);
            float p3 = exp2p(sacc[t][3] - mn1);
            sacc[t][0] = p0; sacc[t][1] = p1; sacc[t][2] = p2; sacc[t][3] = p3;
            ps0 += p0 + p1; ps1 += p2 + p3;
        }
        l0 = l0 * c0 + ps0;
        l1 = l1 * c1 + ps1;
        #pragma unroll
        for (int t = 0; t < 8; t++) {
            oacc[t][0] *= c0; oacc[t][1] *= c0;
            oacc[t][2] *= c1; oacc[t][3] *= c1;
        }

        // O += P @ V  (2-term: PhVh + PlVh)
        #pragma unroll
        for (int kk = 0; kk < 4; kk++) {
            uint32_t PH[4], PL[4];
            pack2hl(sacc[2*kk  ][0], sacc[2*kk  ][1], PH[0], PL[0]);
            pack2hl(sacc[2*kk  ][2], sacc[2*kk  ][3], PH[1], PL[1]);
            pack2hl(sacc[2*kk+1][0], sacc[2*kk+1][1], PH[2], PL[2]);
            pack2hl(sacc[2*kk+1][2], sacc[2*kk+1][3], PH[3], PL[3]);
            int keyrow = kk * 16 + (lane & 7) + 8 * ((lane >> 3) & 1);
            #pragma unroll
            for (int g2 = 0; g2 < 4; g2++) {
                uint32_t bvh[4];
                int dkc = 16 * g2 + 8 * (lane >> 4);
                uint32_t off = swz128((uint32_t)(keyrow * 128 + dkc * 2));
                ldsm_x4_t(bvh, fsvh + off);
                mmah(oacc[2*g2+0], PH, bvh[0], bvh[1]);
                mmah(oacc[2*g2+1], PH, bvh[2], bvh[3]);
                mmah(oacc[2*g2+0], PL, bvh[0], bvh[1]);
                mmah(oacc[2*g2+1], PL, bvh[2], bvh[3]);
            }
        }
        __syncthreads();   // all reads of this stage done before it is refilled
    }

    l0 += __shfl_xor_sync(0xffffffffu, l0, 1);
    l0 += __shfl_xor_sync(0xffffffffu, l0, 2);
    l1 += __shfl_xor_sync(0xffffffffu, l1, 1);
    l1 += __shfl_xor_sync(0xffffffffu, l1, 2);
    float inv0 = 1.f / l0, inv1 = 1.f / l1;

    int b = bh >> 4, hh = bh & 15;
    int s0 = qt * 128 + 16 * wid + (lane >> 2);
    int s1 = s0 + 8;
    #pragma unroll
    for (int t = 0; t < 8; t++) {
        int n = 8 * t + 2 * (lane & 3);
        float v0 = oacc[t][0] * inv0, v1 = oacc[t][1] * inv0;
        float v2 = oacc[t][2] * inv1, v3 = oacc[t][3] * inv1;
        size_t i0 = ((size_t)b * SEQ + s0) * D_MODEL + hh * DK + n;
        size_t i1 = ((size_t)b * SEQ + s1) * D_MODEL + hh * DK + n;
        uint32_t H, L;
        pack2hl(v0, v1, H, L);
        *(uint32_t*)&ch[i0] = H; *(uint32_t*)&cl[i0] = L;
        pack2hl(v2, v3, H, L);
        *(uint32_t*)&ch[i1] = H; *(uint32_t*)&cl[i1] = L;
    }
}

// ---------------------------------------------------------------------------
extern "C" void kernel_launch(void* const* d_in, const int* in_sizes, int n_in,
                              void* d_out, int out_size)
{
    const float* Q   = (const float*)d_in[0];
    const float* W_Q = (const float*)d_in[1];
    const float* b_Q = (const float*)d_in[2];
    const float* W_K = (const float*)d_in[3];
    const float* b_K = (const float*)d_in[4];
    const float* W_V = (const float*)d_in[5];
    const float* b_V = (const float*)d_in[6];
    const float* W_O = (const float*)d_in[7];
    const float* b_O = (const float*)d_in[8];
    float* out = (float*)d_out;

    __half *Qh, *Ql, *wh, *qh, *kh, *vh, *ch, *cl;
    cudaGetSymbolAddress((void**)&Qh, g_Qh);
    cudaGetSymbolAddress((void**)&Ql, g_Ql);
    cudaGetSymbolAddress((void**)&wh, g_wh);
    cudaGetSymbolAddress((void**)&qh, g_qh);
    cudaGetSymbolAddress((void**)&kh, g_kh);
    cudaGetSymbolAddress((void**)&vh, g_vh);
    cudaGetSymbolAddress((void**)&ch, g_ch);
    cudaGetSymbolAddress((void**)&cl, g_cl);

    cudaFuncSetAttribute(gemm_qkv, cudaFuncAttributeMaxDynamicSharedMemorySize, GT_SMEM);
    cudaFuncSetAttribute(gemm_o,   cudaFuncAttributeMaxDynamicSharedMemorySize, GT_SMEM);
    cudaFuncSetAttribute(flash_tc, cudaFuncAttributeMaxDynamicSharedMemorySize, F_SMEM);

    const int nQ = ROWS * D_MODEL;
    splitQ<<<nQ / 16 / 256, 256>>>(Q, Qh, Ql);
    splitW4<<<dim3(WELEM / 16 / 256, 4), 256>>>(W_Q, W_K, W_V, W_O, wh);

    gemm_qkv<<<dim3(8, 32, 3), 256, GT_SMEM>>>(Qh, Ql, wh, b_Q, b_K, b_V,
                                               qh, kh, vh);

    flash_tc<<<dim3(SEQ / 128, BATCH * NHEADS), 256, F_SMEM>>>(qh, kh, vh, ch, cl);

    gemm_o<<<dim3(8, 32), 256, GT_SMEM>>>(ch, cl, wh + 3 * (size_t)WELEM, b_O, out);
}

// round 10
// speedup vs baseline: 6.4273x; 1.3379x over previous
#include <cuda_runtime.h>
#include <cuda_fp16.h>
#include <math.h>
#include <stdint.h>

#define D_MODEL 1024
#define NHEADS  16
#define DK      64
#define SEQ     2048
#define BATCH   2
#define ROWS    (BATCH*SEQ)   // 4096
#define WELEM   (D_MODEL*D_MODEL)

// fp16 scratch (allocation-free rule: __device__ globals; 16B-aligned)
__device__ __align__(16) __half g_Qh[ROWS*D_MODEL];
__device__ __align__(16) __half g_wh[4*WELEM];        // Wq,Wk,Wv,Wo hi
__device__ __align__(16) __half g_qh[ROWS*D_MODEL];   // q fp16 [B,H,S,DK] (pre-scaled)
__device__ __align__(16) __half g_kh[ROWS*D_MODEL];
__device__ __align__(16) __half g_vh[ROWS*D_MODEL];
__device__ __align__(16) __half g_ch[ROWS*D_MODEL];   // ctx fp16 [B,S,D]

// ===========================================================================
// helpers
// ===========================================================================
__device__ __forceinline__ uint32_t smem_u32(const void* p) {
    uint32_t a;
    asm("{ .reg .u64 t; cvta.to.shared.u64 t, %1; cvt.u32.u64 %0, t; }"
        : "=r"(a) : "l"(p));
    return a;
}
__device__ __forceinline__ uint32_t swz128(uint32_t off) {
    return off ^ ((off >> 3) & 0x70);
}
__device__ __forceinline__ void cp16(uint32_t smem_addr, const void* gptr) {
    asm volatile("cp.async.cg.shared.global [%0], [%1], 16;"
                 :: "r"(smem_addr), "l"(gptr));
}
#define CP_COMMIT() asm volatile("cp.async.commit_group;" ::: "memory")
#define CP_WAIT1()  asm volatile("cp.async.wait_group 1;" ::: "memory")
__device__ __forceinline__ void ldsm_x4(uint32_t* r, uint32_t addr) {
    asm volatile("ldmatrix.sync.aligned.m8n8.x4.shared.b16 {%0,%1,%2,%3}, [%4];"
                 : "=r"(r[0]), "=r"(r[1]), "=r"(r[2]), "=r"(r[3]) : "r"(addr));
}
__device__ __forceinline__ void ldsm_x4_t(uint32_t* r, uint32_t addr) {
    asm volatile("ldmatrix.sync.aligned.m8n8.x4.trans.shared.b16 {%0,%1,%2,%3}, [%4];"
                 : "=r"(r[0]), "=r"(r[1]), "=r"(r[2]), "=r"(r[3]) : "r"(addr));
}
__device__ __forceinline__ void mmah(float* c, const uint32_t* a,
                                     uint32_t b0, uint32_t b1) {
    asm volatile("mma.sync.aligned.m16n8k16.row.col.f32.f16.f16.f32 "
                 "{%0,%1,%2,%3}, {%4,%5,%6,%7}, {%8,%9}, {%0,%1,%2,%3};"
                 : "+f"(c[0]), "+f"(c[1]), "+f"(c[2]), "+f"(c[3])
                 : "r"(a[0]), "r"(a[1]), "r"(a[2]), "r"(a[3]), "r"(b0), "r"(b1));
}
// 2^t via FMA-pipe deg-3 minimax poly (rel err ~7e-5, under p's fp16 quant). t <= 0.
__device__ __forceinline__ float exp2p(float t) {
    t = fmaxf(t, -126.0f);
    float i = rintf(t);
    float f = t - i;
    float p = fmaf(f, 0.0558263f, 0.2401597f);
    p = fmaf(f, p, 0.6931475f);
    p = fmaf(f, p, 1.0f);
    return p * __int_as_float(((int)i + 127) << 23);
}
__device__ __forceinline__ void pack2hl(float a, float b, uint32_t& h, uint32_t& l) {
    __half2 H = __floats2half2_rn(a, b);
    float2 F = __half22float2(H);
    __half2 L = __floats2half2_rn(a - F.x, b - F.y);
    h = *reinterpret_cast<uint32_t*>(&H);
    l = *reinterpret_cast<uint32_t*>(&L);
}

// ===========================================================================
// one-time converts (4x ILP for bandwidth)
// ===========================================================================
__global__ void splitQ(const float* __restrict__ s, __half* __restrict__ h) {
    #pragma unroll
    for (int j = 0; j < 4; j++) {
        int i = (blockIdx.x * 1024 + j * 256 + threadIdx.x) * 4;
        float4 x = *(const float4*)(s + i);
        *(__half2*)(h + i)     = __floats2half2_rn(x.x, x.y);
        *(__half2*)(h + i + 2) = __floats2half2_rn(x.z, x.w);
    }
}
__global__ void splitW4(const float* __restrict__ w0, const float* __restrict__ w1,
                        const float* __restrict__ w2, const float* __restrict__ w3,
                        __half* __restrict__ h) {
    int z = blockIdx.y;
    const float* s = (z == 0) ? w0 : (z == 1) ? w1 : (z == 2) ? w2 : w3;
    __half* hz = h + (size_t)z * WELEM;
    #pragma unroll
    for (int j = 0; j < 4; j++) {
        int i = (blockIdx.x * 1024 + j * 256 + threadIdx.x) * 4;
        float4 x = *(const float4*)(s + i);
        *(__half2*)(hz + i)     = __floats2half2_rn(x.x, x.y);
        *(__half2*)(hz + i + 2) = __floats2half2_rn(x.z, x.w);
    }
}

// ===========================================================================
// 1-term fp16 GEMM, cp.async 2-stage, 256 threads, warp tile 32x64, 2 CTA/SM.
// C = Ah @ Bh^T + bias, then *oscale.
// Stage layout: AH +0 (16K), BH +16K. 2 stages = 64K smem.
// mode 0: fp32 [M,N]; mode 1: fp16 [B,H,S,DK]
// ===========================================================================
#define GST 32768
#define GT_SMEM (2*GST)   // 65536

__device__ __forceinline__ void gemm1_body(
    const __half* __restrict__ Ah, const __half* __restrict__ Bh,
    const float* __restrict__ bias,
    float* __restrict__ Cf, __half* __restrict__ Oh, int mode, float oscale)
{
    extern __shared__ __align__(1024) char smem[];
    const uint32_t sbase = smem_u32(smem);
    const int tid  = threadIdx.x;
    const int wid  = tid >> 5;
    const int lane = tid & 31;
    const int wm   = wid & 3;        // 0..3 (M)
    const int wn   = wid >> 2;       // 0..1 (N)

    const int m0 = blockIdx.y * 128;
    const int n0 = blockIdx.x * 128;

    // loader geometry: 4 x 16B-chunk per thread per array
    int rowi[4], c8i[4];
    uint32_t soff[4];
    #pragma unroll
    for (int i = 0; i < 4; i++) {
        int g = i * 256 + tid;       // 0..1023
        rowi[i] = g >> 3;            // 0..127
        c8i[i]  = g & 7;
        soff[i] = swz128((uint32_t)(rowi[i] * 128 + c8i[i] * 16));
    }

    float acc[2][8][4] = {};

    // prologue: chunk 0 -> stage 0
    #pragma unroll
    for (int i = 0; i < 4; i++) {
        size_t ao = (size_t)(m0 + rowi[i]) * D_MODEL + c8i[i] * 8;
        size_t bo = (size_t)(n0 + rowi[i]) * D_MODEL + c8i[i] * 8;
        cp16(sbase + soff[i],          Ah + ao);
        cp16(sbase + 16384 + soff[i],  Bh + bo);
    }
    CP_COMMIT();

    for (int kc = 0; kc < 16; kc++) {
        if (kc + 1 < 16) {
            uint32_t st = sbase + ((kc + 1) & 1) * GST;
            #pragma unroll
            for (int i = 0; i < 4; i++) {
                size_t ao = (size_t)(m0 + rowi[i]) * D_MODEL + (kc + 1) * 64 + c8i[i] * 8;
                size_t bo = (size_t)(n0 + rowi[i]) * D_MODEL + (kc + 1) * 64 + c8i[i] * 8;
                cp16(st + soff[i],         Ah + ao);
                cp16(st + 16384 + soff[i], Bh + bo);
            }
        }
        CP_COMMIT();
        CP_WAIT1();
        __syncthreads();

        const uint32_t sbs = sbase + (kc & 1) * GST;
        #pragma unroll
        for (int ks = 0; ks < 4; ks++) {
            uint32_t ah[2][4];
            #pragma unroll
            for (int mi = 0; mi < 2; mi++) {
                int mrow = wm * 32 + mi * 16 + (lane & 15);
                uint32_t off = swz128((uint32_t)(mrow * 128 + ks * 32 + (lane >> 4) * 16));
                ldsm_x4(ah[mi], sbs + off);
            }
            #pragma unroll
            for (int nj16 = 0; nj16 < 4; nj16++) {
                uint32_t bf[4];
                int nrow = wn * 64 + nj16 * 16 + (lane & 15);
                uint32_t off = swz128((uint32_t)(nrow * 128 + ks * 32 + (lane >> 4) * 16));
                ldsm_x4(bf, sbs + 16384 + off);
                #pragma unroll
                for (int mi = 0; mi < 2; mi++) {
                    mmah(acc[mi][nj16*2+0], ah[mi], bf[0], bf[2]);
                    mmah(acc[mi][nj16*2+1], ah[mi], bf[1], bf[3]);
                }
            }
        }
        __syncthreads();   // all reads of this stage done before it is refilled
    }

    #pragma unroll
    for (int mi = 0; mi < 2; mi++) {
        #pragma unroll
        for (int nj = 0; nj < 8; nj++) {
            int gj = n0 + wn * 64 + nj * 8 + (lane & 3) * 2;
            float bi0 = __ldg(bias + gj), bi1 = __ldg(bias + gj + 1);
            #pragma unroll
            for (int half = 0; half < 2; half++) {
                int gi = m0 + wm * 32 + mi * 16 + (lane >> 2) + half * 8;
                float v0 = (acc[mi][nj][half*2+0] + bi0) * oscale;
                float v1 = (acc[mi][nj][half*2+1] + bi1) * oscale;
                if (mode == 0) {
                    *(float2*)&Cf[(size_t)gi * D_MODEL + gj] = make_float2(v0, v1);
                } else {
                    int b = gi >> 11, s = gi & (SEQ - 1);
                    int h = gj >> 6,  d = gj & (DK - 1);
                    size_t idx = (((size_t)(b * NHEADS + h) * SEQ) + s) * DK + d;
                    __half2 H = __floats2half2_rn(v0, v1);
                    *(__half2*)&Oh[idx] = H;
                }
            }
        }
    }
}

#define QSCALE 0.18033688011f   // 0.125 * log2(e), folded into q

// fused Q/K/V projection: grid (8, 32, 3), z selects weight/bias/output
__global__ __launch_bounds__(256, 2)
void gemm_qkv(const __half* __restrict__ Ah, const __half* __restrict__ wh,
              const float* __restrict__ bQ, const float* __restrict__ bK,
              const float* __restrict__ bV,
              __half* __restrict__ qh, __half* __restrict__ kh,
              __half* __restrict__ vh)
{
    int z = blockIdx.z;
    const __half* Bh = wh + (size_t)z * WELEM;
    if (z == 0)      gemm1_body(Ah, Bh, bQ, nullptr, qh, 1, QSCALE);
    else if (z == 1) gemm1_body(Ah, Bh, bK, nullptr, kh, 1, 1.0f);
    else             gemm1_body(Ah, Bh, bV, nullptr, vh, 1, 1.0f);
}

__global__ __launch_bounds__(256, 2)
void gemm_o(const __half* __restrict__ ch, const __half* __restrict__ woh,
            const float* __restrict__ bO, float* __restrict__ out)
{
    gemm1_body(ch, woh, bO, out, nullptr, 0, 1.0f);
}

// ===========================================================================
// Causal flash attention, fp16 tensor-core, cp.async 2-stage K/V pipeline.
// CTA: 128 q-rows x 64-key tiles, 8 warps, 2 CTAs/SM.
// q pre-scaled by 0.125*log2(e): softmax is exp2(s - m) directly.
// QK 1-term; PV 2-term (PhVh + PlVh). ctx written fp16.
// ===========================================================================
#define F_STAGE(s) (16384 + (s) * 16384)     // K +0 (8K), V +8192 (8K)
#define F_SMEM 49152

__global__ __launch_bounds__(256, 2)
void flash_tc(const __half* __restrict__ qh, const __half* __restrict__ kh,
              const __half* __restrict__ vh, __half* __restrict__ ch)
{
    extern __shared__ __align__(1024) char smem[];
    const uint32_t sb = smem_u32(smem);
    const int tid  = threadIdx.x;
    const int wid  = tid >> 5;
    const int lane = tid & 31;
    const int qt   = (gridDim.x - 1) - blockIdx.x;
    const int bh   = blockIdx.y;
    const size_t base = (size_t)bh * SEQ * DK;
    const int nkt = 2 * qt + 2;

    // loader geometry (shared by K and V)
    int lr[2], lc8[2];
    uint32_t lso[2];
    #pragma unroll
    for (int i = 0; i < 2; i++) {
        int c = i * 256 + tid;          // 0..511
        lr[i]  = c >> 3;
        lc8[i] = c & 7;
        lso[i] = swz128((uint32_t)(lr[i] * 128 + lc8[i] * 16));
    }

    // issue chunk 0 into stage 0 (overlaps Q load below)
    #pragma unroll
    for (int i = 0; i < 2; i++) {
        size_t go = base + (size_t)(lr[i]) * DK + lc8[i] * 8;
        cp16(sb + F_STAGE(0) + lso[i],        kh + go);
        cp16(sb + F_STAGE(0) + 8192 + lso[i], vh + go);
    }
    CP_COMMIT();

    // load Q tile -> smem (swizzled)
    #pragma unroll
    for (int i = 0; i < 4; i++) {
        int c = i * 256 + tid;
        int r = c >> 3, c8 = c & 7;
        uint4 d = *(const uint4*)(qh + base + (size_t)(qt * 128 + r) * DK + c8 * 8);
        asm volatile("st.shared.v4.b32 [%0], {%1,%2,%3,%4};" ::
            "r"(sb + swz128((uint32_t)(r * 128 + c8 * 16))),
            "r"(d.x), "r"(d.y), "r"(d.z), "r"(d.w));
    }
    __syncthreads();

    uint32_t qf[4][4];
    #pragma unroll
    for (int ks = 0; ks < 4; ks++) {
        uint32_t off = swz128((uint32_t)((16 * wid + (lane & 15)) * 128 + ks * 32 + (lane >> 4) * 16));
        ldsm_x4(qf[ks], sb + off);
    }

    float oacc[8][4] = {};
    float m0 = -INFINITY, m1 = -INFINITY, l0 = 0.f, l1 = 0.f;
    const int r0g = qt * 128 + 16 * wid + (lane >> 2);

    for (int kt = 0; kt < nkt; kt++) {
        // issue next chunk into the other stage
        if (kt + 1 < nkt) {
            uint32_t st = sb + F_STAGE((kt + 1) & 1);
            #pragma unroll
            for (int i = 0; i < 2; i++) {
                size_t go = base + (size_t)((kt + 1) * 64 + lr[i]) * DK + lc8[i] * 8;
                cp16(st + lso[i],        kh + go);
                cp16(st + 8192 + lso[i], vh + go);
            }
        }
        CP_COMMIT();
        CP_WAIT1();
        __syncthreads();

        const uint32_t fsk  = sb + F_STAGE(kt & 1);
        const uint32_t fsvh = fsk + 8192;

        // S = Q @ K^T (scores already in log2 domain via q pre-scale)
        float sacc[8][4] = {};
        #pragma unroll
        for (int g = 0; g < 4; g++) {
            #pragma unroll
            for (int ks = 0; ks < 4; ks++) {
                uint32_t bf[4];
                uint32_t off = swz128((uint32_t)((16 * g + (lane & 15)) * 128 + ks * 32 + (lane >> 4) * 16));
                ldsm_x4(bf, fsk + off);
                mmah(sacc[2*g+0], qf[ks], bf[0], bf[2]);
                mmah(sacc[2*g+1], qf[ks], bf[1], bf[3]);
            }
        }

        if (kt * 64 + 63 > qt * 128 + 16 * wid) {
            #pragma unroll
            for (int t = 0; t < 8; t++) {
                int col = kt * 64 + 8 * t + 2 * (lane & 3);
                if (col     > r0g)     sacc[t][0] = -1e9f;
                if (col + 1 > r0g)     sacc[t][1] = -1e9f;
                if (col     > r0g + 8) sacc[t][2] = -1e9f;
                if (col + 1 > r0g + 8) sacc[t][3] = -1e9f;
            }
        }

        float mh0 = -INFINITY, mh1 = -INFINITY;
        #pragma unroll
        for (int t = 0; t < 8; t++) {
            mh0 = fmaxf(mh0, fmaxf(sacc[t][0], sacc[t][1]));
            mh1 = fmaxf(mh1, fmaxf(sacc[t][2], sacc[t][3]));
        }
        mh0 = fmaxf(mh0, __shfl_xor_sync(0xffffffffu, mh0, 1));
        mh0 = fmaxf(mh0, __shfl_xor_sync(0xffffffffu, mh0, 2));
        mh1 = fmaxf(mh1, __shfl_xor_sync(0xffffffffu, mh1, 1));
        mh1 = fmaxf(mh1, __shfl_xor_sync(0xffffffffu, mh1, 2));
        float mn0 = fmaxf(m0, mh0), mn1 = fmaxf(m1, mh1);
        float c0 = exp2p(m0 - mn0);
        float c1 = exp2p(m1 - mn1);
        m0 = mn0; m1 = mn1;

        float ps0 = 0.f, ps1 = 0.f;
        #pragma unroll
        for (int t = 0; t < 8; t++) {
            float p0 = exp2p(sacc[t][0] - mn0);
            float p1 = exp2p(sacc[t][1] - mn0);
            float p2 = exp2p(sacc[t][2] - mn1);
            float p3 = exp2p(sacc[t][3] - mn1);
            sacc[t][0] = p0; sacc[t][1] = p1; sacc[t][2] = p2; sacc[t][3] = p3;
            ps0 += p0 + p1; ps1 += p2 + p3;
        }
        l0 = l0 * c0 + ps0;
        l1 = l1 * c1 + ps1;
        #pragma unroll
        for (int t = 0; t < 8; t++) {
            oacc[t][0] *= c0; oacc[t][1] *= c0;
            oacc[t][2] *= c1; oacc[t][3] *= c1;
        }

        // O += P @ V  (2-term: PhVh + PlVh)
        #pragma unroll
        for (int kk = 0; kk < 4; kk++) {
            uint32_t PH[4], PL[4];
            pack2hl(sacc[2*kk  ][0], sacc[2*kk  ][1], PH[0], PL[0]);
            pack2hl(sacc[2*kk  ][2], sacc[2*kk  ][3], PH[1], PL[1]);
            pack2hl(sacc[2*kk+1][0], sacc[2*kk+1][1], PH[2], PL[2]);
            pack2hl(sacc[2*kk+1][2], sacc[2*kk+1][3], PH[3], PL[3]);
            int keyrow = kk * 16 + (lane & 7) + 8 * ((lane >> 3) & 1);
            #pragma unroll
            for (int g2 = 0; g2 < 4; g2++) {
                uint32_t bvh[4];
                int dkc = 16 * g2 + 8 * (lane >> 4);
                uint32_t off = swz128((uint32_t)(keyrow * 128 + dkc * 2));
                ldsm_x4_t(bvh, fsvh + off);
                mmah(oacc[2*g2+0], PH, bvh[0], bvh[1]);
                mmah(oacc[2*g2+1], PH, bvh[2], bvh[3]);
                mmah(oacc[2*g2+0], PL, bvh[0], bvh[1]);
                mmah(oacc[2*g2+1], PL, bvh[2], bvh[3]);
            }
        }
        __syncthreads();   // all reads of this stage done before it is refilled
    }

    l0 += __shfl_xor_sync(0xffffffffu, l0, 1);
    l0 += __shfl_xor_sync(0xffffffffu, l0, 2);
    l1 += __shfl_xor_sync(0xffffffffu, l1, 1);
    l1 += __shfl_xor_sync(0xffffffffu, l1, 2);
    float inv0 = 1.f / l0, inv1 = 1.f / l1;

    int b = bh >> 4, hh = bh & 15;
    int s0 = qt * 128 + 16 * wid + (lane >> 2);
    int s1 = s0 + 8;
    #pragma unroll
    for (int t = 0; t < 8; t++) {
        int n = 8 * t + 2 * (lane & 3);
        __half2 H0 = __floats2half2_rn(oacc[t][0] * inv0, oacc[t][1] * inv0);
        __half2 H1 = __floats2half2_rn(oacc[t][2] * inv1, oacc[t][3] * inv1);
        *(__half2*)&ch[((size_t)b * SEQ + s0) * D_MODEL + hh * DK + n] = H0;
        *(__half2*)&ch[((size_t)b * SEQ + s1) * D_MODEL + hh * DK + n] = H1;
    }
}

// ---------------------------------------------------------------------------
extern "C" void kernel_launch(void* const* d_in, const int* in_sizes, int n_in,
                              void* d_out, int out_size)
{
    const float* Q   = (const float*)d_in[0];
    const float* W_Q = (const float*)d_in[1];
    const float* b_Q = (const float*)d_in[2];
    const float* W_K = (const float*)d_in[3];
    const float* b_K = (const float*)d_in[4];
    const float* W_V = (const float*)d_in[5];
    const float* b_V = (const float*)d_in[6];
    const float* W_O = (const float*)d_in[7];
    const float* b_O = (const float*)d_in[8];
    float* out = (float*)d_out;

    __half *Qh, *wh, *qh, *kh, *vh, *ch;
    cudaGetSymbolAddress((void**)&Qh, g_Qh);
    cudaGetSymbolAddress((void**)&wh, g_wh);
    cudaGetSymbolAddress((void**)&qh, g_qh);
    cudaGetSymbolAddress((void**)&kh, g_kh);
    cudaGetSymbolAddress((void**)&vh, g_vh);
    cudaGetSymbolAddress((void**)&ch, g_ch);

    cudaFuncSetAttribute(gemm_qkv, cudaFuncAttributeMaxDynamicSharedMemorySize, GT_SMEM);
    cudaFuncSetAttribute(gemm_o,   cudaFuncAttributeMaxDynamicSharedMemorySize, GT_SMEM);
    cudaFuncSetAttribute(flash_tc, cudaFuncAttributeMaxDynamicSharedMemorySize, F_SMEM);

    const int nQ = ROWS * D_MODEL;
    splitQ<<<nQ / 16 / 256, 256>>>(Q, Qh);
    splitW4<<<dim3(WELEM / 16 / 256, 4), 256>>>(W_Q, W_K, W_V, W_O, wh);

    gemm_qkv<<<dim3(8, 32, 3), 256, GT_SMEM>>>(Qh, wh, b_Q, b_K, b_V, qh, kh, vh);

    flash_tc<<<dim3(SEQ / 128, BATCH * NHEADS), 256, F_SMEM>>>(qh, kh, vh, ch);

    gemm_o<<<dim3(8, 32), 256, GT_SMEM>>>(ch, wh + 3 * (size_t)WELEM, b_O, out);
}

// round 11
// speedup vs baseline: 7.3059x; 1.1367x over previous
#include <cuda_runtime.h>
#include <cuda_fp16.h>
#include <math.h>
#include <stdint.h>

#define D_MODEL 1024
#define NHEADS  16
#define DK      64
#define SEQ     2048
#define BATCH   2
#define ROWS    (BATCH*SEQ)   // 4096
#define WELEM   (D_MODEL*D_MODEL)

// fp16 scratch (allocation-free rule: __device__ globals; 16B-aligned)
__device__ __align__(16) __half g_Qh[ROWS*D_MODEL];
__device__ __align__(16) __half g_wh[4*WELEM];        // Wq,Wk,Wv,Wo hi
__device__ __align__(16) __half g_qh[ROWS*D_MODEL];   // q fp16 [B,H,S,DK] (pre-scaled)
__device__ __align__(16) __half g_kh[ROWS*D_MODEL];
__device__ __align__(16) __half g_vh[ROWS*D_MODEL];
__device__ __align__(16) __half g_ch[ROWS*D_MODEL];   // ctx fp16 [B,S,D]

// ===========================================================================
// helpers
// ===========================================================================
__device__ __forceinline__ uint32_t smem_u32(const void* p) {
    uint32_t a;
    asm("{ .reg .u64 t; cvta.to.shared.u64 t, %1; cvt.u32.u64 %0, t; }"
        : "=r"(a) : "l"(p));
    return a;
}
__device__ __forceinline__ uint32_t swz128(uint32_t off) {
    return off ^ ((off >> 3) & 0x70);
}
__device__ __forceinline__ void cp16(uint32_t smem_addr, const void* gptr) {
    asm volatile("cp.async.cg.shared.global [%0], [%1], 16;"
                 :: "r"(smem_addr), "l"(gptr));
}
#define CP_COMMIT() asm volatile("cp.async.commit_group;" ::: "memory")
#define CP_WAIT1()  asm volatile("cp.async.wait_group 1;" ::: "memory")
__device__ __forceinline__ void ldsm_x4(uint32_t* r, uint32_t addr) {
    asm volatile("ldmatrix.sync.aligned.m8n8.x4.shared.b16 {%0,%1,%2,%3}, [%4];"
                 : "=r"(r[0]), "=r"(r[1]), "=r"(r[2]), "=r"(r[3]) : "r"(addr));
}
__device__ __forceinline__ void ldsm_x4_t(uint32_t* r, uint32_t addr) {
    asm volatile("ldmatrix.sync.aligned.m8n8.x4.trans.shared.b16 {%0,%1,%2,%3}, [%4];"
                 : "=r"(r[0]), "=r"(r[1]), "=r"(r[2]), "=r"(r[3]) : "r"(addr));
}
__device__ __forceinline__ void mmah(float* c, const uint32_t* a,
                                     uint32_t b0, uint32_t b1) {
    asm volatile("mma.sync.aligned.m16n8k16.row.col.f32.f16.f16.f32 "
                 "{%0,%1,%2,%3}, {%4,%5,%6,%7}, {%8,%9}, {%0,%1,%2,%3};"
                 : "+f"(c[0]), "+f"(c[1]), "+f"(c[2]), "+f"(c[3])
                 : "r"(a[0]), "r"(a[1]), "r"(a[2]), "r"(a[3]), "r"(b0), "r"(b1));
}
// 2^t via FMA-pipe deg-3 minimax poly (rel err ~7e-5, under p's fp16 quant). t <= 0.
__device__ __forceinline__ float exp2p(float t) {
    t = fmaxf(t, -126.0f);
    float i = rintf(t);
    float f = t - i;
    float p = fmaf(f, 0.0558263f, 0.2401597f);
    p = fmaf(f, p, 0.6931475f);
    p = fmaf(f, p, 1.0f);
    return p * __int_as_float(((int)i + 127) << 23);
}
__device__ __forceinline__ uint32_t pack2h(float a, float b) {
    __half2 H = __floats2half2_rn(a, b);
    return *reinterpret_cast<uint32_t*>(&H);
}

// ===========================================================================
// one-time converts (4x ILP for bandwidth)
// ===========================================================================
__global__ void splitQ(const float* __restrict__ s, __half* __restrict__ h) {
    #pragma unroll
    for (int j = 0; j < 4; j++) {
        int i = (blockIdx.x * 1024 + j * 256 + threadIdx.x) * 4;
        float4 x = *(const float4*)(s + i);
        *(__half2*)(h + i)     = __floats2half2_rn(x.x, x.y);
        *(__half2*)(h + i + 2) = __floats2half2_rn(x.z, x.w);
    }
}
__global__ void splitW4(const float* __restrict__ w0, const float* __restrict__ w1,
                        const float* __restrict__ w2, const float* __restrict__ w3,
                        __half* __restrict__ h) {
    int z = blockIdx.y;
    const float* s = (z == 0) ? w0 : (z == 1) ? w1 : (z == 2) ? w2 : w3;
    __half* hz = h + (size_t)z * WELEM;
    #pragma unroll
    for (int j = 0; j < 4; j++) {
        int i = (blockIdx.x * 1024 + j * 256 + threadIdx.x) * 4;
        float4 x = *(const float4*)(s + i);
        *(__half2*)(hz + i)     = __floats2half2_rn(x.x, x.y);
        *(__half2*)(hz + i + 2) = __floats2half2_rn(x.z, x.w);
    }
}

// ===========================================================================
// 1-term fp16 GEMM, cp.async 2-stage, 256 threads, warp tile 32x64, 2 CTA/SM.
// C = Ah @ Bh^T + bias, then *oscale.
// Stage layout: AH +0 (16K), BH +16K. 2 stages = 64K smem.
// mode 0: fp32 [M,N]; mode 1: fp16 [B,H,S,DK]
// ===========================================================================
#define GST 32768
#define GT_SMEM (2*GST)   // 65536

__device__ __forceinline__ void gemm1_body(
    const __half* __restrict__ Ah, const __half* __restrict__ Bh,
    const float* __restrict__ bias,
    float* __restrict__ Cf, __half* __restrict__ Oh, int mode, float oscale)
{
    extern __shared__ __align__(1024) char smem[];
    const uint32_t sbase = smem_u32(smem);
    const int tid  = threadIdx.x;
    const int wid  = tid >> 5;
    const int lane = tid & 31;
    const int wm   = wid & 3;        // 0..3 (M)
    const int wn   = wid >> 2;       // 0..1 (N)

    const int m0 = blockIdx.y * 128;
    const int n0 = blockIdx.x * 128;

    int rowi[4], c8i[4];
    uint32_t soff[4];
    #pragma unroll
    for (int i = 0; i < 4; i++) {
        int g = i * 256 + tid;       // 0..1023
        rowi[i] = g >> 3;            // 0..127
        c8i[i]  = g & 7;
        soff[i] = swz128((uint32_t)(rowi[i] * 128 + c8i[i] * 16));
    }

    float acc[2][8][4] = {};

    #pragma unroll
    for (int i = 0; i < 4; i++) {
        size_t ao = (size_t)(m0 + rowi[i]) * D_MODEL + c8i[i] * 8;
        size_t bo = (size_t)(n0 + rowi[i]) * D_MODEL + c8i[i] * 8;
        cp16(sbase + soff[i],          Ah + ao);
        cp16(sbase + 16384 + soff[i],  Bh + bo);
    }
    CP_COMMIT();

    for (int kc = 0; kc < 16; kc++) {
        if (kc + 1 < 16) {
            uint32_t st = sbase + ((kc + 1) & 1) * GST;
            #pragma unroll
            for (int i = 0; i < 4; i++) {
                size_t ao = (size_t)(m0 + rowi[i]) * D_MODEL + (kc + 1) * 64 + c8i[i] * 8;
                size_t bo = (size_t)(n0 + rowi[i]) * D_MODEL + (kc + 1) * 64 + c8i[i] * 8;
                cp16(st + soff[i],         Ah + ao);
                cp16(st + 16384 + soff[i], Bh + bo);
            }
        }
        CP_COMMIT();
        CP_WAIT1();
        __syncthreads();

        const uint32_t sbs = sbase + (kc & 1) * GST;
        #pragma unroll
        for (int ks = 0; ks < 4; ks++) {
            uint32_t ah[2][4];
            #pragma unroll
            for (int mi = 0; mi < 2; mi++) {
                int mrow = wm * 32 + mi * 16 + (lane & 15);
                uint32_t off = swz128((uint32_t)(mrow * 128 + ks * 32 + (lane >> 4) * 16));
                ldsm_x4(ah[mi], sbs + off);
            }
            #pragma unroll
            for (int nj16 = 0; nj16 < 4; nj16++) {
                uint32_t bf[4];
                int nrow = wn * 64 + nj16 * 16 + (lane & 15);
                uint32_t off = swz128((uint32_t)(nrow * 128 + ks * 32 + (lane >> 4) * 16));
                ldsm_x4(bf, sbs + 16384 + off);
                #pragma unroll
                for (int mi = 0; mi < 2; mi++) {
                    mmah(acc[mi][nj16*2+0], ah[mi], bf[0], bf[2]);
                    mmah(acc[mi][nj16*2+1], ah[mi], bf[1], bf[3]);
                }
            }
        }
        __syncthreads();   // all reads of this stage done before it is refilled
    }

    #pragma unroll
    for (int mi = 0; mi < 2; mi++) {
        #pragma unroll
        for (int nj = 0; nj < 8; nj++) {
            int gj = n0 + wn * 64 + nj * 8 + (lane & 3) * 2;
            float bi0 = __ldg(bias + gj), bi1 = __ldg(bias + gj + 1);
            #pragma unroll
            for (int half = 0; half < 2; half++) {
                int gi = m0 + wm * 32 + mi * 16 + (lane >> 2) + half * 8;
                float v0 = (acc[mi][nj][half*2+0] + bi0) * oscale;
                float v1 = (acc[mi][nj][half*2+1] + bi1) * oscale;
                if (mode == 0) {
                    *(float2*)&Cf[(size_t)gi * D_MODEL + gj] = make_float2(v0, v1);
                } else {
                    int b = gi >> 11, s = gi & (SEQ - 1);
                    int h = gj >> 6,  d = gj & (DK - 1);
                    size_t idx = (((size_t)(b * NHEADS + h) * SEQ) + s) * DK + d;
                    __half2 H = __floats2half2_rn(v0, v1);
                    *(__half2*)&Oh[idx] = H;
                }
            }
        }
    }
}

#define QSCALE 0.18033688011f   // 0.125 * log2(e), folded into q

// fused Q/K/V projection: grid (8, 32, 3), z selects weight/bias/output
__global__ __launch_bounds__(256, 2)
void gemm_qkv(const __half* __restrict__ Ah, const __half* __restrict__ wh,
              const float* __restrict__ bQ, const float* __restrict__ bK,
              const float* __restrict__ bV,
              __half* __restrict__ qh, __half* __restrict__ kh,
              __half* __restrict__ vh)
{
    int z = blockIdx.z;
    const __half* Bh = wh + (size_t)z * WELEM;
    if (z == 0)      gemm1_body(Ah, Bh, bQ, nullptr, qh, 1, QSCALE);
    else if (z == 1) gemm1_body(Ah, Bh, bK, nullptr, kh, 1, 1.0f);
    else             gemm1_body(Ah, Bh, bV, nullptr, vh, 1, 1.0f);
}

__global__ __launch_bounds__(256, 2)
void gemm_o(const __half* __restrict__ ch, const __half* __restrict__ woh,
            const float* __restrict__ bO, float* __restrict__ out)
{
    gemm1_body(ch, woh, bO, out, nullptr, 0, 1.0f);
}

// ===========================================================================
// Causal flash attention, fp16 tensor-core, cp.async 2-stage K/V pipeline.
// CTA: 128 q-rows x 64-key tiles, 8 warps, 2 CTAs/SM.
// q pre-scaled by 0.125*log2(e): softmax is exp2(s - m) directly.
// QK 1-term; PV 1-term (Ph only; weighted-mean structure suppresses p-quant noise).
// ===========================================================================
#define F_STAGE(s) (16384 + (s) * 16384)     // K +0 (8K), V +8192 (8K)
#define F_SMEM 49152

__global__ __launch_bounds__(256, 2)
void flash_tc(const __half* __restrict__ qh, const __half* __restrict__ kh,
              const __half* __restrict__ vh, __half* __restrict__ ch)
{
    extern __shared__ __align__(1024) char smem[];
    const uint32_t sb = smem_u32(smem);
    const int tid  = threadIdx.x;
    const int wid  = tid >> 5;
    const int lane = tid & 31;
    const int qt   = (gridDim.x - 1) - blockIdx.x;
    const int bh   = blockIdx.y;
    const size_t base = (size_t)bh * SEQ * DK;
    const int nkt = 2 * qt + 2;

    // loader geometry (shared by K and V)
    int lr[2], lc8[2];
    uint32_t lso[2];
    #pragma unroll
    for (int i = 0; i < 2; i++) {
        int c = i * 256 + tid;          // 0..511
        lr[i]  = c >> 3;
        lc8[i] = c & 7;
        lso[i] = swz128((uint32_t)(lr[i] * 128 + lc8[i] * 16));
    }

    // issue chunk 0 into stage 0 (overlaps Q load below)
    #pragma unroll
    for (int i = 0; i < 2; i++) {
        size_t go = base + (size_t)(lr[i]) * DK + lc8[i] * 8;
        cp16(sb + F_STAGE(0) + lso[i],        kh + go);
        cp16(sb + F_STAGE(0) + 8192 + lso[i], vh + go);
    }
    CP_COMMIT();

    // load Q tile -> smem (swizzled)
    #pragma unroll
    for (int i = 0; i < 4; i++) {
        int c = i * 256 + tid;
        int r = c >> 3, c8 = c & 7;
        uint4 d = *(const uint4*)(qh + base + (size_t)(qt * 128 + r) * DK + c8 * 8);
        asm volatile("st.shared.v4.b32 [%0], {%1,%2,%3,%4};" ::
            "r"(sb + swz128((uint32_t)(r * 128 + c8 * 16))),
            "r"(d.x), "r"(d.y), "r"(d.z), "r"(d.w));
    }
    __syncthreads();

    uint32_t qf[4][4];
    #pragma unroll
    for (int ks = 0; ks < 4; ks++) {
        uint32_t off = swz128((uint32_t)((16 * wid + (lane & 15)) * 128 + ks * 32 + (lane >> 4) * 16));
        ldsm_x4(qf[ks], sb + off);
    }

    float oacc[8][4] = {};
    float m0 = -INFINITY, m1 = -INFINITY, l0 = 0.f, l1 = 0.f;
    const int r0g = qt * 128 + 16 * wid + (lane >> 2);

    for (int kt = 0; kt < nkt; kt++) {
        // issue next chunk into the other stage
        if (kt + 1 < nkt) {
            uint32_t st = sb + F_STAGE((kt + 1) & 1);
            #pragma unroll
            for (int i = 0; i < 2; i++) {
                size_t go = base + (size_t)((kt + 1) * 64 + lr[i]) * DK + lc8[i] * 8;
                cp16(st + lso[i],        kh + go);
                cp16(st + 8192 + lso[i], vh + go);
            }
        }
        CP_COMMIT();
        CP_WAIT1();
        __syncthreads();

        const uint32_t fsk  = sb + F_STAGE(kt & 1);
        const uint32_t fsvh = fsk + 8192;

        // S = Q @ K^T (scores already in log2 domain via q pre-scale)
        float sacc[8][4] = {};
        #pragma unroll
        for (int g = 0; g < 4; g++) {
            #pragma unroll
            for (int ks = 0; ks < 4; ks++) {
                uint32_t bf[4];
                uint32_t off = swz128((uint32_t)((16 * g + (lane & 15)) * 128 + ks * 32 + (lane >> 4) * 16));
                ldsm_x4(bf, fsk + off);
                mmah(sacc[2*g+0], qf[ks], bf[0], bf[2]);
                mmah(sacc[2*g+1], qf[ks], bf[1], bf[3]);
            }
        }

        if (kt * 64 + 63 > qt * 128 + 16 * wid) {
            #pragma unroll
            for (int t = 0; t < 8; t++) {
                int col = kt * 64 + 8 * t + 2 * (lane & 3);
                if (col     > r0g)     sacc[t][0] = -1e9f;
                if (col + 1 > r0g)     sacc[t][1] = -1e9f;
                if (col     > r0g + 8) sacc[t][2] = -1e9f;
                if (col + 1 > r0g + 8) sacc[t][3] = -1e9f;
            }
        }

        float mh0 = -INFINITY, mh1 = -INFINITY;
        #pragma unroll
        for (int t = 0; t < 8; t++) {
            mh0 = fmaxf(mh0, fmaxf(sacc[t][0], sacc[t][1]));
            mh1 = fmaxf(mh1, fmaxf(sacc[t][2], sacc[t][3]));
        }
        mh0 = fmaxf(mh0, __shfl_xor_sync(0xffffffffu, mh0, 1));
        mh0 = fmaxf(mh0, __shfl_xor_sync(0xffffffffu, mh0, 2));
        mh1 = fmaxf(mh1, __shfl_xor_sync(0xffffffffu, mh1, 1));
        mh1 = fmaxf(mh1, __shfl_xor_sync(0xffffffffu, mh1, 2));
        float mn0 = fmaxf(m0, mh0), mn1 = fmaxf(m1, mh1);
        float c0 = exp2p(m0 - mn0);
        float c1 = exp2p(m1 - mn1);
        m0 = mn0; m1 = mn1;

        float ps0 = 0.f, ps1 = 0.f;
        #pragma unroll
        for (int t = 0; t < 8; t++) {
            float p0 = exp2p(sacc[t][0] - mn0);
            float p1 = exp2p(sacc[t][1] - mn0);
            float p2 = exp2p(sacc[t][2] - mn1);
            float p3 = exp2p(sacc[t][3] - mn1);
            sacc[t][0] = p0; sacc[t][1] = p1; sacc[t][2] = p2; sacc[t][3] = p3;
            ps0 += p0 + p1; ps1 += p2 + p3;
        }
        l0 = l0 * c0 + ps0;
        l1 = l1 * c1 + ps1;
        #pragma unroll
        for (int t = 0; t < 8; t++) {
            oacc[t][0] *= c0; oacc[t][1] *= c0;
            oacc[t][2] *= c1; oacc[t][3] *= c1;
        }

        // O += P @ V  (1-term, fp16 P)
        #pragma unroll
        for (int kk = 0; kk < 4; kk++) {
            uint32_t PH[4];
            PH[0] = pack2h(sacc[2*kk  ][0], sacc[2*kk  ][1]);
            PH[1] = pack2h(sacc[2*kk  ][2], sacc[2*kk  ][3]);
            PH[2] = pack2h(sacc[2*kk+1][0], sacc[2*kk+1][1]);
            PH[3] = pack2h(sacc[2*kk+1][2], sacc[2*kk+1][3]);
            int keyrow = kk * 16 + (lane & 7) + 8 * ((lane >> 3) & 1);
            #pragma unroll
            for (int g2 = 0; g2 < 4; g2++) {
                uint32_t bvh[4];
                int dkc = 16 * g2 + 8 * (lane >> 4);
                uint32_t off = swz128((uint32_t)(keyrow * 128 + dkc * 2));
                ldsm_x4_t(bvh, fsvh + off);
                mmah(oacc[2*g2+0], PH, bvh[0], bvh[1]);
                mmah(oacc[2*g2+1], PH, bvh[2], bvh[3]);
            }
        }
        __syncthreads();   // all reads of this stage done before it is refilled
    }

    l0 += __shfl_xor_sync(0xffffffffu, l0, 1);
    l0 += __shfl_xor_sync(0xffffffffu, l0, 2);
    l1 += __shfl_xor_sync(0xffffffffu, l1, 1);
    l1 += __shfl_xor_sync(0xffffffffu, l1, 2);
    float inv0 = 1.f / l0, inv1 = 1.f / l1;

    int b = bh >> 4, hh = bh & 15;
    int s0 = qt * 128 + 16 * wid + (lane >> 2);
    int s1 = s0 + 8;
    #pragma unroll
    for (int t = 0; t < 8; t++) {
        int n = 8 * t + 2 * (lane & 3);
        __half2 H0 = __floats2half2_rn(oacc[t][0] * inv0, oacc[t][1] * inv0);
        __half2 H1 = __floats2half2_rn(oacc[t][2] * inv1, oacc[t][3] * inv1);
        *(__half2*)&ch[((size_t)b * SEQ + s0) * D_MODEL + hh * DK + n] = H0;
        *(__half2*)&ch[((size_t)b * SEQ + s1) * D_MODEL + hh * DK + n] = H1;
    }
}

// ---------------------------------------------------------------------------
extern "C" void kernel_launch(void* const* d_in, const int* in_sizes, int n_in,
                              void* d_out, int out_size)
{
    const float* Q   = (const float*)d_in[0];
    const float* W_Q = (const float*)d_in[1];
    const float* b_Q = (const float*)d_in[2];
    const float* W_K = (const float*)d_in[3];
    const float* b_K = (const float*)d_in[4];
    const float* W_V = (const float*)d_in[5];
    const float* b_V = (const float*)d_in[6];
    const float* W_O = (const float*)d_in[7];
    const float* b_O = (const float*)d_in[8];
    float* out = (float*)d_out;

    __half *Qh, *wh, *qh, *kh, *vh, *ch;
    cudaGetSymbolAddress((void**)&Qh, g_Qh);
    cudaGetSymbolAddress((void**)&wh, g_wh);
    cudaGetSymbolAddress((void**)&qh, g_qh);
    cudaGetSymbolAddress((void**)&kh, g_kh);
    cudaGetSymbolAddress((void**)&vh, g_vh);
    cudaGetSymbolAddress((void**)&ch, g_ch);

    cudaFuncSetAttribute(gemm_qkv, cudaFuncAttributeMaxDynamicSharedMemorySize, GT_SMEM);
    cudaFuncSetAttribute(gemm_o,   cudaFuncAttributeMaxDynamicSharedMemorySize, GT_SMEM);
    cudaFuncSetAttribute(flash_tc, cudaFuncAttributeMaxDynamicSharedMemorySize, F_SMEM);

    const int nQ = ROWS * D_MODEL;
    splitQ<<<nQ / 16 / 256, 256>>>(Q, Qh);
    splitW4<<<dim3(WELEM / 16 / 256, 4), 256>>>(W_Q, W_K, W_V, W_O, wh);

    gemm_qkv<<<dim3(8, 32, 3), 256, GT_SMEM>>>(Qh, wh, b_Q, b_K, b_V, qh, kh, vh);

    flash_tc<<<dim3(SEQ / 128, BATCH * NHEADS), 256, F_SMEM>>>(qh, kh, vh, ch);

    gemm_o<<<dim3(8, 32), 256, GT_SMEM>>>(ch, wh + 3 * (size_t)WELEM, b_O, out);
}

// round 12
// speedup vs baseline: 7.6292x; 1.0443x over previous
#include <cuda_runtime.h>
#include <cuda_fp16.h>
#include <math.h>
#include <stdint.h>

#define D_MODEL 1024
#define NHEADS  16
#define DK      64
#define SEQ     2048
#define BATCH   2
#define ROWS    (BATCH*SEQ)   // 4096
#define WELEM   (D_MODEL*D_MODEL)

// fp16 scratch (allocation-free rule: __device__ globals; 16B-aligned)
__device__ __align__(16) __half g_Qh[ROWS*D_MODEL];
__device__ __align__(16) __half g_wh[4*WELEM];        // Wq,Wk,Wv,Wo hi
__device__ __align__(16) __half g_qh[ROWS*D_MODEL];   // q fp16 [B,H,S,DK] (pre-scaled)
__device__ __align__(16) __half g_kh[ROWS*D_MODEL];
__device__ __align__(16) __half g_vh[ROWS*D_MODEL];
__device__ __align__(16) __half g_ch[ROWS*D_MODEL];   // ctx fp16 [B,S,D]

// ===========================================================================
// helpers
// ===========================================================================
__device__ __forceinline__ uint32_t smem_u32(const void* p) {
    uint32_t a;
    asm("{ .reg .u64 t; cvta.to.shared.u64 t, %1; cvt.u32.u64 %0, t; }"
        : "=r"(a) : "l"(p));
    return a;
}
__device__ __forceinline__ uint32_t swz128(uint32_t off) {
    return off ^ ((off >> 3) & 0x70);
}
__device__ __forceinline__ void cp16(uint32_t smem_addr, const void* gptr) {
    asm volatile("cp.async.cg.shared.global [%0], [%1], 16;"
                 :: "r"(smem_addr), "l"(gptr));
}
#define CP_COMMIT() asm volatile("cp.async.commit_group;" ::: "memory")
#define CP_WAIT1()  asm volatile("cp.async.wait_group 1;" ::: "memory")
__device__ __forceinline__ void ldsm_x4(uint32_t* r, uint32_t addr) {
    asm volatile("ldmatrix.sync.aligned.m8n8.x4.shared.b16 {%0,%1,%2,%3}, [%4];"
                 : "=r"(r[0]), "=r"(r[1]), "=r"(r[2]), "=r"(r[3]) : "r"(addr));
}
__device__ __forceinline__ void ldsm_x4_t(uint32_t* r, uint32_t addr) {
    asm volatile("ldmatrix.sync.aligned.m8n8.x4.trans.shared.b16 {%0,%1,%2,%3}, [%4];"
                 : "=r"(r[0]), "=r"(r[1]), "=r"(r[2]), "=r"(r[3]) : "r"(addr));
}
__device__ __forceinline__ void mmah(float* c, const uint32_t* a,
                                     uint32_t b0, uint32_t b1) {
    asm volatile("mma.sync.aligned.m16n8k16.row.col.f32.f16.f16.f32 "
                 "{%0,%1,%2,%3}, {%4,%5,%6,%7}, {%8,%9}, {%0,%1,%2,%3};"
                 : "+f"(c[0]), "+f"(c[1]), "+f"(c[2]), "+f"(c[3])
                 : "r"(a[0]), "r"(a[1]), "r"(a[2]), "r"(a[3]), "r"(b0), "r"(b1));
}
// 2^t via FMA-pipe deg-3 minimax poly. t <= 0.
__device__ __forceinline__ float exp2p(float t) {
    t = fmaxf(t, -126.0f);
    float i = rintf(t);
    float f = t - i;
    float p = fmaf(f, 0.0558263f, 0.2401597f);
    p = fmaf(f, p, 0.6931475f);
    p = fmaf(f, p, 1.0f);
    return p * __int_as_float(((int)i + 127) << 23);
}
// 2^t via MUFU.EX2 (off the FMA pipe; budgeted ~10 per thread-tile)
__device__ __forceinline__ float exp2m(float t) {
    float p;
    asm("ex2.approx.f32 %0, %1;" : "=f"(p) : "f"(t));
    return p;
}
__device__ __forceinline__ uint32_t pack2h(float a, float b) {
    __half2 H = __floats2half2_rn(a, b);
    return *reinterpret_cast<uint32_t*>(&H);
}

// ===========================================================================
// one-time converts (4x ILP for bandwidth)
// ===========================================================================
__global__ void splitQ(const float* __restrict__ s, __half* __restrict__ h) {
    #pragma unroll
    for (int j = 0; j < 4; j++) {
        int i = (blockIdx.x * 1024 + j * 256 + threadIdx.x) * 4;
        float4 x = *(const float4*)(s + i);
        *(__half2*)(h + i)     = __floats2half2_rn(x.x, x.y);
        *(__half2*)(h + i + 2) = __floats2half2_rn(x.z, x.w);
    }
}
__global__ void splitW4(const float* __restrict__ w0, const float* __restrict__ w1,
                        const float* __restrict__ w2, const float* __restrict__ w3,
                        __half* __restrict__ h) {
    int z = blockIdx.y;
    const float* s = (z == 0) ? w0 : (z == 1) ? w1 : (z == 2) ? w2 : w3;
    __half* hz = h + (size_t)z * WELEM;
    #pragma unroll
    for (int j = 0; j < 4; j++) {
        int i = (blockIdx.x * 1024 + j * 256 + threadIdx.x) * 4;
        float4 x = *(const float4*)(s + i);
        *(__half2*)(hz + i)     = __floats2half2_rn(x.x, x.y);
        *(__half2*)(hz + i + 2) = __floats2half2_rn(x.z, x.w);
    }
}

// ===========================================================================
// 1-term fp16 GEMM, cp.async 3-stage, 256 threads, warp tile 32x64, 2 CTA/SM.
// C = Ah @ Bh^T + bias, then *oscale. One barrier per K-chunk.
// Stage layout: AH +0 (16K), BH +16K. 3 stages = 96K smem.
// mode 0: fp32 [M,N]; mode 1: fp16 [B,H,S,DK]
// ===========================================================================
#define GST 32768
#define GT_SMEM (3*GST)   // 98304

__device__ __forceinline__ void gemm1_body(
    const __half* __restrict__ Ah, const __half* __restrict__ Bh,
    const float* __restrict__ bias,
    float* __restrict__ Cf, __half* __restrict__ Oh, int mode, float oscale)
{
    extern __shared__ __align__(1024) char smem[];
    const uint32_t sbase = smem_u32(smem);
    const int tid  = threadIdx.x;
    const int wid  = tid >> 5;
    const int lane = tid & 31;
    const int wm   = wid & 3;        // 0..3 (M)
    const int wn   = wid >> 2;       // 0..1 (N)

    const int m0 = blockIdx.y * 128;
    const int n0 = blockIdx.x * 128;

    int rowi[4], c8i[4];
    uint32_t soff[4];
    #pragma unroll
    for (int i = 0; i < 4; i++) {
        int g = i * 256 + tid;       // 0..1023
        rowi[i] = g >> 3;            // 0..127
        c8i[i]  = g & 7;
        soff[i] = swz128((uint32_t)(rowi[i] * 128 + c8i[i] * 16));
    }

    float acc[2][8][4] = {};

    // prologue: chunks 0,1 -> stages 0,1
    #pragma unroll
    for (int c = 0; c < 2; c++) {
        uint32_t st = sbase + c * GST;
        #pragma unroll
        for (int i = 0; i < 4; i++) {
            size_t ao = (size_t)(m0 + rowi[i]) * D_MODEL + c * 64 + c8i[i] * 8;
            size_t bo = (size_t)(n0 + rowi[i]) * D_MODEL + c * 64 + c8i[i] * 8;
            cp16(st + soff[i],         Ah + ao);
            cp16(st + 16384 + soff[i], Bh + bo);
        }
        CP_COMMIT();
    }

    int s_cur = 0, s_n2 = 2;
    for (int kc = 0; kc < 16; kc++) {
        CP_WAIT1();
        __syncthreads();   // chunk kc visible to all; stage s_n2 free of readers

        if (kc + 2 < 16) {
            uint32_t st = sbase + s_n2 * GST;
            #pragma unroll
            for (int i = 0; i < 4; i++) {
                size_t ao = (size_t)(m0 + rowi[i]) * D_MODEL + (kc + 2) * 64 + c8i[i] * 8;
                size_t bo = (size_t)(n0 + rowi[i]) * D_MODEL + (kc + 2) * 64 + c8i[i] * 8;
                cp16(st + soff[i],         Ah + ao);
                cp16(st + 16384 + soff[i], Bh + bo);
            }
        }
        CP_COMMIT();

        const uint32_t sbs = sbase + s_cur * GST;
        #pragma unroll
        for (int ks = 0; ks < 4; ks++) {
            uint32_t ah[2][4];
            #pragma unroll
            for (int mi = 0; mi < 2; mi++) {
                int mrow = wm * 32 + mi * 16 + (lane & 15);
                uint32_t off = swz128((uint32_t)(mrow * 128 + ks * 32 + (lane >> 4) * 16));
                ldsm_x4(ah[mi], sbs + off);
            }
            #pragma unroll
            for (int nj16 = 0; nj16 < 4; nj16++) {
                uint32_t bf[4];
                int nrow = wn * 64 + nj16 * 16 + (lane & 15);
                uint32_t off = swz128((uint32_t)(nrow * 128 + ks * 32 + (lane >> 4) * 16));
                ldsm_x4(bf, sbs + 16384 + off);
                #pragma unroll
                for (int mi = 0; mi < 2; mi++) {
                    mmah(acc[mi][nj16*2+0], ah[mi], bf[0], bf[2]);
                    mmah(acc[mi][nj16*2+1], ah[mi], bf[1], bf[3]);
                }
            }
        }
        s_cur = (s_cur == 2) ? 0 : s_cur + 1;
        s_n2  = (s_n2  == 2) ? 0 : s_n2  + 1;
    }

    #pragma unroll
    for (int mi = 0; mi < 2; mi++) {
        #pragma unroll
        for (int nj = 0; nj < 8; nj++) {
            int gj = n0 + wn * 64 + nj * 8 + (lane & 3) * 2;
            float bi0 = __ldg(bias + gj), bi1 = __ldg(bias + gj + 1);
            #pragma unroll
            for (int half = 0; half < 2; half++) {
                int gi = m0 + wm * 32 + mi * 16 + (lane >> 2) + half * 8;
                float v0 = (acc[mi][nj][half*2+0] + bi0) * oscale;
                float v1 = (acc[mi][nj][half*2+1] + bi1) * oscale;
                if (mode == 0) {
                    *(float2*)&Cf[(size_t)gi * D_MODEL + gj] = make_float2(v0, v1);
                } else {
                    int b = gi >> 11, s = gi & (SEQ - 1);
                    int h = gj >> 6,  d = gj & (DK - 1);
                    size_t idx = (((size_t)(b * NHEADS + h) * SEQ) + s) * DK + d;
                    __half2 H = __floats2half2_rn(v0, v1);
                    *(__half2*)&Oh[idx] = H;
                }
            }
        }
    }
}

#define QSCALE 0.18033688011f   // 0.125 * log2(e), folded into q

// fused Q/K/V projection: grid (8, 32, 3), z selects weight/bias/output
__global__ __launch_bounds__(256, 2)
void gemm_qkv(const __half* __restrict__ Ah, const __half* __restrict__ wh,
              const float* __restrict__ bQ, const float* __restrict__ bK,
              const float* __restrict__ bV,
              __half* __restrict__ qh, __half* __restrict__ kh,
              __half* __restrict__ vh)
{
    int z = blockIdx.z;
    const __half* Bh = wh + (size_t)z * WELEM;
    if (z == 0)      gemm1_body(Ah, Bh, bQ, nullptr, qh, 1, QSCALE);
    else if (z == 1) gemm1_body(Ah, Bh, bK, nullptr, kh, 1, 1.0f);
    else             gemm1_body(Ah, Bh, bV, nullptr, vh, 1, 1.0f);
}

__global__ __launch_bounds__(256, 2)
void gemm_o(const __half* __restrict__ ch, const __half* __restrict__ woh,
            const float* __restrict__ bO, float* __restrict__ out)
{
    gemm1_body(ch, woh, bO, out, nullptr, 0, 1.0f);
}

// ===========================================================================
// Causal flash attention, fp16 tensor-core, cp.async 3-stage K/V pipeline.
// CTA: 128 q-rows x 64-key tiles, 8 warps, 2 CTAs/SM. One barrier per tile.
// q pre-scaled by 0.125*log2(e): softmax is exp2(s - m) directly.
// Hybrid exp: 8/32 elements + rescale factors on MUFU, rest on FMA poly.
// QK 1-term; PV 1-term.
// ===========================================================================
#define FQ_SZ 16384
#define FST   16384
#define F_SMEM (FQ_SZ + 3*FST)   // 65536

__global__ __launch_bounds__(256, 2)
void flash_tc(const __half* __restrict__ qh, const __half* __restrict__ kh,
              const __half* __restrict__ vh, __half* __restrict__ ch)
{
    extern __shared__ __align__(1024) char smem[];
    const uint32_t sb = smem_u32(smem);
    const int tid  = threadIdx.x;
    const int wid  = tid >> 5;
    const int lane = tid & 31;
    const int qt   = (gridDim.x - 1) - blockIdx.x;
    const int bh   = blockIdx.y;
    const size_t base = (size_t)bh * SEQ * DK;
    const int nkt = 2 * qt + 2;    // >= 2 always

    // loader geometry (shared by K and V)
    int lr[2], lc8[2];
    uint32_t lso[2];
    #pragma unroll
    for (int i = 0; i < 2; i++) {
        int c = i * 256 + tid;          // 0..511
        lr[i]  = c >> 3;
        lc8[i] = c & 7;
        lso[i] = swz128((uint32_t)(lr[i] * 128 + lc8[i] * 16));
    }

    // prologue: chunks 0,1 -> stages 0,1 (overlap Q load)
    #pragma unroll
    for (int c = 0; c < 2; c++) {
        uint32_t st = sb + FQ_SZ + c * FST;
        #pragma unroll
        for (int i = 0; i < 2; i++) {
            size_t go = base + (size_t)(c * 64 + lr[i]) * DK + lc8[i] * 8;
            cp16(st + lso[i],        kh + go);
            cp16(st + 8192 + lso[i], vh + go);
        }
        CP_COMMIT();
    }

    // load Q tile -> smem (swizzled)
    #pragma unroll
    for (int i = 0; i < 4; i++) {
        int c = i * 256 + tid;
        int r = c >> 3, c8 = c & 7;
        uint4 d = *(const uint4*)(qh + base + (size_t)(qt * 128 + r) * DK + c8 * 8);
        asm volatile("st.shared.v4.b32 [%0], {%1,%2,%3,%4};" ::
            "r"(sb + swz128((uint32_t)(r * 128 + c8 * 16))),
            "r"(d.x), "r"(d.y), "r"(d.z), "r"(d.w));
    }
    __syncthreads();

    uint32_t qf[4][4];
    #pragma unroll
    for (int ks = 0; ks < 4; ks++) {
        uint32_t off = swz128((uint32_t)((16 * wid + (lane & 15)) * 128 + ks * 32 + (lane >> 4) * 16));
        ldsm_x4(qf[ks], sb + off);
    }

    float oacc[8][4] = {};
    float m0 = -INFINITY, m1 = -INFINITY, l0 = 0.f, l1 = 0.f;
    const int r0g = qt * 128 + 16 * wid + (lane >> 2);

    int s_cur = 0, s_n2 = 2;
    for (int kt = 0; kt < nkt; kt++) {
        CP_WAIT1();
        __syncthreads();   // chunk kt visible; stage s_n2 free of readers

        if (kt + 2 < nkt) {
            uint32_t st = sb + FQ_SZ + s_n2 * FST;
            #pragma unroll
            for (int i = 0; i < 2; i++) {
                size_t go = base + (size_t)((kt + 2) * 64 + lr[i]) * DK + lc8[i] * 8;
                cp16(st + lso[i],        kh + go);
                cp16(st + 8192 + lso[i], vh + go);
            }
        }
        CP_COMMIT();

        const uint32_t fsk  = sb + FQ_SZ + s_cur * FST;
        const uint32_t fsvh = fsk + 8192;

        // S = Q @ K^T (scores already in log2 domain via q pre-scale)
        float sacc[8][4] = {};
        #pragma unroll
        for (int g = 0; g < 4; g++) {
            #pragma unroll
            for (int ks = 0; ks < 4; ks++) {
                uint32_t bf[4];
                uint32_t off = swz128((uint32_t)((16 * g + (lane & 15)) * 128 + ks * 32 + (lane >> 4) * 16));
                ldsm_x4(bf, fsk + off);
                mmah(sacc[2*g+0], qf[ks], bf[0], bf[2]);
                mmah(sacc[2*g+1], qf[ks], bf[1], bf[3]);
            }
        }

        if (kt * 64 + 63 > qt * 128 + 16 * wid) {
            #pragma unroll
            for (int t = 0; t < 8; t++) {
                int col = kt * 64 + 8 * t + 2 * (lane & 3);
                if (col     > r0g)     sacc[t][0] = -1e9f;
                if (col + 1 > r0g)     sacc[t][1] = -1e9f;
                if (col     > r0g + 8) sacc[t][2] = -1e9f;
                if (col + 1 > r0g + 8) sacc[t][3] = -1e9f;
            }
        }

        float mh0 = -INFINITY, mh1 = -INFINITY;
        #pragma unroll
        for (int t = 0; t < 8; t++) {
            mh0 = fmaxf(mh0, fmaxf(sacc[t][0], sacc[t][1]));
            mh1 = fmaxf(mh1, fmaxf(sacc[t][2], sacc[t][3]));
        }
        mh0 = fmaxf(mh0, __shfl_xor_sync(0xffffffffu, mh0, 1));
        mh0 = fmaxf(mh0, __shfl_xor_sync(0xffffffffu, mh0, 2));
        mh1 = fmaxf(mh1, __shfl_xor_sync(0xffffffffu, mh1, 1));
        mh1 = fmaxf(mh1, __shfl_xor_sync(0xffffffffu, mh1, 2));
        float mn0 = fmaxf(m0, mh0), mn1 = fmaxf(m1, mh1);
        float c0 = exp2m(m0 - mn0);   // MUFU (ex2(-inf)=0 handles first tile)
        float c1 = exp2m(m1 - mn1);
        m0 = mn0; m1 = mn1;

        float ps0 = 0.f, ps1 = 0.f;
        #pragma unroll
        for (int t = 0; t < 8; t++) {
            float t0 = sacc[t][0] - mn0, t1 = sacc[t][1] - mn0;
            float t2 = sacc[t][2] - mn1, t3 = sacc[t][3] - mn1;
            float p0, p1, p2, p3;
            if (t < 2) {               // MUFU path (8 of 32; keeps MUFU sub-saturated)
                p0 = exp2m(t0); p1 = exp2m(t1);
                p2 = exp2m(t2); p3 = exp2m(t3);
            } else {                   // FMA-pipe poly
                p0 = exp2p(t0); p1 = exp2p(t1);
                p2 = exp2p(t2); p3 = exp2p(t3);
            }
            sacc[t][0] = p0; sacc[t][1] = p1; sacc[t][2] = p2; sacc[t][3] = p3;
            ps0 += p0 + p1; ps1 += p2 + p3;
        }
        l0 = l0 * c0 + ps0;
        l1 = l1 * c1 + ps1;
        #pragma unroll
        for (int t = 0; t < 8; t++) {
            oacc[t][0] *= c0; oacc[t][1] *= c0;
            oacc[t][2] *= c1; oacc[t][3] *= c1;
        }

        // O += P @ V  (1-term, fp16 P)
        #pragma unroll
        for (int kk = 0; kk < 4; kk++) {
            uint32_t PH[4];
            PH[0] = pack2h(sacc[2*kk  ][0], sacc[2*kk  ][1]);
            PH[1] = pack2h(sacc[2*kk  ][2], sacc[2*kk  ][3]);
            PH[2] = pack2h(sacc[2*kk+1][0], sacc[2*kk+1][1]);
            PH[3] = pack2h(sacc[2*kk+1][2], sacc[2*kk+1][3]);
            int keyrow = kk * 16 + (lane & 7) + 8 * ((lane >> 3) & 1);
            #pragma unroll
            for (int g2 = 0; g2 < 4; g2++) {
                uint32_t bvh[4];
                int dkc = 16 * g2 + 8 * (lane >> 4);
                uint32_t off = swz128((uint32_t)(keyrow * 128 + dkc * 2));
                ldsm_x4_t(bvh, fsvh + off);
                mmah(oacc[2*g2+0], PH, bvh[0], bvh[1]);
                mmah(oacc[2*g2+1], PH, bvh[2], bvh[3]);
            }
        }
        s_cur = (s_cur == 2) ? 0 : s_cur + 1;
        s_n2  = (s_n2  == 2) ? 0 : s_n2  + 1;
    }

    l0 += __shfl_xor_sync(0xffffffffu, l0, 1);
    l0 += __shfl_xor_sync(0xffffffffu, l0, 2);
    l1 += __shfl_xor_sync(0xffffffffu, l1, 1);
    l1 += __shfl_xor_sync(0xffffffffu, l1, 2);
    float inv0 = 1.f / l0, inv1 = 1.f / l1;

    int b = bh >> 4, hh = bh & 15;
    int s0 = qt * 128 + 16 * wid + (lane >> 2);
    int s1 = s0 + 8;
    #pragma unroll
    for (int t = 0; t < 8; t++) {
        int n = 8 * t + 2 * (lane & 3);
        __half2 H0 = __floats2half2_rn(oacc[t][0] * inv0, oacc[t][1] * inv0);
        __half2 H1 = __floats2half2_rn(oacc[t][2] * inv1, oacc[t][3] * inv1);
        *(__half2*)&ch[((size_t)b * SEQ + s0) * D_MODEL + hh * DK + n] = H0;
        *(__half2*)&ch[((size_t)b * SEQ + s1) * D_MODEL + hh * DK + n] = H1;
    }
}

// ---------------------------------------------------------------------------
extern "C" void kernel_launch(void* const* d_in, const int* in_sizes, int n_in,
                              void* d_out, int out_size)
{
    const float* Q   = (const float*)d_in[0];
    const float* W_Q = (const float*)d_in[1];
    const float* b_Q = (const float*)d_in[2];
    const float* W_K = (const float*)d_in[3];
    const float* b_K = (const float*)d_in[4];
    const float* W_V = (const float*)d_in[5];
    const float* b_V = (const float*)d_in[6];
    const float* W_O = (const float*)d_in[7];
    const float* b_O = (const float*)d_in[8];
    float* out = (float*)d_out;

    __half *Qh, *wh, *qh, *kh, *vh, *ch;
    cudaGetSymbolAddress((void**)&Qh, g_Qh);
    cudaGetSymbolAddress((void**)&wh, g_wh);
    cudaGetSymbolAddress((void**)&qh, g_qh);
    cudaGetSymbolAddress((void**)&kh, g_kh);
    cudaGetSymbolAddress((void**)&vh, g_vh);
    cudaGetSymbolAddress((void**)&ch, g_ch);

    cudaFuncSetAttribute(gemm_qkv, cudaFuncAttributeMaxDynamicSharedMemorySize, GT_SMEM);
    cudaFuncSetAttribute(gemm_o,   cudaFuncAttributeMaxDynamicSharedMemorySize, GT_SMEM);
    cudaFuncSetAttribute(flash_tc, cudaFuncAttributeMaxDynamicSharedMemorySize, F_SMEM);

    const int nQ = ROWS * D_MODEL;
    splitQ<<<nQ / 16 / 256, 256>>>(Q, Qh);
    splitW4<<<dim3(WELEM / 16 / 256, 4), 256>>>(W_Q, W_K, W_V, W_O, wh);

    gemm_qkv<<<dim3(8, 32, 3), 256, GT_SMEM>>>(Qh, wh, b_Q, b_K, b_V, qh, kh, vh);

    flash_tc<<<dim3(SEQ / 128, BATCH * NHEADS), 256, F_SMEM>>>(qh, kh, vh, ch);

    gemm_o<<<dim3(8, 32), 256, GT_SMEM>>>(ch, wh + 3 * (size_t)WELEM, b_O, out);
}

// round 13
// speedup vs baseline: 8.2485x; 1.0812x over previous
#include <cuda_runtime.h>
#include <cuda_fp16.h>
#include <math.h>
#include <stdint.h>

#define D_MODEL 1024
#define NHEADS  16
#define DK      64
#define SEQ     2048
#define BATCH   2
#define ROWS    (BATCH*SEQ)   // 4096
#define WELEM   (D_MODEL*D_MODEL)

// fp16 scratch (allocation-free rule: __device__ globals; 16B-aligned)
__device__ __align__(16) __half g_Qh[ROWS*D_MODEL];
__device__ __align__(16) __half g_wh[4*WELEM];        // Wq,Wk,Wv,Wo hi
__device__ __align__(16) __half g_qh[ROWS*D_MODEL];   // q fp16 [B,H,S,DK] (pre-scaled)
__device__ __align__(16) __half g_kh[ROWS*D_MODEL];
__device__ __align__(16) __half g_vh[ROWS*D_MODEL];
__device__ __align__(16) __half g_ch[ROWS*D_MODEL];   // ctx fp16 [B,S,D]

// ===========================================================================
// helpers
// ===========================================================================
__device__ __forceinline__ uint32_t smem_u32(const void* p) {
    uint32_t a;
    asm("{ .reg .u64 t; cvta.to.shared.u64 t, %1; cvt.u32.u64 %0, t; }"
        : "=r"(a) : "l"(p));
    return a;
}
__device__ __forceinline__ uint32_t swz128(uint32_t off) {
    return off ^ ((off >> 3) & 0x70);
}
__device__ __forceinline__ void cp16(uint32_t smem_addr, const void* gptr) {
    asm volatile("cp.async.cg.shared.global [%0], [%1], 16;"
                 :: "r"(smem_addr), "l"(gptr));
}
#define CP_COMMIT() asm volatile("cp.async.commit_group;" ::: "memory")
#define CP_WAIT1()  asm volatile("cp.async.wait_group 1;" ::: "memory")
__device__ __forceinline__ void ldsm_x4(uint32_t* r, uint32_t addr) {
    asm volatile("ldmatrix.sync.aligned.m8n8.x4.shared.b16 {%0,%1,%2,%3}, [%4];"
                 : "=r"(r[0]), "=r"(r[1]), "=r"(r[2]), "=r"(r[3]) : "r"(addr));
}
__device__ __forceinline__ void ldsm_x4_t(uint32_t* r, uint32_t addr) {
    asm volatile("ldmatrix.sync.aligned.m8n8.x4.trans.shared.b16 {%0,%1,%2,%3}, [%4];"
                 : "=r"(r[0]), "=r"(r[1]), "=r"(r[2]), "=r"(r[3]) : "r"(addr));
}
__device__ __forceinline__ void mmah(float* c, const uint32_t* a,
                                     uint32_t b0, uint32_t b1) {
    asm volatile("mma.sync.aligned.m16n8k16.row.col.f32.f16.f16.f32 "
                 "{%0,%1,%2,%3}, {%4,%5,%6,%7}, {%8,%9}, {%0,%1,%2,%3};"
                 : "+f"(c[0]), "+f"(c[1]), "+f"(c[2]), "+f"(c[3])
                 : "r"(a[0]), "r"(a[1]), "r"(a[2]), "r"(a[3]), "r"(b0), "r"(b1));
}
// 2^t via MUFU.EX2. Tile-time budget shows MUFU stays well under saturation
// even with all softmax exps routed here (34/thread-tile).
__device__ __forceinline__ float exp2m(float t) {
    float p;
    asm("ex2.approx.f32 %0, %1;" : "=f"(p) : "f"(t));
    return p;
}
__device__ __forceinline__ uint32_t pack2h(float a, float b) {
    __half2 H = __floats2half2_rn(a, b);
    return *reinterpret_cast<uint32_t*>(&H);
}

// ===========================================================================
// one-time converts (4x ILP for bandwidth)
// ===========================================================================
__global__ void splitQ(const float* __restrict__ s, __half* __restrict__ h) {
    #pragma unroll
    for (int j = 0; j < 4; j++) {
        int i = (blockIdx.x * 1024 + j * 256 + threadIdx.x) * 4;
        float4 x = *(const float4*)(s + i);
        *(__half2*)(h + i)     = __floats2half2_rn(x.x, x.y);
        *(__half2*)(h + i + 2) = __floats2half2_rn(x.z, x.w);
    }
}
__global__ void splitW4(const float* __restrict__ w0, const float* __restrict__ w1,
                        const float* __restrict__ w2, const float* __restrict__ w3,
                        __half* __restrict__ h) {
    int z = blockIdx.y;
    const float* s = (z == 0) ? w0 : (z == 1) ? w1 : (z == 2) ? w2 : w3;
    __half* hz = h + (size_t)z * WELEM;
    #pragma unroll
    for (int j = 0; j < 4; j++) {
        int i = (blockIdx.x * 1024 + j * 256 + threadIdx.x) * 4;
        float4 x = *(const float4*)(s + i);
        *(__half2*)(hz + i)     = __floats2half2_rn(x.x, x.y);
        *(__half2*)(hz + i + 2) = __floats2half2_rn(x.z, x.w);
    }
}

// ===========================================================================
// 1-term fp16 GEMM, cp.async 3-stage, 256 threads, warp tile 32x64, 2 CTA/SM.
// C = Ah @ Bh^T + bias, then *oscale. One barrier per K-chunk.
// Stage layout: AH +0 (16K), BH +16K. 3 stages = 96K smem.
// mode 0: fp32 [M,N]; mode 1: fp16 [B,H,S,DK]
// ===========================================================================
#define GST 32768
#define GT_SMEM (3*GST)   // 98304

__device__ __forceinline__ void gemm1_body(
    const __half* __restrict__ Ah, const __half* __restrict__ Bh,
    const float* __restrict__ bias,
    float* __restrict__ Cf, __half* __restrict__ Oh, int mode, float oscale)
{
    extern __shared__ __align__(1024) char smem[];
    const uint32_t sbase = smem_u32(smem);
    const int tid  = threadIdx.x;
    const int wid  = tid >> 5;
    const int lane = tid & 31;
    const int wm   = wid & 3;        // 0..3 (M)
    const int wn   = wid >> 2;       // 0..1 (N)

    const int m0 = blockIdx.y * 128;
    const int n0 = blockIdx.x * 128;

    int rowi[4], c8i[4];
    uint32_t soff[4];
    #pragma unroll
    for (int i = 0; i < 4; i++) {
        int g = i * 256 + tid;       // 0..1023
        rowi[i] = g >> 3;            // 0..127
        c8i[i]  = g & 7;
        soff[i] = swz128((uint32_t)(rowi[i] * 128 + c8i[i] * 16));
    }

    float acc[2][8][4] = {};

    // prologue: chunks 0,1 -> stages 0,1
    #pragma unroll
    for (int c = 0; c < 2; c++) {
        uint32_t st = sbase + c * GST;
        #pragma unroll
        for (int i = 0; i < 4; i++) {
            size_t ao = (size_t)(m0 + rowi[i]) * D_MODEL + c * 64 + c8i[i] * 8;
            size_t bo = (size_t)(n0 + rowi[i]) * D_MODEL + c * 64 + c8i[i] * 8;
            cp16(st + soff[i],         Ah + ao);
            cp16(st + 16384 + soff[i], Bh + bo);
        }
        CP_COMMIT();
    }

    int s_cur = 0, s_n2 = 2;
    for (int kc = 0; kc < 16; kc++) {
        CP_WAIT1();
        __syncthreads();   // chunk kc visible to all; stage s_n2 free of readers

        if (kc + 2 < 16) {
            uint32_t st = sbase + s_n2 * GST;
            #pragma unroll
            for (int i = 0; i < 4; i++) {
                size_t ao = (size_t)(m0 + rowi[i]) * D_MODEL + (kc + 2) * 64 + c8i[i] * 8;
                size_t bo = (size_t)(n0 + rowi[i]) * D_MODEL + (kc + 2) * 64 + c8i[i] * 8;
                cp16(st + soff[i],         Ah + ao);
                cp16(st + 16384 + soff[i], Bh + bo);
            }
        }
        CP_COMMIT();

        const uint32_t sbs = sbase + s_cur * GST;
        #pragma unroll
        for (int ks = 0; ks < 4; ks++) {
            uint32_t ah[2][4];
            #pragma unroll
            for (int mi = 0; mi < 2; mi++) {
                int mrow = wm * 32 + mi * 16 + (lane & 15);
                uint32_t off = swz128((uint32_t)(mrow * 128 + ks * 32 + (lane >> 4) * 16));
                ldsm_x4(ah[mi], sbs + off);
            }
            #pragma unroll
            for (int nj16 = 0; nj16 < 4; nj16++) {
                uint32_t bf[4];
                int nrow = wn * 64 + nj16 * 16 + (lane & 15);
                uint32_t off = swz128((uint32_t)(nrow * 128 + ks * 32 + (lane >> 4) * 16));
                ldsm_x4(bf, sbs + 16384 + off);
                #pragma unroll
                for (int mi = 0; mi < 2; mi++) {
                    mmah(acc[mi][nj16*2+0], ah[mi], bf[0], bf[2]);
                    mmah(acc[mi][nj16*2+1], ah[mi], bf[1], bf[3]);
                }
            }
        }
        s_cur = (s_cur == 2) ? 0 : s_cur + 1;
        s_n2  = (s_n2  == 2) ? 0 : s_n2  + 1;
    }

    #pragma unroll
    for (int mi = 0; mi < 2; mi++) {
        #pragma unroll
        for (int nj = 0; nj < 8; nj++) {
            int gj = n0 + wn * 64 + nj * 8 + (lane & 3) * 2;
            float bi0 = __ldg(bias + gj), bi1 = __ldg(bias + gj + 1);
            #pragma unroll
            for (int half = 0; half < 2; half++) {
                int gi = m0 + wm * 32 + mi * 16 + (lane >> 2) + half * 8;
                float v0 = (acc[mi][nj][half*2+0] + bi0) * oscale;
                float v1 = (acc[mi][nj][half*2+1] + bi1) * oscale;
                if (mode == 0) {
                    *(float2*)&Cf[(size_t)gi * D_MODEL + gj] = make_float2(v0, v1);
                } else {
                    int b = gi >> 11, s = gi & (SEQ - 1);
                    int h = gj >> 6,  d = gj & (DK - 1);
                    size_t idx = (((size_t)(b * NHEADS + h) * SEQ) + s) * DK + d;
                    __half2 H = __floats2half2_rn(v0, v1);
                    *(__half2*)&Oh[idx] = H;
                }
            }
        }
    }
}

#define QSCALE 0.18033688011f   // 0.125 * log2(e), folded into q

// fused Q/K/V projection: grid (8, 32, 3), z selects weight/bias/output
__global__ __launch_bounds__(256, 2)
void gemm_qkv(const __half* __restrict__ Ah, const __half* __restrict__ wh,
              const float* __restrict__ bQ, const float* __restrict__ bK,
              const float* __restrict__ bV,
              __half* __restrict__ qh, __half* __restrict__ kh,
              __half* __restrict__ vh)
{
    int z = blockIdx.z;
    const __half* Bh = wh + (size_t)z * WELEM;
    if (z == 0)      gemm1_body(Ah, Bh, bQ, nullptr, qh, 1, QSCALE);
    else if (z == 1) gemm1_body(Ah, Bh, bK, nullptr, kh, 1, 1.0f);
    else             gemm1_body(Ah, Bh, bV, nullptr, vh, 1, 1.0f);
}

__global__ __launch_bounds__(256, 2)
void gemm_o(const __half* __restrict__ ch, const __half* __restrict__ woh,
            const float* __restrict__ bO, float* __restrict__ out)
{
    gemm1_body(ch, woh, bO, out, nullptr, 0, 1.0f);
}

// ===========================================================================
// Causal flash attention, fp16 tensor-core, cp.async 3-stage K/V pipeline.
// CTA: 128 q-rows x 64-key tiles, 8 warps, 2 CTAs/SM. One barrier per tile.
// q pre-scaled by 0.125*log2(e): softmax is exp2(s - m) directly.
// ALL exps on MUFU (EX2); MUFU stays sub-saturated at measured tile times.
// QK 1-term; PV 1-term.
// ===========================================================================
#define FQ_SZ 16384
#define FST   16384
#define F_SMEM (FQ_SZ + 3*FST)   // 65536

__global__ __launch_bounds__(256, 2)
void flash_tc(const __half* __restrict__ qh, const __half* __restrict__ kh,
              const __half* __restrict__ vh, __half* __restrict__ ch)
{
    extern __shared__ __align__(1024) char smem[];
    const uint32_t sb = smem_u32(smem);
    const int tid  = threadIdx.x;
    const int wid  = tid >> 5;
    const int lane = tid & 31;
    const int qt   = (gridDim.x - 1) - blockIdx.x;
    const int bh   = blockIdx.y;
    const size_t base = (size_t)bh * SEQ * DK;
    const int nkt = 2 * qt + 2;    // >= 2 always

    // loader geometry (shared by K and V)
    int lr[2], lc8[2];
    uint32_t lso[2];
    #pragma unroll
    for (int i = 0; i < 2; i++) {
        int c = i * 256 + tid;          // 0..511
        lr[i]  = c >> 3;
        lc8[i] = c & 7;
        lso[i] = swz128((uint32_t)(lr[i] * 128 + lc8[i] * 16));
    }

    // prologue: chunks 0,1 -> stages 0,1 (overlap Q load)
    #pragma unroll
    for (int c = 0; c < 2; c++) {
        uint32_t st = sb + FQ_SZ + c * FST;
        #pragma unroll
        for (int i = 0; i < 2; i++) {
            size_t go = base + (size_t)(c * 64 + lr[i]) * DK + lc8[i] * 8;
            cp16(st + lso[i],        kh + go);
            cp16(st + 8192 + lso[i], vh + go);
        }
        CP_COMMIT();
    }

    // load Q tile -> smem (swizzled)
    #pragma unroll
    for (int i = 0; i < 4; i++) {
        int c = i * 256 + tid;
        int r = c >> 3, c8 = c & 7;
        uint4 d = *(const uint4*)(qh + base + (size_t)(qt * 128 + r) * DK + c8 * 8);
        asm volatile("st.shared.v4.b32 [%0], {%1,%2,%3,%4};" ::
            "r"(sb + swz128((uint32_t)(r * 128 + c8 * 16))),
            "r"(d.x), "r"(d.y), "r"(d.z), "r"(d.w));
    }
    __syncthreads();

    uint32_t qf[4][4];
    #pragma unroll
    for (int ks = 0; ks < 4; ks++) {
        uint32_t off = swz128((uint32_t)((16 * wid + (lane & 15)) * 128 + ks * 32 + (lane >> 4) * 16));
        ldsm_x4(qf[ks], sb + off);
    }

    float oacc[8][4] = {};
    float m0 = -INFINITY, m1 = -INFINITY, l0 = 0.f, l1 = 0.f;
    const int r0g = qt * 128 + 16 * wid + (lane >> 2);

    int s_cur = 0, s_n2 = 2;
    for (int kt = 0; kt < nkt; kt++) {
        CP_WAIT1();
        __syncthreads();   // chunk kt visible; stage s_n2 free of readers

        if (kt + 2 < nkt) {
            uint32_t st = sb + FQ_SZ + s_n2 * FST;
            #pragma unroll
            for (int i = 0; i < 2; i++) {
                size_t go = base + (size_t)((kt + 2) * 64 + lr[i]) * DK + lc8[i] * 8;
                cp16(st + lso[i],        kh + go);
                cp16(st + 8192 + lso[i], vh + go);
            }
        }
        CP_COMMIT();

        const uint32_t fsk  = sb + FQ_SZ + s_cur * FST;
        const uint32_t fsvh = fsk + 8192;

        // S = Q @ K^T (scores already in log2 domain via q pre-scale)
        float sacc[8][4] = {};
        #pragma unroll
        for (int g = 0; g < 4; g++) {
            #pragma unroll
            for (int ks = 0; ks < 4; ks++) {
                uint32_t bf[4];
                uint32_t off = swz128((uint32_t)((16 * g + (lane & 15)) * 128 + ks * 32 + (lane >> 4) * 16));
                ldsm_x4(bf, fsk + off);
                mmah(sacc[2*g+0], qf[ks], bf[0], bf[2]);
                mmah(sacc[2*g+1], qf[ks], bf[1], bf[3]);
            }
        }

        if (kt * 64 + 63 > qt * 128 + 16 * wid) {
            #pragma unroll
            for (int t = 0; t < 8; t++) {
                int col = kt * 64 + 8 * t + 2 * (lane & 3);
                if (col     > r0g)     sacc[t][0] = -1e9f;
                if (col + 1 > r0g)     sacc[t][1] = -1e9f;
                if (col     > r0g + 8) sacc[t][2] = -1e9f;
                if (col + 1 > r0g + 8) sacc[t][3] = -1e9f;
            }
        }

        float mh0 = -INFINITY, mh1 = -INFINITY;
        #pragma unroll
        for (int t = 0; t < 8; t++) {
            mh0 = fmaxf(mh0, fmaxf(sacc[t][0], sacc[t][1]));
            mh1 = fmaxf(mh1, fmaxf(sacc[t][2], sacc[t][3]));
        }
        mh0 = fmaxf(mh0, __shfl_xor_sync(0xffffffffu, mh0, 1));
        mh0 = fmaxf(mh0, __shfl_xor_sync(0xffffffffu, mh0, 2));
        mh1 = fmaxf(mh1, __shfl_xor_sync(0xffffffffu, mh1, 1));
        mh1 = fmaxf(mh1, __shfl_xor_sync(0xffffffffu, mh1, 2));
        float mn0 = fmaxf(m0, mh0), mn1 = fmaxf(m1, mh1);
        float c0 = exp2m(m0 - mn0);   // ex2(-inf)=0 handles first tile
        float c1 = exp2m(m1 - mn1);
        m0 = mn0; m1 = mn1;

        float ps0 = 0.f, ps1 = 0.f;
        #pragma unroll
        for (int t = 0; t < 8; t++) {
            float p0 = exp2m(sacc[t][0] - mn0);
            float p1 = exp2m(sacc[t][1] - mn0);
            float p2 = exp2m(sacc[t][2] - mn1);
            float p3 = exp2m(sacc[t][3] - mn1);
            sacc[t][0] = p0; sacc[t][1] = p1; sacc[t][2] = p2; sacc[t][3] = p3;
            ps0 += p0 + p1; ps1 += p2 + p3;
        }
        l0 = l0 * c0 + ps0;
        l1 = l1 * c1 + ps1;
        #pragma unroll
        for (int t = 0; t < 8; t++) {
            oacc[t][0] *= c0; oacc[t][1] *= c0;
            oacc[t][2] *= c1; oacc[t][3] *= c1;
        }

        // O += P @ V  (1-term, fp16 P)
        #pragma unroll
        for (int kk = 0; kk < 4; kk++) {
            uint32_t PH[4];
            PH[0] = pack2h(sacc[2*kk  ][0], sacc[2*kk  ][1]);
            PH[1] = pack2h(sacc[2*kk  ][2], sacc[2*kk  ][3]);
            PH[2] = pack2h(sacc[2*kk+1][0], sacc[2*kk+1][1]);
            PH[3] = pack2h(sacc[2*kk+1][2], sacc[2*kk+1][3]);
            int keyrow = kk * 16 + (lane & 7) + 8 * ((lane >> 3) & 1);
            #pragma unroll
            for (int g2 = 0; g2 < 4; g2++) {
                uint32_t bvh[4];
                int dkc = 16 * g2 + 8 * (lane >> 4);
                uint32_t off = swz128((uint32_t)(keyrow * 128 + dkc * 2));
                ldsm_x4_t(bvh, fsvh + off);
                mmah(oacc[2*g2+0], PH, bvh[0], bvh[1]);
                mmah(oacc[2*g2+1], PH, bvh[2], bvh[3]);
            }
        }
        s_cur = (s_cur == 2) ? 0 : s_cur + 1;
        s_n2  = (s_n2  == 2) ? 0 : s_n2  + 1;
    }

    l0 += __shfl_xor_sync(0xffffffffu, l0, 1);
    l0 += __shfl_xor_sync(0xffffffffu, l0, 2);
    l1 += __shfl_xor_sync(0xffffffffu, l1, 1);
    l1 += __shfl_xor_sync(0xffffffffu, l1, 2);
    float inv0 = 1.f / l0, inv1 = 1.f / l1;

    int b = bh >> 4, hh = bh & 15;
    int s0 = qt * 128 + 16 * wid + (lane >> 2);
    int s1 = s0 + 8;
    #pragma unroll
    for (int t = 0; t < 8; t++) {
        int n = 8 * t + 2 * (lane & 3);
        __half2 H0 = __floats2half2_rn(oacc[t][0] * inv0, oacc[t][1] * inv0);
        __half2 H1 = __floats2half2_rn(oacc[t][2] * inv1, oacc[t][3] * inv1);
        *(__half2*)&ch[((size_t)b * SEQ + s0) * D_MODEL + hh * DK + n] = H0;
        *(__half2*)&ch[((size_t)b * SEQ + s1) * D_MODEL + hh * DK + n] = H1;
    }
}

// ---------------------------------------------------------------------------
extern "C" void kernel_launch(void* const* d_in, const int* in_sizes, int n_in,
                              void* d_out, int out_size)
{
    const float* Q   = (const float*)d_in[0];
    const float* W_Q = (const float*)d_in[1];
    const float* b_Q = (const float*)d_in[2];
    const float* W_K = (const float*)d_in[3];
    const float* b_K = (const float*)d_in[4];
    const float* W_V = (const float*)d_in[5];
    const float* b_V = (const float*)d_in[6];
    const float* W_O = (const float*)d_in[7];
    const float* b_O = (const float*)d_in[8];
    float* out = (float*)d_out;

    __half *Qh, *wh, *qh, *kh, *vh, *ch;
    cudaGetSymbolAddress((void**)&Qh, g_Qh);
    cudaGetSymbolAddress((void**)&wh, g_wh);
    cudaGetSymbolAddress((void**)&qh, g_qh);
    cudaGetSymbolAddress((void**)&kh, g_kh);
    cudaGetSymbolAddress((void**)&vh, g_vh);
    cudaGetSymbolAddress((void**)&ch, g_ch);

    cudaFuncSetAttribute(gemm_qkv, cudaFuncAttributeMaxDynamicSharedMemorySize, GT_SMEM);
    cudaFuncSetAttribute(gemm_o,   cudaFuncAttributeMaxDynamicSharedMemorySize, GT_SMEM);
    cudaFuncSetAttribute(flash_tc, cudaFuncAttributeMaxDynamicSharedMemorySize, F_SMEM);

    const int nQ = ROWS * D_MODEL;
    splitQ<<<nQ / 16 / 256, 256>>>(Q, Qh);
    splitW4<<<dim3(WELEM / 16 / 256, 4), 256>>>(W_Q, W_K, W_V, W_O, wh);

    gemm_qkv<<<dim3(8, 32, 3), 256, GT_SMEM>>>(Qh, wh, b_Q, b_K, b_V, qh, kh, vh);

    flash_tc<<<dim3(SEQ / 128, BATCH * NHEADS), 256, F_SMEM>>>(qh, kh, vh, ch);

    gemm_o<<<dim3(8, 32), 256, GT_SMEM>>>(ch, wh + 3 * (size_t)WELEM, b_O, out);
}

// round 14
// speedup vs baseline: 8.5956x; 1.0421x over previous
#include <cuda_runtime.h>
#include <cuda_fp16.h>
#include <math.h>
#include <stdint.h>

#define D_MODEL 1024
#define NHEADS  16
#define DK      64
#define SEQ     2048
#define BATCH   2
#define ROWS    (BATCH*SEQ)   // 4096
#define WELEM   (D_MODEL*D_MODEL)

// fp16 scratch (allocation-free rule: __device__ globals; 16B-aligned)
__device__ __align__(16) __half g_Qh[ROWS*D_MODEL];
__device__ __align__(16) __half g_wh[4*WELEM];        // Wq,Wk,Wv,Wo hi
__device__ __align__(16) __half g_qh[ROWS*D_MODEL];   // q fp16 [B,H,S,DK] (pre-scaled)
__device__ __align__(16) __half g_kh[ROWS*D_MODEL];
__device__ __align__(16) __half g_vh[ROWS*D_MODEL];
__device__ __align__(16) __half g_ch[ROWS*D_MODEL];   // ctx fp16 [B,S,D]

// ===========================================================================
// helpers
// ===========================================================================
__device__ __forceinline__ uint32_t smem_u32(const void* p) {
    uint32_t a;
    asm("{ .reg .u64 t; cvta.to.shared.u64 t, %1; cvt.u32.u64 %0, t; }"
        : "=r"(a) : "l"(p));
    return a;
}
__device__ __forceinline__ uint32_t swz128(uint32_t off) {
    return off ^ ((off >> 3) & 0x70);
}
__device__ __forceinline__ void cp16(uint32_t smem_addr, const void* gptr) {
    asm volatile("cp.async.cg.shared.global [%0], [%1], 16;"
                 :: "r"(smem_addr), "l"(gptr));
}
#define CP_COMMIT() asm volatile("cp.async.commit_group;" ::: "memory")
#define CP_WAIT1()  asm volatile("cp.async.wait_group 1;" ::: "memory")
__device__ __forceinline__ void ldsm_x4(uint32_t* r, uint32_t addr) {
    asm volatile("ldmatrix.sync.aligned.m8n8.x4.shared.b16 {%0,%1,%2,%3}, [%4];"
                 : "=r"(r[0]), "=r"(r[1]), "=r"(r[2]), "=r"(r[3]) : "r"(addr));
}
__device__ __forceinline__ void ldsm_x4_t(uint32_t* r, uint32_t addr) {
    asm volatile("ldmatrix.sync.aligned.m8n8.x4.trans.shared.b16 {%0,%1,%2,%3}, [%4];"
                 : "=r"(r[0]), "=r"(r[1]), "=r"(r[2]), "=r"(r[3]) : "r"(addr));
}
__device__ __forceinline__ void mmah(float* c, const uint32_t* a,
                                     uint32_t b0, uint32_t b1) {
    asm volatile("mma.sync.aligned.m16n8k16.row.col.f32.f16.f16.f32 "
                 "{%0,%1,%2,%3}, {%4,%5,%6,%7}, {%8,%9}, {%0,%1,%2,%3};"
                 : "+f"(c[0]), "+f"(c[1]), "+f"(c[2]), "+f"(c[3])
                 : "r"(a[0]), "r"(a[1]), "r"(a[2]), "r"(a[3]), "r"(b0), "r"(b1));
}
// 2^t via MUFU.EX2 (sub-saturated at measured tile times).
__device__ __forceinline__ float exp2m(float t) {
    float p;
    asm("ex2.approx.f32 %0, %1;" : "=f"(p) : "f"(t));
    return p;
}
__device__ __forceinline__ uint32_t pack2h(float a, float b) {
    __half2 H = __floats2half2_rn(a, b);
    return *reinterpret_cast<uint32_t*>(&H);
}

// ===========================================================================
// one-time converts, single launch. grid (256, 8):
// y=0..3 -> quarters of Q; y=4..7 -> W_Q,W_K,W_V,W_O. 4x ILP.
// ===========================================================================
__global__ void splitAll(const float* __restrict__ Q,
                         const float* __restrict__ w0, const float* __restrict__ w1,
                         const float* __restrict__ w2, const float* __restrict__ w3,
                         __half* __restrict__ Qh, __half* __restrict__ wh) {
    int y = blockIdx.y;
    const float* s;
    __half* h;
    if (y < 4) { s = Q + (size_t)y * WELEM; h = Qh + (size_t)y * WELEM; }
    else {
        s = (y == 4) ? w0 : (y == 5) ? w1 : (y == 6) ? w2 : w3;
        h = wh + (size_t)(y - 4) * WELEM;
    }
    #pragma unroll
    for (int j = 0; j < 4; j++) {
        int i = (blockIdx.x * 1024 + j * 256 + threadIdx.x) * 4;
        float4 x = *(const float4*)(s + i);
        *(__half2*)(h + i)     = __floats2half2_rn(x.x, x.y);
        *(__half2*)(h + i + 2) = __floats2half2_rn(x.z, x.w);
    }
}

// ===========================================================================
// 1-term fp16 GEMM, cp.async 3-stage, 256 threads, warp tile 32x64, 2 CTA/SM.
// C = Ah @ Bh^T + bias, then *oscale. One barrier per K-chunk.
// Stage layout: AH +0 (16K), BH +16K. 3 stages = 96K smem.
// mode 0: fp32 [M,N]; mode 1: fp16 [B,H,S,DK]
// ===========================================================================
#define GST 32768
#define GT_SMEM (3*GST)   // 98304

__device__ __forceinline__ void gemm1_body(
    const __half* __restrict__ Ah, const __half* __restrict__ Bh,
    const float* __restrict__ bias,
    float* __restrict__ Cf, __half* __restrict__ Oh, int mode, float oscale)
{
    extern __shared__ __align__(1024) char smem[];
    const uint32_t sbase = smem_u32(smem);
    const int tid  = threadIdx.x;
    const int wid  = tid >> 5;
    const int lane = tid & 31;
    const int wm   = wid & 3;        // 0..3 (M)
    const int wn   = wid >> 2;       // 0..1 (N)

    const int m0 = blockIdx.y * 128;
    const int n0 = blockIdx.x * 128;

    int rowi[4], c8i[4];
    uint32_t soff[4];
    #pragma unroll
    for (int i = 0; i < 4; i++) {
        int g = i * 256 + tid;       // 0..1023
        rowi[i] = g >> 3;            // 0..127
        c8i[i]  = g & 7;
        soff[i] = swz128((uint32_t)(rowi[i] * 128 + c8i[i] * 16));
    }

    float acc[2][8][4] = {};

    // prologue: chunks 0,1 -> stages 0,1
    #pragma unroll
    for (int c = 0; c < 2; c++) {
        uint32_t st = sbase + c * GST;
        #pragma unroll
        for (int i = 0; i < 4; i++) {
            size_t ao = (size_t)(m0 + rowi[i]) * D_MODEL + c * 64 + c8i[i] * 8;
            size_t bo = (size_t)(n0 + rowi[i]) * D_MODEL + c * 64 + c8i[i] * 8;
            cp16(st + soff[i],         Ah + ao);
            cp16(st + 16384 + soff[i], Bh + bo);
        }
        CP_COMMIT();
    }

    int s_cur = 0, s_n2 = 2;
    for (int kc = 0; kc < 16; kc++) {
        CP_WAIT1();
        __syncthreads();   // chunk kc visible to all; stage s_n2 free of readers

        if (kc + 2 < 16) {
            uint32_t st = sbase + s_n2 * GST;
            #pragma unroll
            for (int i = 0; i < 4; i++) {
                size_t ao = (size_t)(m0 + rowi[i]) * D_MODEL + (kc + 2) * 64 + c8i[i] * 8;
                size_t bo = (size_t)(n0 + rowi[i]) * D_MODEL + (kc + 2) * 64 + c8i[i] * 8;
                cp16(st + soff[i],         Ah + ao);
                cp16(st + 16384 + soff[i], Bh + bo);
            }
        }
        CP_COMMIT();

        const uint32_t sbs = sbase + s_cur * GST;
        #pragma unroll
        for (int ks = 0; ks < 4; ks++) {
            uint32_t ah[2][4];
            #pragma unroll
            for (int mi = 0; mi < 2; mi++) {
                int mrow = wm * 32 + mi * 16 + (lane & 15);
                uint32_t off = swz128((uint32_t)(mrow * 128 + ks * 32 + (lane >> 4) * 16));
                ldsm_x4(ah[mi], sbs + off);
            }
            #pragma unroll
            for (int nj16 = 0; nj16 < 4; nj16++) {
                uint32_t bf[4];
                int nrow = wn * 64 + nj16 * 16 + (lane & 15);
                uint32_t off = swz128((uint32_t)(nrow * 128 + ks * 32 + (lane >> 4) * 16));
                ldsm_x4(bf, sbs + 16384 + off);
                #pragma unroll
                for (int mi = 0; mi < 2; mi++) {
                    mmah(acc[mi][nj16*2+0], ah[mi], bf[0], bf[2]);
                    mmah(acc[mi][nj16*2+1], ah[mi], bf[1], bf[3]);
                }
            }
        }
        s_cur = (s_cur == 2) ? 0 : s_cur + 1;
        s_n2  = (s_n2  == 2) ? 0 : s_n2  + 1;
    }

    #pragma unroll
    for (int mi = 0; mi < 2; mi++) {
        #pragma unroll
        for (int nj = 0; nj < 8; nj++) {
            int gj = n0 + wn * 64 + nj * 8 + (lane & 3) * 2;
            float bi0 = __ldg(bias + gj), bi1 = __ldg(bias + gj + 1);
            #pragma unroll
            for (int half = 0; half < 2; half++) {
                int gi = m0 + wm * 32 + mi * 16 + (lane >> 2) + half * 8;
                float v0 = (acc[mi][nj][half*2+0] + bi0) * oscale;
                float v1 = (acc[mi][nj][half*2+1] + bi1) * oscale;
                if (mode == 0) {
                    *(float2*)&Cf[(size_t)gi * D_MODEL + gj] = make_float2(v0, v1);
                } else {
                    int b = gi >> 11, s = gi & (SEQ - 1);
                    int h = gj >> 6,  d = gj & (DK - 1);
                    size_t idx = (((size_t)(b * NHEADS + h) * SEQ) + s) * DK + d;
                    __half2 H = __floats2half2_rn(v0, v1);
                    *(__half2*)&Oh[idx] = H;
                }
            }
        }
    }
}

#define QSCALE 0.18033688011f   // 0.125 * log2(e), folded into q

// fused Q/K/V projection: grid (8, 32, 3), z selects weight/bias/output
__global__ __launch_bounds__(256, 2)
void gemm_qkv(const __half* __restrict__ Ah, const __half* __restrict__ wh,
              const float* __restrict__ bQ, const float* __restrict__ bK,
              const float* __restrict__ bV,
              __half* __restrict__ qh, __half* __restrict__ kh,
              __half* __restrict__ vh)
{
    int z = blockIdx.z;
    const __half* Bh = wh + (size_t)z * WELEM;
    if (z == 0)      gemm1_body(Ah, Bh, bQ, nullptr, qh, 1, QSCALE);
    else if (z == 1) gemm1_body(Ah, Bh, bK, nullptr, kh, 1, 1.0f);
    else             gemm1_body(Ah, Bh, bV, nullptr, vh, 1, 1.0f);
}

__global__ __launch_bounds__(256, 2)
void gemm_o(const __half* __restrict__ ch, const __half* __restrict__ woh,
            const float* __restrict__ bO, float* __restrict__ out)
{
    gemm1_body(ch, woh, bO, out, nullptr, 0, 1.0f);
}

// ===========================================================================
// Causal flash attention, fp16 tensor-core, cp.async 3-stage K/V pipeline.
// CTA: 128 q-rows x 64-key tiles, 8 warps, 2 CTAs/SM. One barrier per tile.
// q pre-scaled by 0.125*log2(e): softmax is exp2(s - m) directly (all MUFU).
// Row sums l computed on the TENSOR pipe: l += P @ ones (consistent with the
// fp16-quantized P used in PV). Rescale skipped via warp vote when max static.
// QK 1-term; PV 1-term.
// ===========================================================================
#define FQ_SZ 16384
#define FST   16384
#define F_SMEM (FQ_SZ + 3*FST)   // 65536
#define ONES16 0x3C003C00u       // fp16 {1.0, 1.0}

__global__ __launch_bounds__(256, 2)
void flash_tc(const __half* __restrict__ qh, const __half* __restrict__ kh,
              const __half* __restrict__ vh, __half* __restrict__ ch)
{
    extern __shared__ __align__(1024) char smem[];
    const uint32_t sb = smem_u32(smem);
    const int tid  = threadIdx.x;
    const int wid  = tid >> 5;
    const int lane = tid & 31;
    const int qt   = (gridDim.x - 1) - blockIdx.x;
    const int bh   = blockIdx.y;
    const size_t base = (size_t)bh * SEQ * DK;
    const int nkt = 2 * qt + 2;    // >= 2 always

    // loader geometry (shared by K and V)
    int lr[2], lc8[2];
    uint32_t lso[2];
    #pragma unroll
    for (int i = 0; i < 2; i++) {
        int c = i * 256 + tid;          // 0..511
        lr[i]  = c >> 3;
        lc8[i] = c & 7;
        lso[i] = swz128((uint32_t)(lr[i] * 128 + lc8[i] * 16));
    }

    // prologue: chunks 0,1 -> stages 0,1 (overlap Q load)
    #pragma unroll
    for (int c = 0; c < 2; c++) {
        uint32_t st = sb + FQ_SZ + c * FST;
        #pragma unroll
        for (int i = 0; i < 2; i++) {
            size_t go = base + (size_t)(c * 64 + lr[i]) * DK + lc8[i] * 8;
            cp16(st + lso[i],        kh + go);
            cp16(st + 8192 + lso[i], vh + go);
        }
        CP_COMMIT();
    }

    // load Q tile -> smem (swizzled)
    #pragma unroll
    for (int i = 0; i < 4; i++) {
        int c = i * 256 + tid;
        int r = c >> 3, c8 = c & 7;
        uint4 d = *(const uint4*)(qh + base + (size_t)(qt * 128 + r) * DK + c8 * 8);
        asm volatile("st.shared.v4.b32 [%0], {%1,%2,%3,%4};" ::
            "r"(sb + swz128((uint32_t)(r * 128 + c8 * 16))),
            "r"(d.x), "r"(d.y), "r"(d.z), "r"(d.w));
    }
    __syncthreads();

    uint32_t qf[4][4];
    #pragma unroll
    for (int ks = 0; ks < 4; ks++) {
        uint32_t off = swz128((uint32_t)((16 * wid + (lane & 15)) * 128 + ks * 32 + (lane >> 4) * 16));
        ldsm_x4(qf[ks], sb + off);
    }

    float oacc[8][4] = {};
    float lacc[4] = {};            // tensor-pipe row sums (cols of P @ ones)
    float m0 = -INFINITY, m1 = -INFINITY;
    const int r0g = qt * 128 + 16 * wid + (lane >> 2);

    int s_cur = 0, s_n2 = 2;
    for (int kt = 0; kt < nkt; kt++) {
        CP_WAIT1();
        __syncthreads();   // chunk kt visible; stage s_n2 free of readers

        if (kt + 2 < nkt) {
            uint32_t st = sb + FQ_SZ + s_n2 * FST;
            #pragma unroll
            for (int i = 0; i < 2; i++) {
                size_t go = base + (size_t)((kt + 2) * 64 + lr[i]) * DK + lc8[i] * 8;
                cp16(st + lso[i],        kh + go);
                cp16(st + 8192 + lso[i], vh + go);
            }
        }
        CP_COMMIT();

        const uint32_t fsk  = sb + FQ_SZ + s_cur * FST;
        const uint32_t fsvh = fsk + 8192;

        // S = Q @ K^T (scores already in log2 domain via q pre-scale)
        float sacc[8][4] = {};
        #pragma unroll
        for (int g = 0; g < 4; g++) {
            #pragma unroll
            for (int ks = 0; ks < 4; ks++) {
                uint32_t bf[4];
                uint32_t off = swz128((uint32_t)((16 * g + (lane & 15)) * 128 + ks * 32 + (lane >> 4) * 16));
                ldsm_x4(bf, fsk + off);
                mmah(sacc[2*g+0], qf[ks], bf[0], bf[2]);
                mmah(sacc[2*g+1], qf[ks], bf[1], bf[3]);
            }
        }

        if (kt * 64 + 63 > qt * 128 + 16 * wid) {
            #pragma unroll
            for (int t = 0; t < 8; t++) {
                int col = kt * 64 + 8 * t + 2 * (lane & 3);
                if (col     > r0g)     sacc[t][0] = -1e9f;
                if (col + 1 > r0g)     sacc[t][1] = -1e9f;
                if (col     > r0g + 8) sacc[t][2] = -1e9f;
                if (col + 1 > r0g + 8) sacc[t][3] = -1e9f;
            }
        }

        float mh0 = -INFINITY, mh1 = -INFINITY;
        #pragma unroll
        for (int t = 0; t < 8; t++) {
            mh0 = fmaxf(mh0, fmaxf(sacc[t][0], sacc[t][1]));
            mh1 = fmaxf(mh1, fmaxf(sacc[t][2], sacc[t][3]));
        }
        mh0 = fmaxf(mh0, __shfl_xor_sync(0xffffffffu, mh0, 1));
        mh0 = fmaxf(mh0, __shfl_xor_sync(0xffffffffu, mh0, 2));
        mh1 = fmaxf(mh1, __shfl_xor_sync(0xffffffffu, mh1, 1));
        mh1 = fmaxf(mh1, __shfl_xor_sync(0xffffffffu, mh1, 2));
        float mn0 = fmaxf(m0, mh0), mn1 = fmaxf(m1, mh1);

        // rescale only when some row's max actually grew (warp vote; ~10% of tiles)
        if (__any_sync(0xffffffffu, (mh0 > m0) || (mh1 > m1))) {
            float c0 = exp2m(m0 - mn0);   // ex2(-inf)=0 handles first tile
            float c1 = exp2m(m1 - mn1);
            #pragma unroll
            for (int t = 0; t < 8; t++) {
                oacc[t][0] *= c0; oacc[t][1] *= c0;
                oacc[t][2] *= c1; oacc[t][3] *= c1;
            }
            lacc[0] *= c0; lacc[1] *= c0;
            lacc[2] *= c1; lacc[3] *= c1;
        }
        m0 = mn0; m1 = mn1;

        // p = 2^(s - m), all on MUFU
        #pragma unroll
        for (int t = 0; t < 8; t++) {
            sacc[t][0] = exp2m(sacc[t][0] - mn0);
            sacc[t][1] = exp2m(sacc[t][1] - mn0);
            sacc[t][2] = exp2m(sacc[t][2] - mn1);
            sacc[t][3] = exp2m(sacc[t][3] - mn1);
        }

        // O += P @ V  and  l += P @ ones   (both on tensor pipe)
        #pragma unroll
        for (int kk = 0; kk < 4; kk++) {
            uint32_t PH[4];
            PH[0] = pack2h(sacc[2*kk  ][0], sacc[2*kk  ][1]);
            PH[1] = pack2h(sacc[2*kk  ][2], sacc[2*kk  ][3]);
            PH[2] = pack2h(sacc[2*kk+1][0], sacc[2*kk+1][1]);
            PH[3] = pack2h(sacc[2*kk+1][2], sacc[2*kk+1][3]);
            mmah(lacc, PH, ONES16, ONES16);
            int keyrow = kk * 16 + (lane & 7) + 8 * ((lane >> 3) & 1);
            #pragma unroll
            for (int g2 = 0; g2 < 4; g2++) {
                uint32_t bvh[4];
                int dkc = 16 * g2 + 8 * (lane >> 4);
                uint32_t off = swz128((uint32_t)(keyrow * 128 + dkc * 2));
                ldsm_x4_t(bvh, fsvh + off);
                mmah(oacc[2*g2+0], PH, bvh[0], bvh[1]);
                mmah(oacc[2*g2+1], PH, bvh[2], bvh[3]);
            }
        }
        s_cur = (s_cur == 2) ? 0 : s_cur + 1;
        s_n2  = (s_n2  == 2) ? 0 : s_n2  + 1;
    }

    // lacc[0]/lacc[2] hold complete row sums (mma reduced across the quad)
    float inv0 = 1.f / lacc[0], inv1 = 1.f / lacc[2];

    int b = bh >> 4, hh = bh & 15;
    int s0 = qt * 128 + 16 * wid + (lane >> 2);
    int s1 = s0 + 8;
    #pragma unroll
    for (int t = 0; t < 8; t++) {
        int n = 8 * t + 2 * (lane & 3);
        __half2 H0 = __floats2half2_rn(oacc[t][0] * inv0, oacc[t][1] * inv0);
        __half2 H1 = __floats2half2_rn(oacc[t][2] * inv1, oacc[t][3] * inv1);
        *(__half2*)&ch[((size_t)b * SEQ + s0) * D_MODEL + hh * DK + n] = H0;
        *(__half2*)&ch[((size_t)b * SEQ + s1) * D_MODEL + hh * DK + n] = H1;
    }
}

// ---------------------------------------------------------------------------
extern "C" void kernel_launch(void* const* d_in, const int* in_sizes, int n_in,
                              void* d_out, int out_size)
{
    const float* Q   = (const float*)d_in[0];
    const float* W_Q = (const float*)d_in[1];
    const float* b_Q = (const float*)d_in[2];
    const float* W_K = (const float*)d_in[3];
    const float* b_K = (const float*)d_in[4];
    const float* W_V = (const float*)d_in[5];
    const float* b_V = (const float*)d_in[6];
    const float* W_O = (const float*)d_in[7];
    const float* b_O = (const float*)d_in[8];
    float* out = (float*)d_out;

    __half *Qh, *wh, *qh, *kh, *vh, *ch;
    cudaGetSymbolAddress((void**)&Qh, g_Qh);
    cudaGetSymbolAddress((void**)&wh, g_wh);
    cudaGetSymbolAddress((void**)&qh, g_qh);
    cudaGetSymbolAddress((void**)&kh, g_kh);
    cudaGetSymbolAddress((void**)&vh, g_vh);
    cudaGetSymbolAddress((void**)&ch, g_ch);

    cudaFuncSetAttribute(gemm_qkv, cudaFuncAttributeMaxDynamicSharedMemorySize, GT_SMEM);
    cudaFuncSetAttribute(gemm_o,   cudaFuncAttributeMaxDynamicSharedMemorySize, GT_SMEM);
    cudaFuncSetAttribute(flash_tc, cudaFuncAttributeMaxDynamicSharedMemorySize, F_SMEM);

    splitAll<<<dim3(WELEM / 16 / 256, 8), 256>>>(Q, W_Q, W_K, W_V, W_O, Qh, wh);

    gemm_qkv<<<dim3(8, 32, 3), 256, GT_SMEM>>>(Qh, wh, b_Q, b_K, b_V, qh, kh, vh);

    flash_tc<<<dim3(SEQ / 128, BATCH * NHEADS), 256, F_SMEM>>>(qh, kh, vh, ch);

    gemm_o<<<dim3(8, 32), 256, GT_SMEM>>>(ch, wh + 3 * (size_t)WELEM, b_O, out);
}